// round 6
// baseline (speedup 1.0000x reference)
#include <cuda_runtime.h>
#include <math.h>

// Problem constants (fixed by the dataset)
#define N_NODES 50000
#define N_EDGES 800000
#define ET_EDGES (N_NODES + N_EDGES)   // edges + self loops
#define HWID 256                        // heads*hid for layers 0/1
#define CDIM 64
#define NBLK_SCAN ((N_NODES + 255) / 256)   // 196

// ---------------- scratch (device globals; no allocation allowed) -------------
static __device__ float g_h   [(size_t)N_NODES * HWID];
static __device__ float g_agg [(size_t)N_NODES * HWID];
static __device__ float g_as  [N_NODES * 4];
static __device__ float g_ad  [N_NODES * 4];
static __device__ float g_sum [HWID];
static __device__ float g_sq  [HWID];
static __device__ float g_scl [HWID];
static __device__ float g_sft [HWID];
static __device__ float g_cls [N_NODES * 32];
// CSR scratch
static __device__ int g_deg   [N_NODES];
static __device__ int g_cursor[N_NODES];
static __device__ int g_rowptr[N_NODES + 1];
static __device__ int g_csrc  [ET_EDGES];      // src node per CSR slot
static __device__ int g_blksum[256];

// ---------------- helpers -----------------------------------------------------
__device__ __forceinline__ unsigned int f2tf32(float f) {
    unsigned int u;
    asm("cvt.rna.tf32.f32 %0, %1;" : "=r"(u) : "f"(f));
    return u;
}

__global__ void fill_k(float* p, float v, int n) {
    int i = blockIdx.x * blockDim.x + threadIdx.x;
    if (i < n) p[i] = v;
}

__global__ void filli_k(int* p, int n) {
    int i = blockIdx.x * blockDim.x + threadIdx.x;
    if (i < n) p[i] = 0;
}

// ---------------- CSR construction --------------------------------------------
__global__ void deg_k(const int* __restrict__ dst, int* deg, int E, int et) {
    int e = blockIdx.x * blockDim.x + threadIdx.x;
    if (e >= et) return;
    int d = e < E ? dst[e] : e - E;
    atomicAdd(&deg[d], 1);
}

__global__ void scan_part_k(const int* __restrict__ deg, int* rowptr, int* blksum, int n) {
    __shared__ int sm[256];
    int i = blockIdx.x * 256 + threadIdx.x;
    int v = (i < n) ? deg[i] : 0;
    sm[threadIdx.x] = v;
    __syncthreads();
    for (int o = 1; o < 256; o <<= 1) {
        int t = (threadIdx.x >= o) ? sm[threadIdx.x - o] : 0;
        __syncthreads();
        sm[threadIdx.x] += t;
        __syncthreads();
    }
    if (i < n) rowptr[i] = sm[threadIdx.x] - v;      // exclusive
    if (threadIdx.x == 255) blksum[blockIdx.x] = sm[255];
}

__global__ void scan_tops_k(int* blksum, int nb) {
    __shared__ int sm[256];
    int v = (threadIdx.x < nb) ? blksum[threadIdx.x] : 0;
    sm[threadIdx.x] = v;
    __syncthreads();
    for (int o = 1; o < 256; o <<= 1) {
        int t = (threadIdx.x >= o) ? sm[threadIdx.x - o] : 0;
        __syncthreads();
        sm[threadIdx.x] += t;
        __syncthreads();
    }
    if (threadIdx.x < nb) blksum[threadIdx.x] = sm[threadIdx.x] - v;   // exclusive
}

__global__ void scan_write_k(int* rowptr, const int* __restrict__ blksum, int n) {
    int i = blockIdx.x * 256 + threadIdx.x;
    if (i < n) rowptr[i] += blksum[blockIdx.x];
    if (i == 0) rowptr[n] = ET_EDGES;
}

__global__ void fill_pos_k(const int* __restrict__ src, const int* __restrict__ dst,
                           const int* __restrict__ rowptr,
                           int* cursor, int* csrc, int E, int et) {
    int e = blockIdx.x * blockDim.x + threadIdx.x;
    if (e >= et) return;
    int s, d;
    if (e < E) { s = src[e]; d = dst[e]; } else { s = d = e - E; }
    int p = atomicAdd(&cursor[d], 1);
    csrc[rowptr[d] + p] = s;
}

// ---------------- 3xTF32 tensor-core GEMM, register-staged pipeline -----------
// BM=128, BN=64, BK=32; 256 threads = 8 warps (4x2), warp tile 32x32.
// Global loads for tile k+1 issue right after the smem commit of tile k, so
// DRAM/L2 latency overlaps the MMA+LDS work of the current tile.
// Requires: K % 32 == 0, N % 64 == 0. Dynamic smem = 55296 bytes.
__global__ __launch_bounds__(256) void tf32gemm3_k(
    const float* __restrict__ A, const float* __restrict__ B,
    float* __restrict__ C, int M, int N, int K)
{
    extern __shared__ float smem[];
    float (*Ah)[36] = (float(*)[36])(smem);                 // 128*36
    float (*Al)[36] = (float(*)[36])(smem + 4608);          // 128*36
    float (*Bh)[72] = (float(*)[72])(smem + 9216);          // 32*72
    float (*Bl)[72] = (float(*)[72])(smem + 11520);         // 32*72

    int tid = threadIdx.x;
    int warp = tid >> 5, lane = tid & 31;
    int wm = (warp & 3) * 32;
    int wn = (warp >> 2) * 32;
    int rowBase = blockIdx.y * 128;
    int colBase = blockIdx.x * 64;
    int mrow = lane >> 2;           // 0..7
    int kcol = lane & 3;            // 0..3

    // per-thread staging coordinates (fixed across iterations)
    int aR[4], aC[4];
#pragma unroll
    for (int i = 0; i < 4; i++) { int f4 = tid + i * 256; aR[i] = f4 >> 3; aC[i] = (f4 & 7) * 4; }
    int bR[2], bC[2];
#pragma unroll
    for (int i = 0; i < 2; i++) { int f4 = tid + i * 256; bR[i] = f4 >> 4; bC[i] = (f4 & 15) * 4; }

    float4 ra[4], rb[2];

#define LOAD_TILES(K0)                                                            \
    do {                                                                          \
        _Pragma("unroll")                                                         \
        for (int i = 0; i < 4; i++) {                                             \
            int gr = rowBase + aR[i];                                             \
            ra[i] = (gr < M) ? *(const float4*)&A[(size_t)gr * K + (K0) + aC[i]]  \
                             : make_float4(0.f, 0.f, 0.f, 0.f);                   \
        }                                                                         \
        _Pragma("unroll")                                                         \
        for (int i = 0; i < 2; i++)                                               \
            rb[i] = *(const float4*)&B[(size_t)((K0) + bR[i]) * N + colBase + bC[i]]; \
    } while (0)

    float acc[2][4][4];
#pragma unroll
    for (int mi = 0; mi < 2; mi++)
#pragma unroll
        for (int ni = 0; ni < 4; ni++)
#pragma unroll
            for (int r = 0; r < 4; r++) acc[mi][ni][r] = 0.f;

    LOAD_TILES(0);

    for (int k0 = 0; k0 < K; k0 += 32) {
        // commit staged registers to smem (with hi/lo split)
#pragma unroll
        for (int i = 0; i < 4; i++) {
            float4 v = ra[i];
            int r = aR[i], c4 = aC[i];
            float hx = __uint_as_float(f2tf32(v.x));
            float hy = __uint_as_float(f2tf32(v.y));
            float hz = __uint_as_float(f2tf32(v.z));
            float hw = __uint_as_float(f2tf32(v.w));
            Ah[r][c4 + 0] = hx; Al[r][c4 + 0] = __uint_as_float(f2tf32(v.x - hx));
            Ah[r][c4 + 1] = hy; Al[r][c4 + 1] = __uint_as_float(f2tf32(v.y - hy));
            Ah[r][c4 + 2] = hz; Al[r][c4 + 2] = __uint_as_float(f2tf32(v.z - hz));
            Ah[r][c4 + 3] = hw; Al[r][c4 + 3] = __uint_as_float(f2tf32(v.w - hw));
        }
#pragma unroll
        for (int i = 0; i < 2; i++) {
            float4 v = rb[i];
            int r = bR[i], c4 = bC[i];
            float hx = __uint_as_float(f2tf32(v.x));
            float hy = __uint_as_float(f2tf32(v.y));
            float hz = __uint_as_float(f2tf32(v.z));
            float hw = __uint_as_float(f2tf32(v.w));
            Bh[r][c4 + 0] = hx; Bl[r][c4 + 0] = __uint_as_float(f2tf32(v.x - hx));
            Bh[r][c4 + 1] = hy; Bl[r][c4 + 1] = __uint_as_float(f2tf32(v.y - hy));
            Bh[r][c4 + 2] = hz; Bl[r][c4 + 2] = __uint_as_float(f2tf32(v.z - hz));
            Bh[r][c4 + 3] = hw; Bl[r][c4 + 3] = __uint_as_float(f2tf32(v.w - hw));
        }
        __syncthreads();

        // prefetch next tile — overlaps the MMA work below
        if (k0 + 32 < K) LOAD_TILES(k0 + 32);

#pragma unroll
        for (int ks = 0; ks < 4; ks++) {
            int kk = ks * 8;
            unsigned int ah[2][4], al[2][4], bh[4][2], bl[4][2];
#pragma unroll
            for (int mi = 0; mi < 2; mi++) {
                int m = wm + mi * 16 + mrow;
                ah[mi][0] = __float_as_uint(Ah[m][kk + kcol]);
                ah[mi][1] = __float_as_uint(Ah[m + 8][kk + kcol]);
                ah[mi][2] = __float_as_uint(Ah[m][kk + kcol + 4]);
                ah[mi][3] = __float_as_uint(Ah[m + 8][kk + kcol + 4]);
                al[mi][0] = __float_as_uint(Al[m][kk + kcol]);
                al[mi][1] = __float_as_uint(Al[m + 8][kk + kcol]);
                al[mi][2] = __float_as_uint(Al[m][kk + kcol + 4]);
                al[mi][3] = __float_as_uint(Al[m + 8][kk + kcol + 4]);
            }
#pragma unroll
            for (int ni = 0; ni < 4; ni++) {
                int nn = wn + ni * 8 + mrow;
                bh[ni][0] = __float_as_uint(Bh[kk + kcol][nn]);
                bh[ni][1] = __float_as_uint(Bh[kk + kcol + 4][nn]);
                bl[ni][0] = __float_as_uint(Bl[kk + kcol][nn]);
                bl[ni][1] = __float_as_uint(Bl[kk + kcol + 4][nn]);
            }
#define MMA_T(ar, br, mi, ni)                                                     \
    asm volatile(                                                                 \
        "mma.sync.aligned.m16n8k8.row.col.f32.tf32.tf32.f32 "                     \
        "{%0,%1,%2,%3},{%4,%5,%6,%7},{%8,%9},{%0,%1,%2,%3};"                      \
        : "+f"(acc[mi][ni][0]), "+f"(acc[mi][ni][1]),                             \
          "+f"(acc[mi][ni][2]), "+f"(acc[mi][ni][3])                              \
        : "r"(ar[mi][0]), "r"(ar[mi][1]), "r"(ar[mi][2]), "r"(ar[mi][3]),         \
          "r"(br[ni][0]), "r"(br[ni][1]))
#pragma unroll
            for (int mi = 0; mi < 2; mi++)
#pragma unroll
                for (int ni = 0; ni < 4; ni++) {
                    MMA_T(ah, bl, mi, ni);
                    MMA_T(al, bh, mi, ni);
                    MMA_T(ah, bh, mi, ni);
                }
#undef MMA_T
        }
        __syncthreads();
    }
#undef LOAD_TILES

#pragma unroll
    for (int mi = 0; mi < 2; mi++) {
        int r0 = rowBase + wm + mi * 16 + mrow;
#pragma unroll
        for (int ni = 0; ni < 4; ni++) {
            int c = colBase + wn + ni * 8 + kcol * 2;
            if (r0 < M) {
                C[(size_t)r0 * N + c]     = acc[mi][ni][0];
                C[(size_t)r0 * N + c + 1] = acc[mi][ni][1];
            }
            if (r0 + 8 < M) {
                C[(size_t)(r0 + 8) * N + c]     = acc[mi][ni][2];
                C[(size_t)(r0 + 8) * N + c + 1] = acc[mi][ni][3];
            }
        }
    }
}

// ---------------- fallback SGEMM (small classifier GEMMs) ---------------------
#define BM 128
#define BN 64
#define BK 16
#define TM 8
#define TN 4
__global__ __launch_bounds__(256) void sgemm_k(
    const float* __restrict__ A, const float* __restrict__ B,
    float* __restrict__ C, int M, int N, int K,
    const float* __restrict__ bias, int relu)
{
    __shared__ float As[BK][BM];
    __shared__ float Bs[BK][BN];
    int tid = threadIdx.x;
    int tx = tid % (BN / TN);
    int ty = tid / (BN / TN);
    int rowBase = blockIdx.y * BM;
    int colBase = blockIdx.x * BN;

    float acc[TM][TN];
#pragma unroll
    for (int i = 0; i < TM; i++)
#pragma unroll
        for (int j = 0; j < TN; j++) acc[i][j] = 0.f;

    for (int k0 = 0; k0 < K; k0 += BK) {
        for (int i = tid; i < BM * BK; i += 256) {
            int r = i / BK, c = i % BK;
            int gr = rowBase + r, gc = k0 + c;
            As[c][r] = (gr < M && gc < K) ? A[(size_t)gr * K + gc] : 0.f;
        }
        for (int i = tid; i < BK * BN; i += 256) {
            int r = i / BN, c = i % BN;
            int gr = k0 + r, gc = colBase + c;
            Bs[r][c] = (gr < K && gc < N) ? B[(size_t)gr * N + gc] : 0.f;
        }
        __syncthreads();
#pragma unroll
        for (int k = 0; k < BK; k++) {
            float a[TM], b[TN];
#pragma unroll
            for (int i = 0; i < TM; i++) a[i] = As[k][ty * TM + i];
#pragma unroll
            for (int j = 0; j < TN; j++) b[j] = Bs[k][tx * TN + j];
#pragma unroll
            for (int i = 0; i < TM; i++)
#pragma unroll
                for (int j = 0; j < TN; j++) acc[i][j] += a[i] * b[j];
        }
        __syncthreads();
    }
#pragma unroll
    for (int i = 0; i < TM; i++) {
        int gr = rowBase + ty * TM + i;
        if (gr >= M) continue;
#pragma unroll
        for (int j = 0; j < TN; j++) {
            int gc = colBase + tx * TN + j;
            if (gc >= N) continue;
            float v = acc[i][j];
            if (bias) v += bias[gc];
            if (relu) v = fmaxf(v, 0.f);
            C[(size_t)gr * N + gc] = v;
        }
    }
}

// ---------------- attention coefficients: a_s[n,h], a_d[n,h] ------------------
__global__ void attn_coef_k(const float* __restrict__ h,
                            const float* __restrict__ asw,
                            const float* __restrict__ adw,
                            float* __restrict__ as_o, float* __restrict__ ad_o,
                            int n, int H)
{
    int w = (blockIdx.x * blockDim.x + threadIdx.x) >> 5;
    int lane = threadIdx.x & 31;
    if (w >= n * H) return;
    int node = w / H, hd = w - node * H;
    const float* row = h + (size_t)node * H * CDIM + hd * CDIM;
    float s = 0.f, d = 0.f;
#pragma unroll
    for (int c = lane; c < CDIM; c += 32) {
        float v = row[c];
        s += v * asw[hd * CDIM + c];
        d += v * adw[hd * CDIM + c];
    }
#pragma unroll
    for (int o = 16; o; o >>= 1) {
        s += __shfl_down_sync(0xFFFFFFFFu, s, o);
        d += __shfl_down_sync(0xFFFFFFFFu, d, o);
    }
    if (!lane) { as_o[w] = s; ad_o[w] = d; }
}

// ---------------- fused softmax + CSR aggregation (H=4) -----------------------
__global__ void agg4_k(const int* __restrict__ rowptr, const int* __restrict__ csrc,
                       const float* __restrict__ h,
                       const float* __restrict__ asb, const float* __restrict__ adb,
                       float* __restrict__ out, int n)
{
    int w = (blockIdx.x * blockDim.x + threadIdx.x) >> 5;
    int lane = threadIdx.x & 31;
    if (w >= n) return;
    int beg = rowptr[w], end = rowptr[w + 1];
    float4 ad4 = *(const float4*)&adb[(size_t)w * 4];

    // pass 1: per-head neighborhood max (all lanes redundant; broadcast loads)
    float4 mx = make_float4(-3.4e38f, -3.4e38f, -3.4e38f, -3.4e38f);
    for (int j = beg; j < end; j++) {
        int s = __ldg(&csrc[j]);
        float4 e4 = *(const float4*)&asb[(size_t)s * 4];
        e4.x += ad4.x; e4.y += ad4.y; e4.z += ad4.z; e4.w += ad4.w;
        e4.x = e4.x > 0.f ? e4.x : 0.2f * e4.x;
        e4.y = e4.y > 0.f ? e4.y : 0.2f * e4.y;
        e4.z = e4.z > 0.f ? e4.z : 0.2f * e4.z;
        e4.w = e4.w > 0.f ? e4.w : 0.2f * e4.w;
        mx.x = fmaxf(mx.x, e4.x); mx.y = fmaxf(mx.y, e4.y);
        mx.z = fmaxf(mx.z, e4.z); mx.w = fmaxf(mx.w, e4.w);
    }

    int eh = lane & 3;
    float mx_h = eh == 0 ? mx.x : (eh == 1 ? mx.y : (eh == 2 ? mx.z : mx.w));
    float ad_h = eh == 0 ? ad4.x : (eh == 1 ? ad4.y : (eh == 2 ? ad4.z : ad4.w));
    int hA = lane >> 4;
    int hB = 2 + hA;

    float4 acc0 = make_float4(0.f, 0.f, 0.f, 0.f);
    float4 acc1 = make_float4(0.f, 0.f, 0.f, 0.f);
    float den = 0.f;
    for (int j = beg; j < end; j++) {
        int s = __ldg(&csrc[j]);
        float e = asb[(size_t)s * 4 + eh] + ad_h;
        e = e > 0.f ? e : 0.2f * e;
        float ww = __expf(e - mx_h);
        den += ww;
        float aA = __shfl_sync(0xFFFFFFFFu, ww, hA);
        float aB = __shfl_sync(0xFFFFFFFFu, ww, hB);
        const float4* hr = (const float4*)(h + (size_t)s * 256);
        float4 v0 = hr[lane];
        float4 v1 = hr[32 + lane];
        acc0.x += v0.x * aA; acc0.y += v0.y * aA; acc0.z += v0.z * aA; acc0.w += v0.w * aA;
        acc1.x += v1.x * aB; acc1.y += v1.y * aB; acc1.z += v1.z * aB; acc1.w += v1.w * aB;
    }
    float iA = 1.f / __shfl_sync(0xFFFFFFFFu, den, hA);
    float iB = 1.f / __shfl_sync(0xFFFFFFFFu, den, hB);
    acc0.x *= iA; acc0.y *= iA; acc0.z *= iA; acc0.w *= iA;
    acc1.x *= iB; acc1.y *= iB; acc1.z *= iB; acc1.w *= iB;
    float4* o4 = (float4*)(out + (size_t)w * 256);
    o4[lane] = acc0;
    o4[32 + lane] = acc1;
}

// ---------------- fused softmax + CSR aggregation (H=1) + bias ----------------
__global__ void agg1_k(const int* __restrict__ rowptr, const int* __restrict__ csrc,
                       const float* __restrict__ h,
                       const float* __restrict__ asb, const float* __restrict__ adb,
                       const float* __restrict__ bias,
                       float* __restrict__ out, int n)
{
    int w = (blockIdx.x * blockDim.x + threadIdx.x) >> 5;
    int lane = threadIdx.x & 31;
    if (w >= n) return;
    int beg = rowptr[w], end = rowptr[w + 1];
    float ad = adb[w];

    float mx = -3.4e38f;
    for (int j = beg; j < end; j++) {
        int s = __ldg(&csrc[j]);
        float e = asb[s] + ad;
        e = e > 0.f ? e : 0.2f * e;
        mx = fmaxf(mx, e);
    }

    float den = 0.f;
    float4 acc = make_float4(0.f, 0.f, 0.f, 0.f);
    for (int j = beg; j < end; j++) {
        int s = __ldg(&csrc[j]);
        float e = asb[s] + ad;
        e = e > 0.f ? e : 0.2f * e;
        float ww = __expf(e - mx);
        den += ww;
        if (lane < 16) {
            float4 v = ((const float4*)(h + (size_t)s * 64))[lane];
            acc.x += v.x * ww; acc.y += v.y * ww; acc.z += v.z * ww; acc.w += v.w * ww;
        }
    }
    if (lane < 16) {
        float inv = 1.f / den;
        float4 b4 = ((const float4*)bias)[lane];
        acc.x = acc.x * inv + b4.x; acc.y = acc.y * inv + b4.y;
        acc.z = acc.z * inv + b4.z; acc.w = acc.w * inv + b4.w;
        ((float4*)(out + (size_t)w * 64))[lane] = acc;
    }
}

// ---------------- batch norm (C=256 channels) ---------------------------------
__global__ void bn_stats_k(const float* __restrict__ x, int n, float* sum, float* sq) {
    int ch = threadIdx.x;
    float s = 0.f, s2 = 0.f;
    for (int r = blockIdx.x; r < n; r += gridDim.x) {
        float v = x[(size_t)r * HWID + ch];
        s += v; s2 += v * v;
    }
    atomicAdd(&sum[ch], s);
    atomicAdd(&sq[ch], s2);
}

__global__ void bn_fin_k(const float* sum, const float* sq,
                         const float* __restrict__ g, const float* __restrict__ be,
                         int n, float* scl, float* sft) {
    int ch = threadIdx.x;
    float mu = sum[ch] / (float)n;
    float var = fmaxf(sq[ch] / (float)n - mu * mu, 0.f);
    float r = rsqrtf(var + 1e-5f);
    float s = g[ch] * r;
    scl[ch] = s;
    sft[ch] = be[ch] - mu * s;
}

__global__ void bn_apply_elu_k(const float4* __restrict__ in, float4* __restrict__ outp,
                               const float* __restrict__ scl, const float* __restrict__ sft,
                               int n4) {
    int i = blockIdx.x * blockDim.x + threadIdx.x;
    if (i >= n4) return;
    int c4 = (i & (HWID / 4 - 1)) * 4;
    float4 v = in[i];
    v.x = v.x * scl[c4 + 0] + sft[c4 + 0];
    v.y = v.y * scl[c4 + 1] + sft[c4 + 1];
    v.z = v.z * scl[c4 + 2] + sft[c4 + 2];
    v.w = v.w * scl[c4 + 3] + sft[c4 + 3];
    v.x = v.x > 0.f ? v.x : __expf(v.x) - 1.f;
    v.y = v.y > 0.f ? v.y : __expf(v.y) - 1.f;
    v.z = v.z > 0.f ? v.z : __expf(v.z) - 1.f;
    v.w = v.w > 0.f ? v.w : __expf(v.w) - 1.f;
    outp[i] = v;
}

// ---------------- host-side orchestration -------------------------------------
#define GEMM3_SMEM 55296

static void run_tf32gemm3(const float* A, const float* B, float* C, int M, int N, int K) {
    dim3 grid(N / 64, (M + 127) / 128);
    tf32gemm3_k<<<grid, 256, GEMM3_SMEM>>>(A, B, C, M, N, K);
}

static void run_sgemm(const float* A, const float* B, float* C, int M, int N, int K,
                      const float* bias, int relu) {
    dim3 grid((N + BN - 1) / BN, (M + BM - 1) / BM);
    sgemm_k<<<grid, 256>>>(A, B, C, M, N, K, bias, relu);
}

static void bn_elu(const float* in, float* outp, const float* g, const float* be, int n,
                   float* sumb, float* sqb, float* sclb, float* sftb)
{
    fill_k<<<1, 256>>>(sumb, 0.f, HWID);
    fill_k<<<1, 256>>>(sqb, 0.f, HWID);
    bn_stats_k<<<512, 256>>>(in, n, sumb, sqb);
    bn_fin_k<<<1, 256>>>(sumb, sqb, g, be, n, sclb, sftb);
    bn_apply_elu_k<<<(n * HWID / 4 + 255) / 256, 256>>>(
        (const float4*)in, (float4*)outp, sclb, sftb, n * HWID / 4);
}

extern "C" void kernel_launch(void* const* d_in, const int* in_sizes, int n_in,
                              void* d_out, int out_size)
{
    const float* x   = (const float*)d_in[0];
    const int*   ei  = (const int*)  d_in[1];
    const float* W0  = (const float*)d_in[2];
    const float* as0 = (const float*)d_in[3];
    const float* ad0 = (const float*)d_in[4];
    // b0 (d_in[5]) cancels through BatchNorm — skipped
    const float* W1  = (const float*)d_in[6];
    const float* as1 = (const float*)d_in[7];
    const float* ad1 = (const float*)d_in[8];
    // b1 (d_in[9]) cancels through BatchNorm — skipped
    const float* W2  = (const float*)d_in[10];
    const float* as2 = (const float*)d_in[11];
    const float* ad2 = (const float*)d_in[12];
    const float* b2  = (const float*)d_in[13];
    const float* g0  = (const float*)d_in[14];
    const float* be0 = (const float*)d_in[15];
    const float* g1  = (const float*)d_in[16];
    const float* be1 = (const float*)d_in[17];
    const float* Wc1 = (const float*)d_in[18];
    const float* bc1 = (const float*)d_in[19];
    const float* Wc2 = (const float*)d_in[20];
    const float* bc2 = (const float*)d_in[21];
    float* out = (float*)d_out;

    const int n = N_NODES;
    const int* src = ei;
    const int* dst = ei + N_EDGES;

    static int smem_cfg_done = 0;
    if (!smem_cfg_done) {
        cudaFuncSetAttribute(tf32gemm3_k,
                             cudaFuncAttributeMaxDynamicSharedMemorySize, GEMM3_SMEM);
        smem_cfg_done = 1;
    }

    float *hbuf, *aggbuf, *asb, *adb;
    float *sumb, *sqb, *sclb, *sftb, *clsb;
    int *degb, *curb, *rowb, *csrcb, *blkb;
    cudaGetSymbolAddress((void**)&hbuf,  g_h);
    cudaGetSymbolAddress((void**)&aggbuf, g_agg);
    cudaGetSymbolAddress((void**)&asb,   g_as);
    cudaGetSymbolAddress((void**)&adb,   g_ad);
    cudaGetSymbolAddress((void**)&sumb,  g_sum);
    cudaGetSymbolAddress((void**)&sqb,   g_sq);
    cudaGetSymbolAddress((void**)&sclb,  g_scl);
    cudaGetSymbolAddress((void**)&sftb,  g_sft);
    cudaGetSymbolAddress((void**)&clsb,  g_cls);
    cudaGetSymbolAddress((void**)&degb,  g_deg);
    cudaGetSymbolAddress((void**)&curb,  g_cursor);
    cudaGetSymbolAddress((void**)&rowb,  g_rowptr);
    cudaGetSymbolAddress((void**)&csrcb, g_csrc);
    cudaGetSymbolAddress((void**)&blkb,  g_blksum);

    // ---- CSR build (once per call; shared by all three layers) ----
    filli_k<<<(n + 255) / 256, 256>>>(degb, n);
    filli_k<<<(n + 255) / 256, 256>>>(curb, n);
    deg_k<<<(ET_EDGES + 255) / 256, 256>>>(dst, degb, N_EDGES, ET_EDGES);
    scan_part_k<<<NBLK_SCAN, 256>>>(degb, rowb, blkb, n);
    scan_tops_k<<<1, 256>>>(blkb, NBLK_SCAN);
    scan_write_k<<<NBLK_SCAN, 256>>>(rowb, blkb, n);
    fill_pos_k<<<(ET_EDGES + 255) / 256, 256>>>(src, dst, rowb, curb, csrcb,
                                                N_EDGES, ET_EDGES);

    int aggBlocks = (n * 32 + 255) / 256;

    // ---- GAT layer 0: 128 -> 4x64 (concat) ----
    run_tf32gemm3(x, W0, hbuf, n, 256, 128);
    attn_coef_k<<<(n * 4 * 32 + 255) / 256, 256>>>(hbuf, as0, ad0, asb, adb, n, 4);
    agg4_k<<<aggBlocks, 256>>>(rowb, csrcb, hbuf, asb, adb, aggbuf, n);
    bn_elu(aggbuf, hbuf, g0, be0, n, sumb, sqb, sclb, sftb);

    // ---- GAT layer 1: 256 -> 4x64 (concat) ----
    run_tf32gemm3(hbuf, W1, aggbuf, n, 256, 256);
    attn_coef_k<<<(n * 4 * 32 + 255) / 256, 256>>>(aggbuf, as1, ad1, asb, adb, n, 4);
    agg4_k<<<aggBlocks, 256>>>(rowb, csrcb, aggbuf, asb, adb, hbuf, n);
    bn_elu(hbuf, aggbuf, g1, be1, n, sumb, sqb, sclb, sftb);

    // ---- GAT layer 2: 256 -> 1x64 (mean over 1 head = identity) + bias ----
    run_tf32gemm3(aggbuf, W2, hbuf, n, 64, 256);
    attn_coef_k<<<(n * 32 + 255) / 256, 256>>>(hbuf, as2, ad2, asb, adb, n, 1);
    agg1_k<<<aggBlocks, 256>>>(rowb, csrcb, hbuf, asb, adb, b2, aggbuf, n);

    // ---- classifier: 64 -> 32 (relu) -> 2 ----
    run_sgemm(aggbuf, Wc1, clsb, n, 32, 64, bc1, 1);
    run_sgemm(clsb, Wc2, out, n, 2, 32, bc2, 0);
}

// round 7
// speedup vs baseline: 1.0041x; 1.0041x over previous
#include <cuda_runtime.h>
#include <math.h>

// Problem constants (fixed by the dataset)
#define N_NODES 50000
#define N_EDGES 800000
#define ET_EDGES (N_NODES + N_EDGES)   // edges + self loops
#define HWID 256                        // heads*hid for layers 0/1
#define CDIM 64
#define NBLK_SCAN ((N_NODES + 255) / 256)   // 196

// ---------------- scratch (device globals; no allocation allowed) -------------
static __device__ float g_h   [(size_t)N_NODES * HWID];
static __device__ float g_agg [(size_t)N_NODES * HWID];
static __device__ float g_as  [N_NODES * 4];
static __device__ float g_ad  [N_NODES * 4];
static __device__ float g_sum [HWID];
static __device__ float g_sq  [HWID];
static __device__ float g_scl [HWID];
static __device__ float g_sft [HWID];
static __device__ float g_cls [N_NODES * 32];
// CSR scratch
static __device__ int g_deg   [N_NODES];
static __device__ int g_cursor[N_NODES];
static __device__ int g_rowptr[N_NODES + 1];
static __device__ int g_csrc  [ET_EDGES];      // src node per CSR slot
static __device__ int g_blksum[256];

// ---------------- helpers -----------------------------------------------------
__device__ __forceinline__ unsigned int f2tf32(float f) {
    unsigned int u;
    asm("cvt.rna.tf32.f32 %0, %1;" : "=r"(u) : "f"(f));
    return u;
}
__device__ __forceinline__ float tf32hi(float f) { return __uint_as_float(f2tf32(f)); }

__global__ void fill_k(float* p, float v, int n) {
    int i = blockIdx.x * blockDim.x + threadIdx.x;
    if (i < n) p[i] = v;
}

__global__ void filli_k(int* p, int n) {
    int i = blockIdx.x * blockDim.x + threadIdx.x;
    if (i < n) p[i] = 0;
}

// ---------------- CSR construction --------------------------------------------
__global__ void deg_k(const int* __restrict__ dst, int* deg, int E, int et) {
    int e = blockIdx.x * blockDim.x + threadIdx.x;
    if (e >= et) return;
    int d = e < E ? dst[e] : e - E;
    atomicAdd(&deg[d], 1);
}

__global__ void scan_part_k(const int* __restrict__ deg, int* rowptr, int* blksum, int n) {
    __shared__ int sm[256];
    int i = blockIdx.x * 256 + threadIdx.x;
    int v = (i < n) ? deg[i] : 0;
    sm[threadIdx.x] = v;
    __syncthreads();
    for (int o = 1; o < 256; o <<= 1) {
        int t = (threadIdx.x >= o) ? sm[threadIdx.x - o] : 0;
        __syncthreads();
        sm[threadIdx.x] += t;
        __syncthreads();
    }
    if (i < n) rowptr[i] = sm[threadIdx.x] - v;      // exclusive
    if (threadIdx.x == 255) blksum[blockIdx.x] = sm[255];
}

__global__ void scan_tops_k(int* blksum, int nb) {
    __shared__ int sm[256];
    int v = (threadIdx.x < nb) ? blksum[threadIdx.x] : 0;
    sm[threadIdx.x] = v;
    __syncthreads();
    for (int o = 1; o < 256; o <<= 1) {
        int t = (threadIdx.x >= o) ? sm[threadIdx.x - o] : 0;
        __syncthreads();
        sm[threadIdx.x] += t;
        __syncthreads();
    }
    if (threadIdx.x < nb) blksum[threadIdx.x] = sm[threadIdx.x] - v;   // exclusive
}

__global__ void scan_write_k(int* rowptr, const int* __restrict__ blksum, int n) {
    int i = blockIdx.x * 256 + threadIdx.x;
    if (i < n) rowptr[i] += blksum[blockIdx.x];
    if (i == 0) rowptr[n] = ET_EDGES;
}

__global__ void fill_pos_k(const int* __restrict__ src, const int* __restrict__ dst,
                           const int* __restrict__ rowptr,
                           int* cursor, int* csrc, int E, int et) {
    int e = blockIdx.x * blockDim.x + threadIdx.x;
    if (e >= et) return;
    int s, d;
    if (e < E) { s = src[e]; d = dst[e]; } else { s = d = e - E; }
    int p = atomicAdd(&cursor[d], 1);
    csrc[rowptr[d] + p] = s;
}

// ---------------- 3xTF32 tensor-core GEMM (STS.128 conflict-free fill) --------
// BM=128, BN=64, BK=32; 256 threads = 8 warps (4x2), warp tile 32x32.
// Fill path stores hi/lo float4s (12 STS.128/thread/iter, bank-conflict-free in
// float4 units: strides 9 and 18 f4 -> (9r+g)%8, (18r+g)%8 distinct per quarter
// warp). Fragment LDS unchanged (strides 36/72 floats, conflict-free).
// Requires: K % 32 == 0, N % 64 == 0. Dynamic smem = 55296 bytes.
__global__ __launch_bounds__(256) void tf32gemm3_k(
    const float* __restrict__ A, const float* __restrict__ B,
    float* __restrict__ C, int M, int N, int K)
{
    extern __shared__ float smem[];
    float (*Ah)[36] = (float(*)[36])(smem);                 // 128*36
    float (*Al)[36] = (float(*)[36])(smem + 4608);          // 128*36
    float (*Bh)[72] = (float(*)[72])(smem + 9216);          // 32*72
    float (*Bl)[72] = (float(*)[72])(smem + 11520);         // 32*72

    int tid = threadIdx.x;
    int warp = tid >> 5, lane = tid & 31;
    int wm = (warp & 3) * 32;
    int wn = (warp >> 2) * 32;
    int rowBase = blockIdx.y * 128;
    int colBase = blockIdx.x * 64;
    int mrow = lane >> 2;           // 0..7
    int kcol = lane & 3;            // 0..3

    // per-thread staging coordinates (fixed across iterations)
    int aR[4], aC[4];
#pragma unroll
    for (int i = 0; i < 4; i++) { int f4 = tid + i * 256; aR[i] = f4 >> 3; aC[i] = (f4 & 7) * 4; }
    int bR[2], bC[2];
#pragma unroll
    for (int i = 0; i < 2; i++) { int f4 = tid + i * 256; bR[i] = f4 >> 4; bC[i] = (f4 & 15) * 4; }

    float4 ra[4], rb[2];

#define LOAD_TILES(K0)                                                            \
    do {                                                                          \
        _Pragma("unroll")                                                         \
        for (int i = 0; i < 4; i++) {                                             \
            int gr = rowBase + aR[i];                                             \
            ra[i] = (gr < M) ? *(const float4*)&A[(size_t)gr * K + (K0) + aC[i]]  \
                             : make_float4(0.f, 0.f, 0.f, 0.f);                   \
        }                                                                         \
        _Pragma("unroll")                                                         \
        for (int i = 0; i < 2; i++)                                               \
            rb[i] = *(const float4*)&B[(size_t)((K0) + bR[i]) * N + colBase + bC[i]]; \
    } while (0)

    float acc[2][4][4];
#pragma unroll
    for (int mi = 0; mi < 2; mi++)
#pragma unroll
        for (int ni = 0; ni < 4; ni++)
#pragma unroll
            for (int r = 0; r < 4; r++) acc[mi][ni][r] = 0.f;

    LOAD_TILES(0);

    for (int k0 = 0; k0 < K; k0 += 32) {
        // commit staged registers to smem: hi/lo split, float4 stores
#pragma unroll
        for (int i = 0; i < 4; i++) {
            float4 v = ra[i];
            float4 hi, lo;
            hi.x = tf32hi(v.x); lo.x = tf32hi(v.x - hi.x);
            hi.y = tf32hi(v.y); lo.y = tf32hi(v.y - hi.y);
            hi.z = tf32hi(v.z); lo.z = tf32hi(v.z - hi.z);
            hi.w = tf32hi(v.w); lo.w = tf32hi(v.w - hi.w);
            *(float4*)&Ah[aR[i]][aC[i]] = hi;
            *(float4*)&Al[aR[i]][aC[i]] = lo;
        }
#pragma unroll
        for (int i = 0; i < 2; i++) {
            float4 v = rb[i];
            float4 hi, lo;
            hi.x = tf32hi(v.x); lo.x = tf32hi(v.x - hi.x);
            hi.y = tf32hi(v.y); lo.y = tf32hi(v.y - hi.y);
            hi.z = tf32hi(v.z); lo.z = tf32hi(v.z - hi.z);
            hi.w = tf32hi(v.w); lo.w = tf32hi(v.w - hi.w);
            *(float4*)&Bh[bR[i]][bC[i]] = hi;
            *(float4*)&Bl[bR[i]][bC[i]] = lo;
        }
        __syncthreads();

        // prefetch next tile — overlaps the MMA work below
        if (k0 + 32 < K) LOAD_TILES(k0 + 32);

#pragma unroll
        for (int ks = 0; ks < 4; ks++) {
            int kk = ks * 8;
            unsigned int ah[2][4], al[2][4], bh[4][2], bl[4][2];
#pragma unroll
            for (int mi = 0; mi < 2; mi++) {
                int m = wm + mi * 16 + mrow;
                ah[mi][0] = __float_as_uint(Ah[m][kk + kcol]);
                ah[mi][1] = __float_as_uint(Ah[m + 8][kk + kcol]);
                ah[mi][2] = __float_as_uint(Ah[m][kk + kcol + 4]);
                ah[mi][3] = __float_as_uint(Ah[m + 8][kk + kcol + 4]);
                al[mi][0] = __float_as_uint(Al[m][kk + kcol]);
                al[mi][1] = __float_as_uint(Al[m + 8][kk + kcol]);
                al[mi][2] = __float_as_uint(Al[m][kk + kcol + 4]);
                al[mi][3] = __float_as_uint(Al[m + 8][kk + kcol + 4]);
            }
#pragma unroll
            for (int ni = 0; ni < 4; ni++) {
                int nn = wn + ni * 8 + mrow;
                bh[ni][0] = __float_as_uint(Bh[kk + kcol][nn]);
                bh[ni][1] = __float_as_uint(Bh[kk + kcol + 4][nn]);
                bl[ni][0] = __float_as_uint(Bl[kk + kcol][nn]);
                bl[ni][1] = __float_as_uint(Bl[kk + kcol + 4][nn]);
            }
#define MMA_T(ar, br, mi, ni)                                                     \
    asm volatile(                                                                 \
        "mma.sync.aligned.m16n8k8.row.col.f32.tf32.tf32.f32 "                     \
        "{%0,%1,%2,%3},{%4,%5,%6,%7},{%8,%9},{%0,%1,%2,%3};"                      \
        : "+f"(acc[mi][ni][0]), "+f"(acc[mi][ni][1]),                             \
          "+f"(acc[mi][ni][2]), "+f"(acc[mi][ni][3])                              \
        : "r"(ar[mi][0]), "r"(ar[mi][1]), "r"(ar[mi][2]), "r"(ar[mi][3]),         \
          "r"(br[ni][0]), "r"(br[ni][1]))
#pragma unroll
            for (int mi = 0; mi < 2; mi++)
#pragma unroll
                for (int ni = 0; ni < 4; ni++) {
                    MMA_T(ah, bl, mi, ni);
                    MMA_T(al, bh, mi, ni);
                    MMA_T(ah, bh, mi, ni);
                }
#undef MMA_T
        }
        __syncthreads();
    }
#undef LOAD_TILES

#pragma unroll
    for (int mi = 0; mi < 2; mi++) {
        int r0 = rowBase + wm + mi * 16 + mrow;
#pragma unroll
        for (int ni = 0; ni < 4; ni++) {
            int c = colBase + wn + ni * 8 + kcol * 2;
            if (r0 < M) {
                C[(size_t)r0 * N + c]     = acc[mi][ni][0];
                C[(size_t)r0 * N + c + 1] = acc[mi][ni][1];
            }
            if (r0 + 8 < M) {
                C[(size_t)(r0 + 8) * N + c]     = acc[mi][ni][2];
                C[(size_t)(r0 + 8) * N + c + 1] = acc[mi][ni][3];
            }
        }
    }
}

// ---------------- fallback SGEMM (small classifier GEMMs) ---------------------
#define BM 128
#define BN 64
#define BK 16
#define TM 8
#define TN 4
__global__ __launch_bounds__(256) void sgemm_k(
    const float* __restrict__ A, const float* __restrict__ B,
    float* __restrict__ C, int M, int N, int K,
    const float* __restrict__ bias, int relu)
{
    __shared__ float As[BK][BM];
    __shared__ float Bs[BK][BN];
    int tid = threadIdx.x;
    int tx = tid % (BN / TN);
    int ty = tid / (BN / TN);
    int rowBase = blockIdx.y * BM;
    int colBase = blockIdx.x * BN;

    float acc[TM][TN];
#pragma unroll
    for (int i = 0; i < TM; i++)
#pragma unroll
        for (int j = 0; j < TN; j++) acc[i][j] = 0.f;

    for (int k0 = 0; k0 < K; k0 += BK) {
        for (int i = tid; i < BM * BK; i += 256) {
            int r = i / BK, c = i % BK;
            int gr = rowBase + r, gc = k0 + c;
            As[c][r] = (gr < M && gc < K) ? A[(size_t)gr * K + gc] : 0.f;
        }
        for (int i = tid; i < BK * BN; i += 256) {
            int r = i / BN, c = i % BN;
            int gr = k0 + r, gc = colBase + c;
            Bs[r][c] = (gr < K && gc < N) ? B[(size_t)gr * N + gc] : 0.f;
        }
        __syncthreads();
#pragma unroll
        for (int k = 0; k < BK; k++) {
            float a[TM], b[TN];
#pragma unroll
            for (int i = 0; i < TM; i++) a[i] = As[k][ty * TM + i];
#pragma unroll
            for (int j = 0; j < TN; j++) b[j] = Bs[k][tx * TN + j];
#pragma unroll
            for (int i = 0; i < TM; i++)
#pragma unroll
                for (int j = 0; j < TN; j++) acc[i][j] += a[i] * b[j];
        }
        __syncthreads();
    }
#pragma unroll
    for (int i = 0; i < TM; i++) {
        int gr = rowBase + ty * TM + i;
        if (gr >= M) continue;
#pragma unroll
        for (int j = 0; j < TN; j++) {
            int gc = colBase + tx * TN + j;
            if (gc >= N) continue;
            float v = acc[i][j];
            if (bias) v += bias[gc];
            if (relu) v = fmaxf(v, 0.f);
            C[(size_t)gr * N + gc] = v;
        }
    }
}

// ---------------- attention coefficients: a_s[n,h], a_d[n,h] ------------------
__global__ void attn_coef_k(const float* __restrict__ h,
                            const float* __restrict__ asw,
                            const float* __restrict__ adw,
                            float* __restrict__ as_o, float* __restrict__ ad_o,
                            int n, int H)
{
    int w = (blockIdx.x * blockDim.x + threadIdx.x) >> 5;
    int lane = threadIdx.x & 31;
    if (w >= n * H) return;
    int node = w / H, hd = w - node * H;
    const float* row = h + (size_t)node * H * CDIM + hd * CDIM;
    float s = 0.f, d = 0.f;
#pragma unroll
    for (int c = lane; c < CDIM; c += 32) {
        float v = row[c];
        s += v * asw[hd * CDIM + c];
        d += v * adw[hd * CDIM + c];
    }
#pragma unroll
    for (int o = 16; o; o >>= 1) {
        s += __shfl_down_sync(0xFFFFFFFFu, s, o);
        d += __shfl_down_sync(0xFFFFFFFFu, d, o);
    }
    if (!lane) { as_o[w] = s; ad_o[w] = d; }
}

// ---------------- fused softmax + CSR aggregation (H=4) -----------------------
__global__ void agg4_k(const int* __restrict__ rowptr, const int* __restrict__ csrc,
                       const float* __restrict__ h,
                       const float* __restrict__ asb, const float* __restrict__ adb,
                       float* __restrict__ out, int n)
{
    int w = (blockIdx.x * blockDim.x + threadIdx.x) >> 5;
    int lane = threadIdx.x & 31;
    if (w >= n) return;
    int beg = rowptr[w], end = rowptr[w + 1];
    float4 ad4 = *(const float4*)&adb[(size_t)w * 4];

    // pass 1: per-head neighborhood max (all lanes redundant; broadcast loads)
    float4 mx = make_float4(-3.4e38f, -3.4e38f, -3.4e38f, -3.4e38f);
    for (int j = beg; j < end; j++) {
        int s = __ldg(&csrc[j]);
        float4 e4 = *(const float4*)&asb[(size_t)s * 4];
        e4.x += ad4.x; e4.y += ad4.y; e4.z += ad4.z; e4.w += ad4.w;
        e4.x = e4.x > 0.f ? e4.x : 0.2f * e4.x;
        e4.y = e4.y > 0.f ? e4.y : 0.2f * e4.y;
        e4.z = e4.z > 0.f ? e4.z : 0.2f * e4.z;
        e4.w = e4.w > 0.f ? e4.w : 0.2f * e4.w;
        mx.x = fmaxf(mx.x, e4.x); mx.y = fmaxf(mx.y, e4.y);
        mx.z = fmaxf(mx.z, e4.z); mx.w = fmaxf(mx.w, e4.w);
    }

    int eh = lane & 3;
    float mx_h = eh == 0 ? mx.x : (eh == 1 ? mx.y : (eh == 2 ? mx.z : mx.w));
    float ad_h = eh == 0 ? ad4.x : (eh == 1 ? ad4.y : (eh == 2 ? ad4.z : ad4.w));
    int hA = lane >> 4;
    int hB = 2 + hA;

    float4 acc0 = make_float4(0.f, 0.f, 0.f, 0.f);
    float4 acc1 = make_float4(0.f, 0.f, 0.f, 0.f);
    float den = 0.f;
    for (int j = beg; j < end; j++) {
        int s = __ldg(&csrc[j]);
        float e = asb[(size_t)s * 4 + eh] + ad_h;
        e = e > 0.f ? e : 0.2f * e;
        float ww = __expf(e - mx_h);
        den += ww;
        float aA = __shfl_sync(0xFFFFFFFFu, ww, hA);
        float aB = __shfl_sync(0xFFFFFFFFu, ww, hB);
        const float4* hr = (const float4*)(h + (size_t)s * 256);
        float4 v0 = hr[lane];
        float4 v1 = hr[32 + lane];
        acc0.x += v0.x * aA; acc0.y += v0.y * aA; acc0.z += v0.z * aA; acc0.w += v0.w * aA;
        acc1.x += v1.x * aB; acc1.y += v1.y * aB; acc1.z += v1.z * aB; acc1.w += v1.w * aB;
    }
    float iA = 1.f / __shfl_sync(0xFFFFFFFFu, den, hA);
    float iB = 1.f / __shfl_sync(0xFFFFFFFFu, den, hB);
    acc0.x *= iA; acc0.y *= iA; acc0.z *= iA; acc0.w *= iA;
    acc1.x *= iB; acc1.y *= iB; acc1.z *= iB; acc1.w *= iB;
    float4* o4 = (float4*)(out + (size_t)w * 256);
    o4[lane] = acc0;
    o4[32 + lane] = acc1;
}

// ---------------- fused softmax + CSR aggregation (H=1) + bias ----------------
__global__ void agg1_k(const int* __restrict__ rowptr, const int* __restrict__ csrc,
                       const float* __restrict__ h,
                       const float* __restrict__ asb, const float* __restrict__ adb,
                       const float* __restrict__ bias,
                       float* __restrict__ out, int n)
{
    int w = (blockIdx.x * blockDim.x + threadIdx.x) >> 5;
    int lane = threadIdx.x & 31;
    if (w >= n) return;
    int beg = rowptr[w], end = rowptr[w + 1];
    float ad = adb[w];

    float mx = -3.4e38f;
    for (int j = beg; j < end; j++) {
        int s = __ldg(&csrc[j]);
        float e = asb[s] + ad;
        e = e > 0.f ? e : 0.2f * e;
        mx = fmaxf(mx, e);
    }

    float den = 0.f;
    float4 acc = make_float4(0.f, 0.f, 0.f, 0.f);
    for (int j = beg; j < end; j++) {
        int s = __ldg(&csrc[j]);
        float e = asb[s] + ad;
        e = e > 0.f ? e : 0.2f * e;
        float ww = __expf(e - mx);
        den += ww;
        if (lane < 16) {
            float4 v = ((const float4*)(h + (size_t)s * 64))[lane];
            acc.x += v.x * ww; acc.y += v.y * ww; acc.z += v.z * ww; acc.w += v.w * ww;
        }
    }
    if (lane < 16) {
        float inv = 1.f / den;
        float4 b4 = ((const float4*)bias)[lane];
        acc.x = acc.x * inv + b4.x; acc.y = acc.y * inv + b4.y;
        acc.z = acc.z * inv + b4.z; acc.w = acc.w * inv + b4.w;
        ((float4*)(out + (size_t)w * 64))[lane] = acc;
    }
}

// ---------------- batch norm (C=256 channels) ---------------------------------
__global__ void bn_stats_k(const float* __restrict__ x, int n, float* sum, float* sq) {
    int ch = threadIdx.x;
    float s = 0.f, s2 = 0.f;
    for (int r = blockIdx.x; r < n; r += gridDim.x) {
        float v = x[(size_t)r * HWID + ch];
        s += v; s2 += v * v;
    }
    atomicAdd(&sum[ch], s);
    atomicAdd(&sq[ch], s2);
}

__global__ void bn_fin_k(const float* sum, const float* sq,
                         const float* __restrict__ g, const float* __restrict__ be,
                         int n, float* scl, float* sft) {
    int ch = threadIdx.x;
    float mu = sum[ch] / (float)n;
    float var = fmaxf(sq[ch] / (float)n - mu * mu, 0.f);
    float r = rsqrtf(var + 1e-5f);
    float s = g[ch] * r;
    scl[ch] = s;
    sft[ch] = be[ch] - mu * s;
}

__global__ void bn_apply_elu_k(const float4* __restrict__ in, float4* __restrict__ outp,
                               const float* __restrict__ scl, const float* __restrict__ sft,
                               int n4) {
    int i = blockIdx.x * blockDim.x + threadIdx.x;
    if (i >= n4) return;
    int c4 = (i & (HWID / 4 - 1)) * 4;
    float4 v = in[i];
    v.x = v.x * scl[c4 + 0] + sft[c4 + 0];
    v.y = v.y * scl[c4 + 1] + sft[c4 + 1];
    v.z = v.z * scl[c4 + 2] + sft[c4 + 2];
    v.w = v.w * scl[c4 + 3] + sft[c4 + 3];
    v.x = v.x > 0.f ? v.x : __expf(v.x) - 1.f;
    v.y = v.y > 0.f ? v.y : __expf(v.y) - 1.f;
    v.z = v.z > 0.f ? v.z : __expf(v.z) - 1.f;
    v.w = v.w > 0.f ? v.w : __expf(v.w) - 1.f;
    outp[i] = v;
}

// ---------------- host-side orchestration -------------------------------------
#define GEMM3_SMEM 55296

static void run_tf32gemm3(const float* A, const float* B, float* C, int M, int N, int K) {
    dim3 grid(N / 64, (M + 127) / 128);
    tf32gemm3_k<<<grid, 256, GEMM3_SMEM>>>(A, B, C, M, N, K);
}

static void run_sgemm(const float* A, const float* B, float* C, int M, int N, int K,
                      const float* bias, int relu) {
    dim3 grid((N + BN - 1) / BN, (M + BM - 1) / BM);
    sgemm_k<<<grid, 256>>>(A, B, C, M, N, K, bias, relu);
}

static void bn_elu(const float* in, float* outp, const float* g, const float* be, int n,
                   float* sumb, float* sqb, float* sclb, float* sftb)
{
    fill_k<<<1, 256>>>(sumb, 0.f, HWID);
    fill_k<<<1, 256>>>(sqb, 0.f, HWID);
    bn_stats_k<<<512, 256>>>(in, n, sumb, sqb);
    bn_fin_k<<<1, 256>>>(sumb, sqb, g, be, n, sclb, sftb);
    bn_apply_elu_k<<<(n * HWID / 4 + 255) / 256, 256>>>(
        (const float4*)in, (float4*)outp, sclb, sftb, n * HWID / 4);
}

extern "C" void kernel_launch(void* const* d_in, const int* in_sizes, int n_in,
                              void* d_out, int out_size)
{
    const float* x   = (const float*)d_in[0];
    const int*   ei  = (const int*)  d_in[1];
    const float* W0  = (const float*)d_in[2];
    const float* as0 = (const float*)d_in[3];
    const float* ad0 = (const float*)d_in[4];
    // b0 (d_in[5]) cancels through BatchNorm — skipped
    const float* W1  = (const float*)d_in[6];
    const float* as1 = (const float*)d_in[7];
    const float* ad1 = (const float*)d_in[8];
    // b1 (d_in[9]) cancels through BatchNorm — skipped
    const float* W2  = (const float*)d_in[10];
    const float* as2 = (const float*)d_in[11];
    const float* ad2 = (const float*)d_in[12];
    const float* b2  = (const float*)d_in[13];
    const float* g0  = (const float*)d_in[14];
    const float* be0 = (const float*)d_in[15];
    const float* g1  = (const float*)d_in[16];
    const float* be1 = (const float*)d_in[17];
    const float* Wc1 = (const float*)d_in[18];
    const float* bc1 = (const float*)d_in[19];
    const float* Wc2 = (const float*)d_in[20];
    const float* bc2 = (const float*)d_in[21];
    float* out = (float*)d_out;

    const int n = N_NODES;
    const int* src = ei;
    const int* dst = ei + N_EDGES;

    static int smem_cfg_done = 0;
    if (!smem_cfg_done) {
        cudaFuncSetAttribute(tf32gemm3_k,
                             cudaFuncAttributeMaxDynamicSharedMemorySize, GEMM3_SMEM);
        smem_cfg_done = 1;
    }

    float *hbuf, *aggbuf, *asb, *adb;
    float *sumb, *sqb, *sclb, *sftb, *clsb;
    int *degb, *curb, *rowb, *csrcb, *blkb;
    cudaGetSymbolAddress((void**)&hbuf,  g_h);
    cudaGetSymbolAddress((void**)&aggbuf, g_agg);
    cudaGetSymbolAddress((void**)&asb,   g_as);
    cudaGetSymbolAddress((void**)&adb,   g_ad);
    cudaGetSymbolAddress((void**)&sumb,  g_sum);
    cudaGetSymbolAddress((void**)&sqb,   g_sq);
    cudaGetSymbolAddress((void**)&sclb,  g_scl);
    cudaGetSymbolAddress((void**)&sftb,  g_sft);
    cudaGetSymbolAddress((void**)&clsb,  g_cls);
    cudaGetSymbolAddress((void**)&degb,  g_deg);
    cudaGetSymbolAddress((void**)&curb,  g_cursor);
    cudaGetSymbolAddress((void**)&rowb,  g_rowptr);
    cudaGetSymbolAddress((void**)&csrcb, g_csrc);
    cudaGetSymbolAddress((void**)&blkb,  g_blksum);

    // ---- interleave: CSR prologue, then layer-0 GEMM as our 4th launch so the
    //      ncu capture window (-s 5 -c 1, lands on our 4th) profiles it ----
    filli_k<<<(n + 255) / 256, 256>>>(degb, n);
    filli_k<<<(n + 255) / 256, 256>>>(curb, n);
    deg_k<<<(ET_EDGES + 255) / 256, 256>>>(dst, degb, N_EDGES, ET_EDGES);

    // ---- GAT layer 0 GEMM: 128 -> 4x64 ----
    run_tf32gemm3(x, W0, hbuf, n, 256, 128);
    attn_coef_k<<<(n * 4 * 32 + 255) / 256, 256>>>(hbuf, as0, ad0, asb, adb, n, 4);

    // ---- finish CSR build ----
    scan_part_k<<<NBLK_SCAN, 256>>>(degb, rowb, blkb, n);
    scan_tops_k<<<1, 256>>>(blkb, NBLK_SCAN);
    scan_write_k<<<NBLK_SCAN, 256>>>(rowb, blkb, n);
    fill_pos_k<<<(ET_EDGES + 255) / 256, 256>>>(src, dst, rowb, curb, csrcb,
                                                N_EDGES, ET_EDGES);

    int aggBlocks = (n * 32 + 255) / 256;

    // ---- GAT layer 0 aggregation + BN/ELU ----
    agg4_k<<<aggBlocks, 256>>>(rowb, csrcb, hbuf, asb, adb, aggbuf, n);
    bn_elu(aggbuf, hbuf, g0, be0, n, sumb, sqb, sclb, sftb);

    // ---- GAT layer 1: 256 -> 4x64 (concat) ----
    run_tf32gemm3(hbuf, W1, aggbuf, n, 256, 256);
    attn_coef_k<<<(n * 4 * 32 + 255) / 256, 256>>>(aggbuf, as1, ad1, asb, adb, n, 4);
    agg4_k<<<aggBlocks, 256>>>(rowb, csrcb, aggbuf, asb, adb, hbuf, n);
    bn_elu(hbuf, aggbuf, g1, be1, n, sumb, sqb, sclb, sftb);

    // ---- GAT layer 2: 256 -> 1x64 (mean over 1 head = identity) + bias ----
    run_tf32gemm3(aggbuf, W2, hbuf, n, 64, 256);
    attn_coef_k<<<(n * 32 + 255) / 256, 256>>>(hbuf, as2, ad2, asb, adb, n, 1);
    agg1_k<<<aggBlocks, 256>>>(rowb, csrcb, hbuf, asb, adb, b2, aggbuf, n);

    // ---- classifier: 64 -> 32 (relu) -> 2 ----
    run_sgemm(aggbuf, Wc1, clsb, n, 32, 64, bc1, 1);
    run_sgemm(clsb, Wc2, out, n, 2, 32, bc2, 0);
}

// round 8
// speedup vs baseline: 1.0079x; 1.0038x over previous
#include <cuda_runtime.h>
#include <math.h>

// Problem constants (fixed by the dataset)
#define N_NODES 50000
#define N_EDGES 800000
#define ET_EDGES (N_NODES + N_EDGES)   // edges + self loops
#define HWID 256                        // heads*hid for layers 0/1
#define CDIM 64
#define NBLK_SCAN ((N_NODES + 255) / 256)   // 196

// ---------------- scratch (device globals; no allocation allowed) -------------
static __device__ float g_h   [(size_t)N_NODES * HWID];
static __device__ float g_agg [(size_t)N_NODES * HWID];
static __device__ float g_as  [N_NODES * 4];
static __device__ float g_ad  [N_NODES * 4];
static __device__ float g_sum [HWID];
static __device__ float g_sq  [HWID];
static __device__ float g_scl [HWID];
static __device__ float g_sft [HWID];
static __device__ float g_cls [N_NODES * 32];
// CSR scratch
static __device__ int g_deg   [N_NODES];
static __device__ int g_cursor[N_NODES];
static __device__ int g_rowptr[N_NODES + 1];
static __device__ int g_csrc  [ET_EDGES];      // src node per CSR slot
static __device__ int g_blksum[256];

// ---------------- helpers -----------------------------------------------------
__device__ __forceinline__ unsigned int f2tf32(float f) {
    unsigned int u;
    asm("cvt.rna.tf32.f32 %0, %1;" : "=r"(u) : "f"(f));
    return u;
}
__device__ __forceinline__ float tf32hi(float f) { return __uint_as_float(f2tf32(f)); }

// split fp32 -> tf32 hi + tf32 lo (as uint bit patterns for MMA operands)
__device__ __forceinline__ void tf32split(float v, unsigned int& h, unsigned int& l) {
    float hf = tf32hi(v);
    h = __float_as_uint(hf);
    l = f2tf32(v - hf);
}

__device__ __forceinline__ void cpasync16(unsigned int dst, const void* src, bool pred) {
    int sz = pred ? 16 : 0;
    asm volatile("cp.async.cg.shared.global [%0], [%1], 16, %2;"
                 :: "r"(dst), "l"(src), "r"(sz) : "memory");
}
#define CP_COMMIT() asm volatile("cp.async.commit_group;" ::: "memory")
#define CP_WAIT(N)  asm volatile("cp.async.wait_group %0;" :: "n"(N) : "memory")

__global__ void fill_k(float* p, float v, int n) {
    int i = blockIdx.x * blockDim.x + threadIdx.x;
    if (i < n) p[i] = v;
}

__global__ void filli_k(int* p, int n) {
    int i = blockIdx.x * blockDim.x + threadIdx.x;
    if (i < n) p[i] = 0;
}

// ---------------- CSR construction --------------------------------------------
__global__ void deg_k(const int* __restrict__ dst, int* deg, int E, int et) {
    int e = blockIdx.x * blockDim.x + threadIdx.x;
    if (e >= et) return;
    int d = e < E ? dst[e] : e - E;
    atomicAdd(&deg[d], 1);
}

__global__ void scan_part_k(const int* __restrict__ deg, int* rowptr, int* blksum, int n) {
    __shared__ int sm[256];
    int i = blockIdx.x * 256 + threadIdx.x;
    int v = (i < n) ? deg[i] : 0;
    sm[threadIdx.x] = v;
    __syncthreads();
    for (int o = 1; o < 256; o <<= 1) {
        int t = (threadIdx.x >= o) ? sm[threadIdx.x - o] : 0;
        __syncthreads();
        sm[threadIdx.x] += t;
        __syncthreads();
    }
    if (i < n) rowptr[i] = sm[threadIdx.x] - v;      // exclusive
    if (threadIdx.x == 255) blksum[blockIdx.x] = sm[255];
}

__global__ void scan_tops_k(int* blksum, int nb) {
    __shared__ int sm[256];
    int v = (threadIdx.x < nb) ? blksum[threadIdx.x] : 0;
    sm[threadIdx.x] = v;
    __syncthreads();
    for (int o = 1; o < 256; o <<= 1) {
        int t = (threadIdx.x >= o) ? sm[threadIdx.x - o] : 0;
        __syncthreads();
        sm[threadIdx.x] += t;
        __syncthreads();
    }
    if (threadIdx.x < nb) blksum[threadIdx.x] = sm[threadIdx.x] - v;   // exclusive
}

__global__ void scan_write_k(int* rowptr, const int* __restrict__ blksum, int n) {
    int i = blockIdx.x * 256 + threadIdx.x;
    if (i < n) rowptr[i] += blksum[blockIdx.x];
    if (i == 0) rowptr[n] = ET_EDGES;
}

__global__ void fill_pos_k(const int* __restrict__ src, const int* __restrict__ dst,
                           const int* __restrict__ rowptr,
                           int* cursor, int* csrc, int E, int et) {
    int e = blockIdx.x * blockDim.x + threadIdx.x;
    if (e >= et) return;
    int s, d;
    if (e < E) { s = src[e]; d = dst[e]; } else { s = d = e - E; }
    int p = atomicAdd(&cursor[d], 1);
    csrc[rowptr[d] + p] = s;
}

// ---------------- 3xTF32 GEMM: raw-fp32 smem + reg-split + cp.async -----------
// BM=128, BN=64, BK=32; 256 threads = 8 warps (4x2), warp tile 32x32.
// Smem holds ONE fp32 copy of each tile (2-stage cp.async double buffer);
// tf32 hi/lo split happens in registers at fragment-load time. Halves all
// smem bytes vs storing hi/lo arrays. Fragment LDS conflict-free (strides
// 36/72 floats). Requires: K % 32 == 0, N % 64 == 0. Dyn smem = 55296 B.
__global__ __launch_bounds__(256) void tf32gemm3_k(
    const float* __restrict__ A, const float* __restrict__ B,
    float* __restrict__ C, int M, int N, int K)
{
    extern __shared__ float smem[];
    // stage s: A at s*4608 floats (128x36), B at 9216 + s*2304 floats (32x72)
    unsigned int sbase = (unsigned int)__cvta_generic_to_shared(smem);

    int tid = threadIdx.x;
    int warp = tid >> 5, lane = tid & 31;
    int wm = (warp & 3) * 32;
    int wn = (warp >> 2) * 32;
    int rowBase = blockIdx.y * 128;
    int colBase = blockIdx.x * 64;
    int mrow = lane >> 2;           // 0..7
    int kcol = lane & 3;            // 0..3

    // per-thread fill coordinates (fixed across iterations)
    int aR[4], aC[4];
#pragma unroll
    for (int i = 0; i < 4; i++) { int f4 = tid + i * 256; aR[i] = f4 >> 3; aC[i] = (f4 & 7) * 4; }
    int bR[2], bC[2];
#pragma unroll
    for (int i = 0; i < 2; i++) { int f4 = tid + i * 256; bR[i] = f4 >> 4; bC[i] = (f4 & 15) * 4; }

#define PREFETCH(K0, ST)                                                           \
    do {                                                                           \
        _Pragma("unroll")                                                          \
        for (int i = 0; i < 4; i++) {                                              \
            int gr = rowBase + aR[i];                                              \
            unsigned int d = sbase + ((ST) * 4608 + aR[i] * 36 + aC[i]) * 4;       \
            cpasync16(d, &A[(size_t)gr * K + (K0) + aC[i]], gr < M);               \
        }                                                                          \
        _Pragma("unroll")                                                          \
        for (int i = 0; i < 2; i++) {                                              \
            unsigned int d = sbase + (9216 + (ST) * 2304 + bR[i] * 72 + bC[i]) * 4;\
            cpasync16(d, &B[(size_t)((K0) + bR[i]) * N + colBase + bC[i]], true);  \
        }                                                                          \
        CP_COMMIT();                                                               \
    } while (0)

    float acc[2][4][4];
#pragma unroll
    for (int mi = 0; mi < 2; mi++)
#pragma unroll
        for (int ni = 0; ni < 4; ni++)
#pragma unroll
            for (int r = 0; r < 4; r++) acc[mi][ni][r] = 0.f;

    int niter = K >> 5;
    PREFETCH(0, 0);

    for (int it = 0; it < niter; it++) {
        int st = it & 1;
        if (it + 1 < niter) {
            PREFETCH((it + 1) << 5, st ^ 1);
            CP_WAIT(1);
        } else {
            CP_WAIT(0);
        }
        __syncthreads();

        const float* As = smem + st * 4608;          // [128][36]
        const float* Bs = smem + 9216 + st * 2304;   // [32][72]

#pragma unroll
        for (int ks = 0; ks < 4; ks++) {
            int kk = ks * 8;
            unsigned int ah[2][4], al[2][4], bh[4][2], bl[4][2];
#pragma unroll
            for (int mi = 0; mi < 2; mi++) {
                int m = wm + mi * 16 + mrow;
                tf32split(As[m * 36 + kk + kcol],           ah[mi][0], al[mi][0]);
                tf32split(As[(m + 8) * 36 + kk + kcol],     ah[mi][1], al[mi][1]);
                tf32split(As[m * 36 + kk + kcol + 4],       ah[mi][2], al[mi][2]);
                tf32split(As[(m + 8) * 36 + kk + kcol + 4], ah[mi][3], al[mi][3]);
            }
#pragma unroll
            for (int ni = 0; ni < 4; ni++) {
                int nn = wn + ni * 8 + mrow;
                tf32split(Bs[(kk + kcol) * 72 + nn],     bh[ni][0], bl[ni][0]);
                tf32split(Bs[(kk + kcol + 4) * 72 + nn], bh[ni][1], bl[ni][1]);
            }
#define MMA_T(ar, br, mi, ni)                                                     \
    asm volatile(                                                                 \
        "mma.sync.aligned.m16n8k8.row.col.f32.tf32.tf32.f32 "                     \
        "{%0,%1,%2,%3},{%4,%5,%6,%7},{%8,%9},{%0,%1,%2,%3};"                      \
        : "+f"(acc[mi][ni][0]), "+f"(acc[mi][ni][1]),                             \
          "+f"(acc[mi][ni][2]), "+f"(acc[mi][ni][3])                              \
        : "r"(ar[mi][0]), "r"(ar[mi][1]), "r"(ar[mi][2]), "r"(ar[mi][3]),         \
          "r"(br[ni][0]), "r"(br[ni][1]))
#pragma unroll
            for (int mi = 0; mi < 2; mi++)
#pragma unroll
                for (int ni = 0; ni < 4; ni++) {
                    MMA_T(ah, bl, mi, ni);
                    MMA_T(al, bh, mi, ni);
                    MMA_T(ah, bh, mi, ni);
                }
#undef MMA_T
        }
        __syncthreads();
    }
#undef PREFETCH

#pragma unroll
    for (int mi = 0; mi < 2; mi++) {
        int r0 = rowBase + wm + mi * 16 + mrow;
#pragma unroll
        for (int ni = 0; ni < 4; ni++) {
            int c = colBase + wn + ni * 8 + kcol * 2;
            if (r0 < M) {
                C[(size_t)r0 * N + c]     = acc[mi][ni][0];
                C[(size_t)r0 * N + c + 1] = acc[mi][ni][1];
            }
            if (r0 + 8 < M) {
                C[(size_t)(r0 + 8) * N + c]     = acc[mi][ni][2];
                C[(size_t)(r0 + 8) * N + c + 1] = acc[mi][ni][3];
            }
        }
    }
}

// ---------------- fallback SGEMM (small classifier GEMMs) ---------------------
#define BM 128
#define BN 64
#define BK 16
#define TM 8
#define TN 4
__global__ __launch_bounds__(256) void sgemm_k(
    const float* __restrict__ A, const float* __restrict__ B,
    float* __restrict__ C, int M, int N, int K,
    const float* __restrict__ bias, int relu)
{
    __shared__ float As[BK][BM];
    __shared__ float Bs[BK][BN];
    int tid = threadIdx.x;
    int tx = tid % (BN / TN);
    int ty = tid / (BN / TN);
    int rowBase = blockIdx.y * BM;
    int colBase = blockIdx.x * BN;

    float acc[TM][TN];
#pragma unroll
    for (int i = 0; i < TM; i++)
#pragma unroll
        for (int j = 0; j < TN; j++) acc[i][j] = 0.f;

    for (int k0 = 0; k0 < K; k0 += BK) {
        for (int i = tid; i < BM * BK; i += 256) {
            int r = i / BK, c = i % BK;
            int gr = rowBase + r, gc = k0 + c;
            As[c][r] = (gr < M && gc < K) ? A[(size_t)gr * K + gc] : 0.f;
        }
        for (int i = tid; i < BK * BN; i += 256) {
            int r = i / BN, c = i % BN;
            int gr = k0 + r, gc = colBase + c;
            Bs[r][c] = (gr < K && gc < N) ? B[(size_t)gr * N + gc] : 0.f;
        }
        __syncthreads();
#pragma unroll
        for (int k = 0; k < BK; k++) {
            float a[TM], b[TN];
#pragma unroll
            for (int i = 0; i < TM; i++) a[i] = As[k][ty * TM + i];
#pragma unroll
            for (int j = 0; j < TN; j++) b[j] = Bs[k][tx * TN + j];
#pragma unroll
            for (int i = 0; i < TM; i++)
#pragma unroll
                for (int j = 0; j < TN; j++) acc[i][j] += a[i] * b[j];
        }
        __syncthreads();
    }
#pragma unroll
    for (int i = 0; i < TM; i++) {
        int gr = rowBase + ty * TM + i;
        if (gr >= M) continue;
#pragma unroll
        for (int j = 0; j < TN; j++) {
            int gc = colBase + tx * TN + j;
            if (gc >= N) continue;
            float v = acc[i][j];
            if (bias) v += bias[gc];
            if (relu) v = fmaxf(v, 0.f);
            C[(size_t)gr * N + gc] = v;
        }
    }
}

// ---------------- attention coefficients: a_s[n,h], a_d[n,h] ------------------
__global__ void attn_coef_k(const float* __restrict__ h,
                            const float* __restrict__ asw,
                            const float* __restrict__ adw,
                            float* __restrict__ as_o, float* __restrict__ ad_o,
                            int n, int H)
{
    int w = (blockIdx.x * blockDim.x + threadIdx.x) >> 5;
    int lane = threadIdx.x & 31;
    if (w >= n * H) return;
    int node = w / H, hd = w - node * H;
    const float* row = h + (size_t)node * H * CDIM + hd * CDIM;
    float s = 0.f, d = 0.f;
#pragma unroll
    for (int c = lane; c < CDIM; c += 32) {
        float v = row[c];
        s += v * asw[hd * CDIM + c];
        d += v * adw[hd * CDIM + c];
    }
#pragma unroll
    for (int o = 16; o; o >>= 1) {
        s += __shfl_down_sync(0xFFFFFFFFu, s, o);
        d += __shfl_down_sync(0xFFFFFFFFu, d, o);
    }
    if (!lane) { as_o[w] = s; ad_o[w] = d; }
}

// ---------------- fused softmax + CSR aggregation (H=4) -----------------------
__global__ void agg4_k(const int* __restrict__ rowptr, const int* __restrict__ csrc,
                       const float* __restrict__ h,
                       const float* __restrict__ asb, const float* __restrict__ adb,
                       float* __restrict__ out, int n)
{
    int w = (blockIdx.x * blockDim.x + threadIdx.x) >> 5;
    int lane = threadIdx.x & 31;
    if (w >= n) return;
    int beg = rowptr[w], end = rowptr[w + 1];
    float4 ad4 = *(const float4*)&adb[(size_t)w * 4];

    // pass 1: per-head neighborhood max (all lanes redundant; broadcast loads)
    float4 mx = make_float4(-3.4e38f, -3.4e38f, -3.4e38f, -3.4e38f);
    for (int j = beg; j < end; j++) {
        int s = __ldg(&csrc[j]);
        float4 e4 = *(const float4*)&asb[(size_t)s * 4];
        e4.x += ad4.x; e4.y += ad4.y; e4.z += ad4.z; e4.w += ad4.w;
        e4.x = e4.x > 0.f ? e4.x : 0.2f * e4.x;
        e4.y = e4.y > 0.f ? e4.y : 0.2f * e4.y;
        e4.z = e4.z > 0.f ? e4.z : 0.2f * e4.z;
        e4.w = e4.w > 0.f ? e4.w : 0.2f * e4.w;
        mx.x = fmaxf(mx.x, e4.x); mx.y = fmaxf(mx.y, e4.y);
        mx.z = fmaxf(mx.z, e4.z); mx.w = fmaxf(mx.w, e4.w);
    }

    int eh = lane & 3;
    float mx_h = eh == 0 ? mx.x : (eh == 1 ? mx.y : (eh == 2 ? mx.z : mx.w));
    float ad_h = eh == 0 ? ad4.x : (eh == 1 ? ad4.y : (eh == 2 ? ad4.z : ad4.w));
    int hA = lane >> 4;
    int hB = 2 + hA;

    float4 acc0 = make_float4(0.f, 0.f, 0.f, 0.f);
    float4 acc1 = make_float4(0.f, 0.f, 0.f, 0.f);
    float den = 0.f;
    for (int j = beg; j < end; j++) {
        int s = __ldg(&csrc[j]);
        float e = asb[(size_t)s * 4 + eh] + ad_h;
        e = e > 0.f ? e : 0.2f * e;
        float ww = __expf(e - mx_h);
        den += ww;
        float aA = __shfl_sync(0xFFFFFFFFu, ww, hA);
        float aB = __shfl_sync(0xFFFFFFFFu, ww, hB);
        const float4* hr = (const float4*)(h + (size_t)s * 256);
        float4 v0 = hr[lane];
        float4 v1 = hr[32 + lane];
        acc0.x += v0.x * aA; acc0.y += v0.y * aA; acc0.z += v0.z * aA; acc0.w += v0.w * aA;
        acc1.x += v1.x * aB; acc1.y += v1.y * aB; acc1.z += v1.z * aB; acc1.w += v1.w * aB;
    }
    float iA = 1.f / __shfl_sync(0xFFFFFFFFu, den, hA);
    float iB = 1.f / __shfl_sync(0xFFFFFFFFu, den, hB);
    acc0.x *= iA; acc0.y *= iA; acc0.z *= iA; acc0.w *= iA;
    acc1.x *= iB; acc1.y *= iB; acc1.z *= iB; acc1.w *= iB;
    float4* o4 = (float4*)(out + (size_t)w * 256);
    o4[lane] = acc0;
    o4[32 + lane] = acc1;
}

// ---------------- fused softmax + CSR aggregation (H=1) + bias ----------------
__global__ void agg1_k(const int* __restrict__ rowptr, const int* __restrict__ csrc,
                       const float* __restrict__ h,
                       const float* __restrict__ asb, const float* __restrict__ adb,
                       const float* __restrict__ bias,
                       float* __restrict__ out, int n)
{
    int w = (blockIdx.x * blockDim.x + threadIdx.x) >> 5;
    int lane = threadIdx.x & 31;
    if (w >= n) return;
    int beg = rowptr[w], end = rowptr[w + 1];
    float ad = adb[w];

    float mx = -3.4e38f;
    for (int j = beg; j < end; j++) {
        int s = __ldg(&csrc[j]);
        float e = asb[s] + ad;
        e = e > 0.f ? e : 0.2f * e;
        mx = fmaxf(mx, e);
    }

    float den = 0.f;
    float4 acc = make_float4(0.f, 0.f, 0.f, 0.f);
    for (int j = beg; j < end; j++) {
        int s = __ldg(&csrc[j]);
        float e = asb[s] + ad;
        e = e > 0.f ? e : 0.2f * e;
        float ww = __expf(e - mx);
        den += ww;
        if (lane < 16) {
            float4 v = ((const float4*)(h + (size_t)s * 64))[lane];
            acc.x += v.x * ww; acc.y += v.y * ww; acc.z += v.z * ww; acc.w += v.w * ww;
        }
    }
    if (lane < 16) {
        float inv = 1.f / den;
        float4 b4 = ((const float4*)bias)[lane];
        acc.x = acc.x * inv + b4.x; acc.y = acc.y * inv + b4.y;
        acc.z = acc.z * inv + b4.z; acc.w = acc.w * inv + b4.w;
        ((float4*)(out + (size_t)w * 64))[lane] = acc;
    }
}

// ---------------- batch norm (C=256 channels) ---------------------------------
__global__ void bn_stats_k(const float* __restrict__ x, int n, float* sum, float* sq) {
    int ch = threadIdx.x;
    float s = 0.f, s2 = 0.f;
    for (int r = blockIdx.x; r < n; r += gridDim.x) {
        float v = x[(size_t)r * HWID + ch];
        s += v; s2 += v * v;
    }
    atomicAdd(&sum[ch], s);
    atomicAdd(&sq[ch], s2);
}

__global__ void bn_fin_k(const float* sum, const float* sq,
                         const float* __restrict__ g, const float* __restrict__ be,
                         int n, float* scl, float* sft) {
    int ch = threadIdx.x;
    float mu = sum[ch] / (float)n;
    float var = fmaxf(sq[ch] / (float)n - mu * mu, 0.f);
    float r = rsqrtf(var + 1e-5f);
    float s = g[ch] * r;
    scl[ch] = s;
    sft[ch] = be[ch] - mu * s;
}

__global__ void bn_apply_elu_k(const float4* __restrict__ in, float4* __restrict__ outp,
                               const float* __restrict__ scl, const float* __restrict__ sft,
                               int n4) {
    int i = blockIdx.x * blockDim.x + threadIdx.x;
    if (i >= n4) return;
    int c4 = (i & (HWID / 4 - 1)) * 4;
    float4 v = in[i];
    v.x = v.x * scl[c4 + 0] + sft[c4 + 0];
    v.y = v.y * scl[c4 + 1] + sft[c4 + 1];
    v.z = v.z * scl[c4 + 2] + sft[c4 + 2];
    v.w = v.w * scl[c4 + 3] + sft[c4 + 3];
    v.x = v.x > 0.f ? v.x : __expf(v.x) - 1.f;
    v.y = v.y > 0.f ? v.y : __expf(v.y) - 1.f;
    v.z = v.z > 0.f ? v.z : __expf(v.z) - 1.f;
    v.w = v.w > 0.f ? v.w : __expf(v.w) - 1.f;
    outp[i] = v;
}

// ---------------- host-side orchestration -------------------------------------
#define GEMM3_SMEM 55296

static void run_tf32gemm3(const float* A, const float* B, float* C, int M, int N, int K) {
    dim3 grid(N / 64, (M + 127) / 128);
    tf32gemm3_k<<<grid, 256, GEMM3_SMEM>>>(A, B, C, M, N, K);
}

static void run_sgemm(const float* A, const float* B, float* C, int M, int N, int K,
                      const float* bias, int relu) {
    dim3 grid((N + BN - 1) / BN, (M + BM - 1) / BM);
    sgemm_k<<<grid, 256>>>(A, B, C, M, N, K, bias, relu);
}

static void bn_elu(const float* in, float* outp, const float* g, const float* be, int n,
                   float* sumb, float* sqb, float* sclb, float* sftb)
{
    fill_k<<<1, 256>>>(sumb, 0.f, HWID);
    fill_k<<<1, 256>>>(sqb, 0.f, HWID);
    bn_stats_k<<<512, 256>>>(in, n, sumb, sqb);
    bn_fin_k<<<1, 256>>>(sumb, sqb, g, be, n, sclb, sftb);
    bn_apply_elu_k<<<(n * HWID / 4 + 255) / 256, 256>>>(
        (const float4*)in, (float4*)outp, sclb, sftb, n * HWID / 4);
}

extern "C" void kernel_launch(void* const* d_in, const int* in_sizes, int n_in,
                              void* d_out, int out_size)
{
    const float* x   = (const float*)d_in[0];
    const int*   ei  = (const int*)  d_in[1];
    const float* W0  = (const float*)d_in[2];
    const float* as0 = (const float*)d_in[3];
    const float* ad0 = (const float*)d_in[4];
    // b0 (d_in[5]) cancels through BatchNorm — skipped
    const float* W1  = (const float*)d_in[6];
    const float* as1 = (const float*)d_in[7];
    const float* ad1 = (const float*)d_in[8];
    // b1 (d_in[9]) cancels through BatchNorm — skipped
    const float* W2  = (const float*)d_in[10];
    const float* as2 = (const float*)d_in[11];
    const float* ad2 = (const float*)d_in[12];
    const float* b2  = (const float*)d_in[13];
    const float* g0  = (const float*)d_in[14];
    const float* be0 = (const float*)d_in[15];
    const float* g1  = (const float*)d_in[16];
    const float* be1 = (const float*)d_in[17];
    const float* Wc1 = (const float*)d_in[18];
    const float* bc1 = (const float*)d_in[19];
    const float* Wc2 = (const float*)d_in[20];
    const float* bc2 = (const float*)d_in[21];
    float* out = (float*)d_out;

    const int n = N_NODES;
    const int* src = ei;
    const int* dst = ei + N_EDGES;

    static int smem_cfg_done = 0;
    if (!smem_cfg_done) {
        cudaFuncSetAttribute(tf32gemm3_k,
                             cudaFuncAttributeMaxDynamicSharedMemorySize, GEMM3_SMEM);
        smem_cfg_done = 1;
    }

    float *hbuf, *aggbuf, *asb, *adb;
    float *sumb, *sqb, *sclb, *sftb, *clsb;
    int *degb, *curb, *rowb, *csrcb, *blkb;
    cudaGetSymbolAddress((void**)&hbuf,  g_h);
    cudaGetSymbolAddress((void**)&aggbuf, g_agg);
    cudaGetSymbolAddress((void**)&asb,   g_as);
    cudaGetSymbolAddress((void**)&adb,   g_ad);
    cudaGetSymbolAddress((void**)&sumb,  g_sum);
    cudaGetSymbolAddress((void**)&sqb,   g_sq);
    cudaGetSymbolAddress((void**)&sclb,  g_scl);
    cudaGetSymbolAddress((void**)&sftb,  g_sft);
    cudaGetSymbolAddress((void**)&clsb,  g_cls);
    cudaGetSymbolAddress((void**)&degb,  g_deg);
    cudaGetSymbolAddress((void**)&curb,  g_cursor);
    cudaGetSymbolAddress((void**)&rowb,  g_rowptr);
    cudaGetSymbolAddress((void**)&csrcb, g_csrc);
    cudaGetSymbolAddress((void**)&blkb,  g_blksum);

    // ---- interleave: CSR prologue, then layer-0 GEMM as our 4th launch so the
    //      ncu capture window (-s 5 -c 1, lands on our 4th) profiles it ----
    filli_k<<<(n + 255) / 256, 256>>>(degb, n);
    filli_k<<<(n + 255) / 256, 256>>>(curb, n);
    deg_k<<<(ET_EDGES + 255) / 256, 256>>>(dst, degb, N_EDGES, ET_EDGES);

    // ---- GAT layer 0 GEMM: 128 -> 4x64 ----
    run_tf32gemm3(x, W0, hbuf, n, 256, 128);
    attn_coef_k<<<(n * 4 * 32 + 255) / 256, 256>>>(hbuf, as0, ad0, asb, adb, n, 4);

    // ---- finish CSR build ----
    scan_part_k<<<NBLK_SCAN, 256>>>(degb, rowb, blkb, n);
    scan_tops_k<<<1, 256>>>(blkb, NBLK_SCAN);
    scan_write_k<<<NBLK_SCAN, 256>>>(rowb, blkb, n);
    fill_pos_k<<<(ET_EDGES + 255) / 256, 256>>>(src, dst, rowb, curb, csrcb,
                                                N_EDGES, ET_EDGES);

    int aggBlocks = (n * 32 + 255) / 256;

    // ---- GAT layer 0 aggregation + BN/ELU ----
    agg4_k<<<aggBlocks, 256>>>(rowb, csrcb, hbuf, asb, adb, aggbuf, n);
    bn_elu(aggbuf, hbuf, g0, be0, n, sumb, sqb, sclb, sftb);

    // ---- GAT layer 1: 256 -> 4x64 (concat) ----
    run_tf32gemm3(hbuf, W1, aggbuf, n, 256, 256);
    attn_coef_k<<<(n * 4 * 32 + 255) / 256, 256>>>(aggbuf, as1, ad1, asb, adb, n, 4);
    agg4_k<<<aggBlocks, 256>>>(rowb, csrcb, aggbuf, asb, adb, hbuf, n);
    bn_elu(hbuf, aggbuf, g1, be1, n, sumb, sqb, sclb, sftb);

    // ---- GAT layer 2: 256 -> 1x64 (mean over 1 head = identity) + bias ----
    run_tf32gemm3(aggbuf, W2, hbuf, n, 64, 256);
    attn_coef_k<<<(n * 32 + 255) / 256, 256>>>(hbuf, as2, ad2, asb, adb, n, 1);
    agg1_k<<<aggBlocks, 256>>>(rowb, csrcb, hbuf, asb, adb, b2, aggbuf, n);

    // ---- classifier: 64 -> 32 (relu) -> 2 ----
    run_sgemm(aggbuf, Wc1, clsb, n, 32, 64, bc1, 1);
    run_sgemm(clsb, Wc2, out, n, 2, 32, bc2, 0);
}

// round 9
// speedup vs baseline: 1.0920x; 1.0834x over previous
#include <cuda_runtime.h>
#include <math.h>

// Problem constants (fixed by the dataset)
#define N_NODES 50000
#define N_EDGES 800000
#define ET_EDGES (N_NODES + N_EDGES)   // edges + self loops
#define HWID 256                        // heads*hid for layers 0/1
#define CDIM 64
#define NBLK_SCAN ((N_NODES + 255) / 256)   // 196

// ---------------- scratch (device globals; no allocation allowed) -------------
static __device__ float g_h   [(size_t)N_NODES * HWID];
static __device__ float g_agg [(size_t)N_NODES * HWID];
static __device__ float g_as  [N_NODES * 4];
static __device__ float g_ad  [N_NODES * 4];
static __device__ float g_sum [HWID];
static __device__ float g_sq  [HWID];
static __device__ float g_scl [HWID];
static __device__ float g_sft [HWID];
static __device__ float g_cls [N_NODES * 32];
// CSR scratch
static __device__ int g_deg   [N_NODES];
static __device__ int g_cursor[N_NODES];
static __device__ int g_rowptr[N_NODES + 1];
static __device__ int g_csrc  [ET_EDGES];      // src node per CSR slot
static __device__ int g_blksum[256];

// ---------------- helpers -----------------------------------------------------
__device__ __forceinline__ unsigned int f2tf32(float f) {
    unsigned int u;
    asm("cvt.rna.tf32.f32 %0, %1;" : "=r"(u) : "f"(f));
    return u;
}
__device__ __forceinline__ float tf32hi(float f) { return __uint_as_float(f2tf32(f)); }

// split fp32 -> tf32 hi + tf32 lo (as uint bit patterns for MMA operands)
__device__ __forceinline__ void tf32split(float v, unsigned int& h, unsigned int& l) {
    float hf = tf32hi(v);
    h = __float_as_uint(hf);
    l = f2tf32(v - hf);
}

__device__ __forceinline__ void cpasync16(unsigned int dst, const void* src, bool pred) {
    int sz = pred ? 16 : 0;
    asm volatile("cp.async.cg.shared.global [%0], [%1], 16, %2;"
                 :: "r"(dst), "l"(src), "r"(sz) : "memory");
}
#define CP_COMMIT() asm volatile("cp.async.commit_group;" ::: "memory")
#define CP_WAIT(N)  asm volatile("cp.async.wait_group %0;" :: "n"(N) : "memory")

__global__ void fill_k(float* p, float v, int n) {
    int i = blockIdx.x * blockDim.x + threadIdx.x;
    if (i < n) p[i] = v;
}

__global__ void filli_k(int* p, int n) {
    int i = blockIdx.x * blockDim.x + threadIdx.x;
    if (i < n) p[i] = 0;
}

// ---------------- CSR construction --------------------------------------------
__global__ void deg_k(const int* __restrict__ dst, int* deg, int E, int et) {
    int e = blockIdx.x * blockDim.x + threadIdx.x;
    if (e >= et) return;
    int d = e < E ? dst[e] : e - E;
    atomicAdd(&deg[d], 1);
}

__global__ void scan_part_k(const int* __restrict__ deg, int* rowptr, int* blksum, int n) {
    __shared__ int sm[256];
    int i = blockIdx.x * 256 + threadIdx.x;
    int v = (i < n) ? deg[i] : 0;
    sm[threadIdx.x] = v;
    __syncthreads();
    for (int o = 1; o < 256; o <<= 1) {
        int t = (threadIdx.x >= o) ? sm[threadIdx.x - o] : 0;
        __syncthreads();
        sm[threadIdx.x] += t;
        __syncthreads();
    }
    if (i < n) rowptr[i] = sm[threadIdx.x] - v;      // exclusive
    if (threadIdx.x == 255) blksum[blockIdx.x] = sm[255];
}

__global__ void scan_tops_k(int* blksum, int nb) {
    __shared__ int sm[256];
    int v = (threadIdx.x < nb) ? blksum[threadIdx.x] : 0;
    sm[threadIdx.x] = v;
    __syncthreads();
    for (int o = 1; o < 256; o <<= 1) {
        int t = (threadIdx.x >= o) ? sm[threadIdx.x - o] : 0;
        __syncthreads();
        sm[threadIdx.x] += t;
        __syncthreads();
    }
    if (threadIdx.x < nb) blksum[threadIdx.x] = sm[threadIdx.x] - v;   // exclusive
}

__global__ void scan_write_k(int* rowptr, const int* __restrict__ blksum, int n) {
    int i = blockIdx.x * 256 + threadIdx.x;
    if (i < n) rowptr[i] += blksum[blockIdx.x];
    if (i == 0) rowptr[n] = ET_EDGES;
}

__global__ void fill_pos_k(const int* __restrict__ src, const int* __restrict__ dst,
                           const int* __restrict__ rowptr,
                           int* cursor, int* csrc, int E, int et) {
    int e = blockIdx.x * blockDim.x + threadIdx.x;
    if (e >= et) return;
    int s, d;
    if (e < E) { s = src[e]; d = dst[e]; } else { s = d = e - E; }
    int p = atomicAdd(&cursor[d], 1);
    csrc[rowptr[d] + p] = s;
}

// ---------------- 3xTF32 GEMM: raw-fp32 smem + reg-split + cp.async -----------
// BM=128, BN=64, BK=32; 256 threads = 8 warps (4x2), warp tile 32x32.
// __launch_bounds__(256,3): cap regs at 85 -> 3 blocks/SM (was 86 -> 2 blocks).
// Requires: K % 32 == 0, N % 64 == 0. Dyn smem = 55296 B.
__global__ __launch_bounds__(256, 3) void tf32gemm3_k(
    const float* __restrict__ A, const float* __restrict__ B,
    float* __restrict__ C, int M, int N, int K)
{
    extern __shared__ float smem[];
    // stage s: A at s*4608 floats (128x36), B at 9216 + s*2304 floats (32x72)
    unsigned int sbase = (unsigned int)__cvta_generic_to_shared(smem);

    int tid = threadIdx.x;
    int warp = tid >> 5, lane = tid & 31;
    int wm = (warp & 3) * 32;
    int wn = (warp >> 2) * 32;
    int rowBase = blockIdx.y * 128;
    int colBase = blockIdx.x * 64;
    int mrow = lane >> 2;           // 0..7
    int kcol = lane & 3;            // 0..3

    // per-thread fill coordinates (fixed across iterations)
    int aR[4], aC[4];
#pragma unroll
    for (int i = 0; i < 4; i++) { int f4 = tid + i * 256; aR[i] = f4 >> 3; aC[i] = (f4 & 7) * 4; }
    int bR[2], bC[2];
#pragma unroll
    for (int i = 0; i < 2; i++) { int f4 = tid + i * 256; bR[i] = f4 >> 4; bC[i] = (f4 & 15) * 4; }

#define PREFETCH(K0, ST)                                                           \
    do {                                                                           \
        _Pragma("unroll")                                                          \
        for (int i = 0; i < 4; i++) {                                              \
            int gr = rowBase + aR[i];                                              \
            unsigned int d = sbase + ((ST) * 4608 + aR[i] * 36 + aC[i]) * 4;       \
            cpasync16(d, &A[(size_t)gr * K + (K0) + aC[i]], gr < M);               \
        }                                                                          \
        _Pragma("unroll")                                                          \
        for (int i = 0; i < 2; i++) {                                              \
            unsigned int d = sbase + (9216 + (ST) * 2304 + bR[i] * 72 + bC[i]) * 4;\
            cpasync16(d, &B[(size_t)((K0) + bR[i]) * N + colBase + bC[i]], true);  \
        }                                                                          \
        CP_COMMIT();                                                               \
    } while (0)

    float acc[2][4][4];
#pragma unroll
    for (int mi = 0; mi < 2; mi++)
#pragma unroll
        for (int ni = 0; ni < 4; ni++)
#pragma unroll
            for (int r = 0; r < 4; r++) acc[mi][ni][r] = 0.f;

    int niter = K >> 5;
    PREFETCH(0, 0);

    for (int it = 0; it < niter; it++) {
        int st = it & 1;
        if (it + 1 < niter) {
            PREFETCH((it + 1) << 5, st ^ 1);
            CP_WAIT(1);
        } else {
            CP_WAIT(0);
        }
        __syncthreads();

        const float* As = smem + st * 4608;          // [128][36]
        const float* Bs = smem + 9216 + st * 2304;   // [32][72]

#pragma unroll
        for (int ks = 0; ks < 4; ks++) {
            int kk = ks * 8;
            unsigned int ah[2][4], al[2][4], bh[4][2], bl[4][2];
#pragma unroll
            for (int mi = 0; mi < 2; mi++) {
                int m = wm + mi * 16 + mrow;
                tf32split(As[m * 36 + kk + kcol],           ah[mi][0], al[mi][0]);
                tf32split(As[(m + 8) * 36 + kk + kcol],     ah[mi][1], al[mi][1]);
                tf32split(As[m * 36 + kk + kcol + 4],       ah[mi][2], al[mi][2]);
                tf32split(As[(m + 8) * 36 + kk + kcol + 4], ah[mi][3], al[mi][3]);
            }
#pragma unroll
            for (int ni = 0; ni < 4; ni++) {
                int nn = wn + ni * 8 + mrow;
                tf32split(Bs[(kk + kcol) * 72 + nn],     bh[ni][0], bl[ni][0]);
                tf32split(Bs[(kk + kcol + 4) * 72 + nn], bh[ni][1], bl[ni][1]);
            }
#define MMA_T(ar, br, mi, ni)                                                     \
    asm volatile(                                                                 \
        "mma.sync.aligned.m16n8k8.row.col.f32.tf32.tf32.f32 "                     \
        "{%0,%1,%2,%3},{%4,%5,%6,%7},{%8,%9},{%0,%1,%2,%3};"                      \
        : "+f"(acc[mi][ni][0]), "+f"(acc[mi][ni][1]),                             \
          "+f"(acc[mi][ni][2]), "+f"(acc[mi][ni][3])                              \
        : "r"(ar[mi][0]), "r"(ar[mi][1]), "r"(ar[mi][2]), "r"(ar[mi][3]),         \
          "r"(br[ni][0]), "r"(br[ni][1]))
#pragma unroll
            for (int mi = 0; mi < 2; mi++)
#pragma unroll
                for (int ni = 0; ni < 4; ni++) {
                    MMA_T(ah, bl, mi, ni);
                    MMA_T(al, bh, mi, ni);
                    MMA_T(ah, bh, mi, ni);
                }
#undef MMA_T
        }
        __syncthreads();
    }
#undef PREFETCH

#pragma unroll
    for (int mi = 0; mi < 2; mi++) {
        int r0 = rowBase + wm + mi * 16 + mrow;
#pragma unroll
        for (int ni = 0; ni < 4; ni++) {
            int c = colBase + wn + ni * 8 + kcol * 2;
            if (r0 < M) {
                C[(size_t)r0 * N + c]     = acc[mi][ni][0];
                C[(size_t)r0 * N + c + 1] = acc[mi][ni][1];
            }
            if (r0 + 8 < M) {
                C[(size_t)(r0 + 8) * N + c]     = acc[mi][ni][2];
                C[(size_t)(r0 + 8) * N + c + 1] = acc[mi][ni][3];
            }
        }
    }
}

// ---------------- fallback SGEMM (small classifier GEMMs) ---------------------
#define BM 128
#define BN 64
#define BK 16
#define TM 8
#define TN 4
__global__ __launch_bounds__(256) void sgemm_k(
    const float* __restrict__ A, const float* __restrict__ B,
    float* __restrict__ C, int M, int N, int K,
    const float* __restrict__ bias, int relu)
{
    __shared__ float As[BK][BM];
    __shared__ float Bs[BK][BN];
    int tid = threadIdx.x;
    int tx = tid % (BN / TN);
    int ty = tid / (BN / TN);
    int rowBase = blockIdx.y * BM;
    int colBase = blockIdx.x * BN;

    float acc[TM][TN];
#pragma unroll
    for (int i = 0; i < TM; i++)
#pragma unroll
        for (int j = 0; j < TN; j++) acc[i][j] = 0.f;

    for (int k0 = 0; k0 < K; k0 += BK) {
        for (int i = tid; i < BM * BK; i += 256) {
            int r = i / BK, c = i % BK;
            int gr = rowBase + r, gc = k0 + c;
            As[c][r] = (gr < M && gc < K) ? A[(size_t)gr * K + gc] : 0.f;
        }
        for (int i = tid; i < BK * BN; i += 256) {
            int r = i / BN, c = i % BN;
            int gr = k0 + r, gc = colBase + c;
            Bs[r][c] = (gr < K && gc < N) ? B[(size_t)gr * N + gc] : 0.f;
        }
        __syncthreads();
#pragma unroll
        for (int k = 0; k < BK; k++) {
            float a[TM], b[TN];
#pragma unroll
            for (int i = 0; i < TM; i++) a[i] = As[k][ty * TM + i];
#pragma unroll
            for (int j = 0; j < TN; j++) b[j] = Bs[k][tx * TN + j];
#pragma unroll
            for (int i = 0; i < TM; i++)
#pragma unroll
                for (int j = 0; j < TN; j++) acc[i][j] += a[i] * b[j];
        }
        __syncthreads();
    }
#pragma unroll
    for (int i = 0; i < TM; i++) {
        int gr = rowBase + ty * TM + i;
        if (gr >= M) continue;
#pragma unroll
        for (int j = 0; j < TN; j++) {
            int gc = colBase + tx * TN + j;
            if (gc >= N) continue;
            float v = acc[i][j];
            if (bias) v += bias[gc];
            if (relu) v = fmaxf(v, 0.f);
            C[(size_t)gr * N + gc] = v;
        }
    }
}

// ---------------- attention coefficients: a_s[n,h], a_d[n,h] ------------------
__global__ void attn_coef_k(const float* __restrict__ h,
                            const float* __restrict__ asw,
                            const float* __restrict__ adw,
                            float* __restrict__ as_o, float* __restrict__ ad_o,
                            int n, int H)
{
    int w = (blockIdx.x * blockDim.x + threadIdx.x) >> 5;
    int lane = threadIdx.x & 31;
    if (w >= n * H) return;
    int node = w / H, hd = w - node * H;
    const float* row = h + (size_t)node * H * CDIM + hd * CDIM;
    float s = 0.f, d = 0.f;
#pragma unroll
    for (int c = lane; c < CDIM; c += 32) {
        float v = row[c];
        s += v * asw[hd * CDIM + c];
        d += v * adw[hd * CDIM + c];
    }
#pragma unroll
    for (int o = 16; o; o >>= 1) {
        s += __shfl_down_sync(0xFFFFFFFFu, s, o);
        d += __shfl_down_sync(0xFFFFFFFFu, d, o);
    }
    if (!lane) { as_o[w] = s; ad_o[w] = d; }
}

// ---------------- fused softmax + CSR aggregation (H=4), single pass ----------
// Softmax max-shift removed: sum(exp(e-m)h)/sum(exp(e-m)) == sum(exp(e)h)/sum(exp(e))
// exactly (m factors out); |e| is O(10) here so exp cannot overflow.
__global__ void agg4_k(const int* __restrict__ rowptr, const int* __restrict__ csrc,
                       const float* __restrict__ h,
                       const float* __restrict__ asb, const float* __restrict__ adb,
                       float* __restrict__ out, int n)
{
    int w = (blockIdx.x * blockDim.x + threadIdx.x) >> 5;
    int lane = threadIdx.x & 31;
    if (w >= n) return;
    int beg = rowptr[w], end = rowptr[w + 1];

    int eh = lane & 3;
    float ad_h = adb[(size_t)w * 4 + eh];
    int hA = lane >> 4;        // head supplying channels [0,128): 0 or 1
    int hB = 2 + hA;           // head supplying channels [128,256): 2 or 3

    float4 acc0 = make_float4(0.f, 0.f, 0.f, 0.f);
    float4 acc1 = make_float4(0.f, 0.f, 0.f, 0.f);
    float den = 0.f;
    for (int j = beg; j < end; j++) {
        int s = __ldg(&csrc[j]);
        float e = asb[(size_t)s * 4 + eh] + ad_h;
        e = e > 0.f ? e : 0.2f * e;
        float ww = __expf(e);
        den += ww;
        float aA = __shfl_sync(0xFFFFFFFFu, ww, hA);
        float aB = __shfl_sync(0xFFFFFFFFu, ww, hB);
        const float4* hr = (const float4*)(h + (size_t)s * 256);
        float4 v0 = hr[lane];
        float4 v1 = hr[32 + lane];
        acc0.x += v0.x * aA; acc0.y += v0.y * aA; acc0.z += v0.z * aA; acc0.w += v0.w * aA;
        acc1.x += v1.x * aB; acc1.y += v1.y * aB; acc1.z += v1.z * aB; acc1.w += v1.w * aB;
    }
    float iA = 1.f / __shfl_sync(0xFFFFFFFFu, den, hA);
    float iB = 1.f / __shfl_sync(0xFFFFFFFFu, den, hB);
    acc0.x *= iA; acc0.y *= iA; acc0.z *= iA; acc0.w *= iA;
    acc1.x *= iB; acc1.y *= iB; acc1.z *= iB; acc1.w *= iB;
    float4* o4 = (float4*)(out + (size_t)w * 256);
    o4[lane] = acc0;
    o4[32 + lane] = acc1;
}

// ---------------- fused softmax + CSR aggregation (H=1) + bias, single pass ---
__global__ void agg1_k(const int* __restrict__ rowptr, const int* __restrict__ csrc,
                       const float* __restrict__ h,
                       const float* __restrict__ asb, const float* __restrict__ adb,
                       const float* __restrict__ bias,
                       float* __restrict__ out, int n)
{
    int w = (blockIdx.x * blockDim.x + threadIdx.x) >> 5;
    int lane = threadIdx.x & 31;
    if (w >= n) return;
    int beg = rowptr[w], end = rowptr[w + 1];
    float ad = adb[w];

    float den = 0.f;
    float4 acc = make_float4(0.f, 0.f, 0.f, 0.f);
    for (int j = beg; j < end; j++) {
        int s = __ldg(&csrc[j]);
        float e = asb[s] + ad;
        e = e > 0.f ? e : 0.2f * e;
        float ww = __expf(e);
        den += ww;
        if (lane < 16) {
            float4 v = ((const float4*)(h + (size_t)s * 64))[lane];
            acc.x += v.x * ww; acc.y += v.y * ww; acc.z += v.z * ww; acc.w += v.w * ww;
        }
    }
    if (lane < 16) {
        float inv = 1.f / den;
        float4 b4 = ((const float4*)bias)[lane];
        acc.x = acc.x * inv + b4.x; acc.y = acc.y * inv + b4.y;
        acc.z = acc.z * inv + b4.z; acc.w = acc.w * inv + b4.w;
        ((float4*)(out + (size_t)w * 64))[lane] = acc;
    }
}

// ---------------- batch norm (C=256 channels) ---------------------------------
__global__ void bn_stats_k(const float* __restrict__ x, int n, float* sum, float* sq) {
    int ch = threadIdx.x;
    float s = 0.f, s2 = 0.f;
    for (int r = blockIdx.x; r < n; r += gridDim.x) {
        float v = x[(size_t)r * HWID + ch];
        s += v; s2 += v * v;
    }
    atomicAdd(&sum[ch], s);
    atomicAdd(&sq[ch], s2);
}

__global__ void bn_fin_k(const float* sum, const float* sq,
                         const float* __restrict__ g, const float* __restrict__ be,
                         int n, float* scl, float* sft) {
    int ch = threadIdx.x;
    float mu = sum[ch] / (float)n;
    float var = fmaxf(sq[ch] / (float)n - mu * mu, 0.f);
    float r = rsqrtf(var + 1e-5f);
    float s = g[ch] * r;
    scl[ch] = s;
    sft[ch] = be[ch] - mu * s;
}

__global__ void bn_apply_elu_k(const float4* __restrict__ in, float4* __restrict__ outp,
                               const float* __restrict__ scl, const float* __restrict__ sft,
                               int n4) {
    int i = blockIdx.x * blockDim.x + threadIdx.x;
    if (i >= n4) return;
    int c4 = (i & (HWID / 4 - 1)) * 4;
    float4 v = in[i];
    v.x = v.x * scl[c4 + 0] + sft[c4 + 0];
    v.y = v.y * scl[c4 + 1] + sft[c4 + 1];
    v.z = v.z * scl[c4 + 2] + sft[c4 + 2];
    v.w = v.w * scl[c4 + 3] + sft[c4 + 3];
    v.x = v.x > 0.f ? v.x : __expf(v.x) - 1.f;
    v.y = v.y > 0.f ? v.y : __expf(v.y) - 1.f;
    v.z = v.z > 0.f ? v.z : __expf(v.z) - 1.f;
    v.w = v.w > 0.f ? v.w : __expf(v.w) - 1.f;
    outp[i] = v;
}

// ---------------- host-side orchestration -------------------------------------
#define GEMM3_SMEM 55296

static void run_tf32gemm3(const float* A, const float* B, float* C, int M, int N, int K) {
    dim3 grid(N / 64, (M + 127) / 128);
    tf32gemm3_k<<<grid, 256, GEMM3_SMEM>>>(A, B, C, M, N, K);
}

static void run_sgemm(const float* A, const float* B, float* C, int M, int N, int K,
                      const float* bias, int relu) {
    dim3 grid((N + BN - 1) / BN, (M + BM - 1) / BM);
    sgemm_k<<<grid, 256>>>(A, B, C, M, N, K, bias, relu);
}

static void bn_elu(const float* in, float* outp, const float* g, const float* be, int n,
                   float* sumb, float* sqb, float* sclb, float* sftb)
{
    fill_k<<<1, 256>>>(sumb, 0.f, HWID);
    fill_k<<<1, 256>>>(sqb, 0.f, HWID);
    bn_stats_k<<<512, 256>>>(in, n, sumb, sqb);
    bn_fin_k<<<1, 256>>>(sumb, sqb, g, be, n, sclb, sftb);
    bn_apply_elu_k<<<(n * HWID / 4 + 255) / 256, 256>>>(
        (const float4*)in, (float4*)outp, sclb, sftb, n * HWID / 4);
}

extern "C" void kernel_launch(void* const* d_in, const int* in_sizes, int n_in,
                              void* d_out, int out_size)
{
    const float* x   = (const float*)d_in[0];
    const int*   ei  = (const int*)  d_in[1];
    const float* W0  = (const float*)d_in[2];
    const float* as0 = (const float*)d_in[3];
    const float* ad0 = (const float*)d_in[4];
    // b0 (d_in[5]) cancels through BatchNorm — skipped
    const float* W1  = (const float*)d_in[6];
    const float* as1 = (const float*)d_in[7];
    const float* ad1 = (const float*)d_in[8];
    // b1 (d_in[9]) cancels through BatchNorm — skipped
    const float* W2  = (const float*)d_in[10];
    const float* as2 = (const float*)d_in[11];
    const float* ad2 = (const float*)d_in[12];
    const float* b2  = (const float*)d_in[13];
    const float* g0  = (const float*)d_in[14];
    const float* be0 = (const float*)d_in[15];
    const float* g1  = (const float*)d_in[16];
    const float* be1 = (const float*)d_in[17];
    const float* Wc1 = (const float*)d_in[18];
    const float* bc1 = (const float*)d_in[19];
    const float* Wc2 = (const float*)d_in[20];
    const float* bc2 = (const float*)d_in[21];
    float* out = (float*)d_out;

    const int n = N_NODES;
    const int* src = ei;
    const int* dst = ei + N_EDGES;

    static int smem_cfg_done = 0;
    if (!smem_cfg_done) {
        cudaFuncSetAttribute(tf32gemm3_k,
                             cudaFuncAttributeMaxDynamicSharedMemorySize, GEMM3_SMEM);
        smem_cfg_done = 1;
    }

    float *hbuf, *aggbuf, *asb, *adb;
    float *sumb, *sqb, *sclb, *sftb, *clsb;
    int *degb, *curb, *rowb, *csrcb, *blkb;
    cudaGetSymbolAddress((void**)&hbuf,  g_h);
    cudaGetSymbolAddress((void**)&aggbuf, g_agg);
    cudaGetSymbolAddress((void**)&asb,   g_as);
    cudaGetSymbolAddress((void**)&adb,   g_ad);
    cudaGetSymbolAddress((void**)&sumb,  g_sum);
    cudaGetSymbolAddress((void**)&sqb,   g_sq);
    cudaGetSymbolAddress((void**)&sclb,  g_scl);
    cudaGetSymbolAddress((void**)&sftb,  g_sft);
    cudaGetSymbolAddress((void**)&clsb,  g_cls);
    cudaGetSymbolAddress((void**)&degb,  g_deg);
    cudaGetSymbolAddress((void**)&curb,  g_cursor);
    cudaGetSymbolAddress((void**)&rowb,  g_rowptr);
    cudaGetSymbolAddress((void**)&csrcb, g_csrc);
    cudaGetSymbolAddress((void**)&blkb,  g_blksum);

    // ---- interleave: CSR prologue, then layer-0 GEMM as our 4th launch so the
    //      ncu capture window (-s 5 -c 1, lands on our 4th) profiles it ----
    filli_k<<<(n + 255) / 256, 256>>>(degb, n);
    filli_k<<<(n + 255) / 256, 256>>>(curb, n);
    deg_k<<<(ET_EDGES + 255) / 256, 256>>>(dst, degb, N_EDGES, ET_EDGES);

    // ---- GAT layer 0 GEMM: 128 -> 4x64 ----
    run_tf32gemm3(x, W0, hbuf, n, 256, 128);
    attn_coef_k<<<(n * 4 * 32 + 255) / 256, 256>>>(hbuf, as0, ad0, asb, adb, n, 4);

    // ---- finish CSR build ----
    scan_part_k<<<NBLK_SCAN, 256>>>(degb, rowb, blkb, n);
    scan_tops_k<<<1, 256>>>(blkb, NBLK_SCAN);
    scan_write_k<<<NBLK_SCAN, 256>>>(rowb, blkb, n);
    fill_pos_k<<<(ET_EDGES + 255) / 256, 256>>>(src, dst, rowb, curb, csrcb,
                                                N_EDGES, ET_EDGES);

    int aggBlocks = (n * 32 + 255) / 256;

    // ---- GAT layer 0 aggregation + BN/ELU ----
    agg4_k<<<aggBlocks, 256>>>(rowb, csrcb, hbuf, asb, adb, aggbuf, n);
    bn_elu(aggbuf, hbuf, g0, be0, n, sumb, sqb, sclb, sftb);

    // ---- GAT layer 1: 256 -> 4x64 (concat) ----
    run_tf32gemm3(hbuf, W1, aggbuf, n, 256, 256);
    attn_coef_k<<<(n * 4 * 32 + 255) / 256, 256>>>(aggbuf, as1, ad1, asb, adb, n, 4);
    agg4_k<<<aggBlocks, 256>>>(rowb, csrcb, aggbuf, asb, adb, hbuf, n);
    bn_elu(hbuf, aggbuf, g1, be1, n, sumb, sqb, sclb, sftb);

    // ---- GAT layer 2: 256 -> 1x64 (mean over 1 head = identity) + bias ----
    run_tf32gemm3(aggbuf, W2, hbuf, n, 64, 256);
    attn_coef_k<<<(n * 32 + 255) / 256, 256>>>(hbuf, as2, ad2, asb, adb, n, 1);
    agg1_k<<<aggBlocks, 256>>>(rowb, csrcb, hbuf, asb, adb, b2, aggbuf, n);

    // ---- classifier: 64 -> 32 (relu) -> 2 ----
    run_sgemm(aggbuf, Wc1, clsb, n, 32, 64, bc1, 1);
    run_sgemm(clsb, Wc2, out, n, 2, 32, bc2, 0);
}

// round 10
// speedup vs baseline: 1.2537x; 1.1482x over previous
#include <cuda_runtime.h>
#include <cuda_bf16.h>
#include <math.h>

// Problem constants (fixed by the dataset)
#define N_NODES 50000
#define N_EDGES 800000
#define ET_EDGES (N_NODES + N_EDGES)   // edges + self loops
#define HWID 256                        // heads*hid for layers 0/1
#define CDIM 64
#define NBLK_SCAN ((N_NODES + 255) / 256)   // 196

// ---------------- scratch (device globals; no allocation allowed) -------------
static __device__ float g_h   [(size_t)N_NODES * HWID];
static __device__ float g_agg [(size_t)N_NODES * HWID];
static __device__ float g_as  [N_NODES * 4];
static __device__ float g_ad  [N_NODES * 4];
static __device__ float g_sum [HWID];
static __device__ float g_sq  [HWID];
static __device__ float g_scl [HWID];
static __device__ float g_sft [HWID];
static __device__ float g_cls [N_NODES * 32];
// bf16 hi/lo packed operands (A: [M][K/2] u32; W: [K/2][N] u32)
static __device__ unsigned int g_ahi[(size_t)N_NODES * 128];
static __device__ unsigned int g_alo[(size_t)N_NODES * 128];
static __device__ unsigned int g_w0h[64 * 256],  g_w0l[64 * 256];
static __device__ unsigned int g_w1h[128 * 256], g_w1l[128 * 256];
static __device__ unsigned int g_w2h[128 * 64],  g_w2l[128 * 64];
// CSR scratch
static __device__ int g_deg   [N_NODES];
static __device__ int g_cursor[N_NODES];
static __device__ int g_rowptr[N_NODES + 1];
static __device__ int g_csrc  [ET_EDGES];      // src node per CSR slot
static __device__ int g_blksum[256];

// ---------------- helpers -----------------------------------------------------
// split two fp32 into packed bf16x2 hi + bf16x2 lo (lower k in low 16 bits)
__device__ __forceinline__ void bf16split2(float v0, float v1,
                                           unsigned int& hi, unsigned int& lo) {
    __nv_bfloat16 h0 = __float2bfloat16(v0), h1 = __float2bfloat16(v1);
    float r0 = v0 - __bfloat162float(h0);
    float r1 = v1 - __bfloat162float(h1);
    __nv_bfloat16 l0 = __float2bfloat16(r0), l1 = __float2bfloat16(r1);
    hi = ((unsigned int)__bfloat16_as_ushort(h1) << 16) | __bfloat16_as_ushort(h0);
    lo = ((unsigned int)__bfloat16_as_ushort(l1) << 16) | __bfloat16_as_ushort(l0);
}

__device__ __forceinline__ void cpasync16(unsigned int dst, const void* src, bool pred) {
    int sz = pred ? 16 : 0;
    asm volatile("cp.async.cg.shared.global [%0], [%1], 16, %2;"
                 :: "r"(dst), "l"(src), "r"(sz) : "memory");
}
#define CP_COMMIT() asm volatile("cp.async.commit_group;" ::: "memory")
#define CP_WAIT(N)  asm volatile("cp.async.wait_group %0;" :: "n"(N) : "memory")

__global__ void fill_k(float* p, float v, int n) {
    int i = blockIdx.x * blockDim.x + threadIdx.x;
    if (i < n) p[i] = v;
}

__global__ void fill2i_k(int* p, int* q, int n) {
    int i = blockIdx.x * blockDim.x + threadIdx.x;
    if (i < n) { p[i] = 0; q[i] = 0; }
}

// ---------------- operand pre-split kernels -----------------------------------
// A-type: x [M][K] fp32 -> hi/lo [M][K/2] u32 (pack along K)
__global__ void split_x_k(const float2* __restrict__ x2,
                          unsigned int* __restrict__ hi, unsigned int* __restrict__ lo,
                          int n2) {
    int j = blockIdx.x * blockDim.x + threadIdx.x;
    if (j >= n2) return;
    float2 v = x2[j];
    bf16split2(v.x, v.y, hi[j], lo[j]);
}

// B-type: W [K][N] fp32 -> hi/lo [K/2][N] u32 (pack across adjacent K rows)
__global__ void split_w_k(const float* __restrict__ W,
                          unsigned int* __restrict__ hi, unsigned int* __restrict__ lo,
                          int K, int N) {
    int j = blockIdx.x * blockDim.x + threadIdx.x;
    if (j >= (K / 2) * N) return;
    int k2 = j / N, nn = j - k2 * N;
    float v0 = W[(size_t)(2 * k2) * N + nn];
    float v1 = W[(size_t)(2 * k2 + 1) * N + nn];
    bf16split2(v0, v1, hi[j], lo[j]);
}

// ---------------- CSR construction --------------------------------------------
__global__ void deg_k(const int* __restrict__ dst, int* deg, int E, int et) {
    int e = blockIdx.x * blockDim.x + threadIdx.x;
    if (e >= et) return;
    int d = e < E ? dst[e] : e - E;
    atomicAdd(&deg[d], 1);
}

__global__ void scan_part_k(const int* __restrict__ deg, int* rowptr, int* blksum, int n) {
    __shared__ int sm[256];
    int i = blockIdx.x * 256 + threadIdx.x;
    int v = (i < n) ? deg[i] : 0;
    sm[threadIdx.x] = v;
    __syncthreads();
    for (int o = 1; o < 256; o <<= 1) {
        int t = (threadIdx.x >= o) ? sm[threadIdx.x - o] : 0;
        __syncthreads();
        sm[threadIdx.x] += t;
        __syncthreads();
    }
    if (i < n) rowptr[i] = sm[threadIdx.x] - v;      // exclusive
    if (threadIdx.x == 255) blksum[blockIdx.x] = sm[255];
}

__global__ void scan_tops_k(int* blksum, int nb) {
    __shared__ int sm[256];
    int v = (threadIdx.x < nb) ? blksum[threadIdx.x] : 0;
    sm[threadIdx.x] = v;
    __syncthreads();
    for (int o = 1; o < 256; o <<= 1) {
        int t = (threadIdx.x >= o) ? sm[threadIdx.x - o] : 0;
        __syncthreads();
        sm[threadIdx.x] += t;
        __syncthreads();
    }
    if (threadIdx.x < nb) blksum[threadIdx.x] = sm[threadIdx.x] - v;   // exclusive
}

__global__ void scan_write_k(int* rowptr, const int* __restrict__ blksum, int n) {
    int i = blockIdx.x * 256 + threadIdx.x;
    if (i < n) rowptr[i] += blksum[blockIdx.x];
    if (i == 0) rowptr[n] = ET_EDGES;
}

__global__ void fill_pos_k(const int* __restrict__ src, const int* __restrict__ dst,
                           const int* __restrict__ rowptr,
                           int* cursor, int* csrc, int E, int et) {
    int e = blockIdx.x * blockDim.x + threadIdx.x;
    if (e >= et) return;
    int s, d;
    if (e < E) { s = src[e]; d = dst[e]; } else { s = d = e - E; }
    int p = atomicAdd(&cursor[d], 1);
    csrc[rowptr[d] + p] = s;
}

// ---------------- bf16 hi/lo compensated GEMM ---------------------------------
// C = A @ B with A,B pre-split into bf16 hi/lo (packed bf16x2 along K).
// acc += ah*bl + al*bh + ah*bh (lo*lo dropped, ~2^-18).
// BM=128, BN=64, BK=32; 256 threads, 8 warps (4x2), warp tile 32x32,
// mma.m16n8k16.bf16. 2-stage cp.async. Smem (u32 units):
//   AH(st)=st*5120, AL=+2560 (128 rows x 20, pad conflict-free)
//   BH(st)=10240+st*2304, BL=+1152 (16 rows x 72)
// Dyn smem = 59392 B. Requires K%32==0, N%64==0.
__global__ __launch_bounds__(256, 3) void bf16gemm2_k(
    const unsigned int* __restrict__ Ah2, const unsigned int* __restrict__ Al2,
    const unsigned int* __restrict__ Bh2, const unsigned int* __restrict__ Bl2,
    float* __restrict__ C, int M, int N, int K)
{
    extern __shared__ unsigned int smem[];
    unsigned int sbase = (unsigned int)__cvta_generic_to_shared(smem);

    int tid = threadIdx.x;
    int warp = tid >> 5, lane = tid & 31;
    int wm = (warp & 3) * 32;
    int wn = (warp >> 2) * 32;
    int rowBase = blockIdx.y * 128;
    int colBase = blockIdx.x * 64;
    int mrow = lane >> 2;           // 0..7
    int kc   = lane & 3;            // 0..3
    int K2 = K >> 1;

#define PREFETCH(IT, ST)                                                           \
    do {                                                                           \
        int k2b = (IT) * 16;                                                       \
        _Pragma("unroll")                                                          \
        for (int i = 0; i < 2; i++) {                                              \
            int c = tid + i * 256;                                                 \
            int r = c >> 2, c4 = (c & 3) * 4;                                      \
            int gr = rowBase + r;                                                  \
            bool ok = gr < M;                                                      \
            unsigned int off = ((ST) * 5120 + r * 20 + c4) * 4;                    \
            cpasync16(sbase + off, &Ah2[(size_t)gr * K2 + k2b + c4], ok);          \
            cpasync16(sbase + off + 2560 * 4, &Al2[(size_t)gr * K2 + k2b + c4], ok); \
        }                                                                          \
        {                                                                          \
            int r = tid >> 4, c4 = (tid & 15) * 4;                                 \
            unsigned int off = (10240 + (ST) * 2304 + r * 72 + c4) * 4;            \
            cpasync16(sbase + off, &Bh2[(size_t)(k2b + r) * N + colBase + c4], true); \
            cpasync16(sbase + off + 1152 * 4, &Bl2[(size_t)(k2b + r) * N + colBase + c4], true); \
        }                                                                          \
        CP_COMMIT();                                                               \
    } while (0)

    float acc[2][4][4];
#pragma unroll
    for (int mi = 0; mi < 2; mi++)
#pragma unroll
        for (int ni = 0; ni < 4; ni++)
#pragma unroll
            for (int r = 0; r < 4; r++) acc[mi][ni][r] = 0.f;

    int niter = K >> 5;
    PREFETCH(0, 0);

    for (int it = 0; it < niter; it++) {
        int st = it & 1;
        if (it + 1 < niter) {
            PREFETCH(it + 1, st ^ 1);
            CP_WAIT(1);
        } else {
            CP_WAIT(0);
        }
        __syncthreads();

        const unsigned int* AsH = smem + st * 5120;
        const unsigned int* AsL = AsH + 2560;
        const unsigned int* BsH = smem + 10240 + st * 2304;
        const unsigned int* BsL = BsH + 1152;

#pragma unroll
        for (int ks = 0; ks < 2; ks++) {
            unsigned int ah[2][4], al[2][4], bh[4][2], bl[4][2];
#pragma unroll
            for (int mi = 0; mi < 2; mi++) {
                int m = wm + mi * 16 + mrow;
                int i0 = m * 20 + ks * 8 + kc;
                ah[mi][0] = AsH[i0];            al[mi][0] = AsL[i0];
                ah[mi][1] = AsH[i0 + 160];      al[mi][1] = AsL[i0 + 160];   // row+8
                ah[mi][2] = AsH[i0 + 4];        al[mi][2] = AsL[i0 + 4];     // k+8
                ah[mi][3] = AsH[i0 + 164];      al[mi][3] = AsL[i0 + 164];
            }
#pragma unroll
            for (int ni = 0; ni < 4; ni++) {
                int ib = (ks * 8 + kc) * 72 + wn + ni * 8 + mrow;
                bh[ni][0] = BsH[ib];            bl[ni][0] = BsL[ib];
                bh[ni][1] = BsH[ib + 288];      bl[ni][1] = BsL[ib + 288];   // k+8
            }
#define MMA_B(ar, br, mi, ni)                                                     \
    asm volatile(                                                                 \
        "mma.sync.aligned.m16n8k16.row.col.f32.bf16.bf16.f32 "                    \
        "{%0,%1,%2,%3},{%4,%5,%6,%7},{%8,%9},{%0,%1,%2,%3};"                      \
        : "+f"(acc[mi][ni][0]), "+f"(acc[mi][ni][1]),                             \
          "+f"(acc[mi][ni][2]), "+f"(acc[mi][ni][3])                              \
        : "r"(ar[mi][0]), "r"(ar[mi][1]), "r"(ar[mi][2]), "r"(ar[mi][3]),         \
          "r"(br[ni][0]), "r"(br[ni][1]))
#pragma unroll
            for (int mi = 0; mi < 2; mi++)
#pragma unroll
                for (int ni = 0; ni < 4; ni++) {
                    MMA_B(ah, bl, mi, ni);
                    MMA_B(al, bh, mi, ni);
                    MMA_B(ah, bh, mi, ni);
                }
#undef MMA_B
        }
        __syncthreads();
    }
#undef PREFETCH

#pragma unroll
    for (int mi = 0; mi < 2; mi++) {
        int r0 = rowBase + wm + mi * 16 + mrow;
#pragma unroll
        for (int ni = 0; ni < 4; ni++) {
            int c = colBase + wn + ni * 8 + kc * 2;
            if (r0 < M) {
                C[(size_t)r0 * N + c]     = acc[mi][ni][0];
                C[(size_t)r0 * N + c + 1] = acc[mi][ni][1];
            }
            if (r0 + 8 < M) {
                C[(size_t)(r0 + 8) * N + c]     = acc[mi][ni][2];
                C[(size_t)(r0 + 8) * N + c + 1] = acc[mi][ni][3];
            }
        }
    }
}

// ---------------- fallback SGEMM (small classifier GEMMs) ---------------------
#define BM 128
#define BN 64
#define BK 16
#define TM 8
#define TN 4
__global__ __launch_bounds__(256) void sgemm_k(
    const float* __restrict__ A, const float* __restrict__ B,
    float* __restrict__ C, int M, int N, int K,
    const float* __restrict__ bias, int relu)
{
    __shared__ float As[BK][BM];
    __shared__ float Bs[BK][BN];
    int tid = threadIdx.x;
    int tx = tid % (BN / TN);
    int ty = tid / (BN / TN);
    int rowBase = blockIdx.y * BM;
    int colBase = blockIdx.x * BN;

    float acc[TM][TN];
#pragma unroll
    for (int i = 0; i < TM; i++)
#pragma unroll
        for (int j = 0; j < TN; j++) acc[i][j] = 0.f;

    for (int k0 = 0; k0 < K; k0 += BK) {
        for (int i = tid; i < BM * BK; i += 256) {
            int r = i / BK, c = i % BK;
            int gr = rowBase + r, gc = k0 + c;
            As[c][r] = (gr < M && gc < K) ? A[(size_t)gr * K + gc] : 0.f;
        }
        for (int i = tid; i < BK * BN; i += 256) {
            int r = i / BN, c = i % BN;
            int gr = k0 + r, gc = colBase + c;
            Bs[r][c] = (gr < K && gc < N) ? B[(size_t)gr * N + gc] : 0.f;
        }
        __syncthreads();
#pragma unroll
        for (int k = 0; k < BK; k++) {
            float a[TM], b[TN];
#pragma unroll
            for (int i = 0; i < TM; i++) a[i] = As[k][ty * TM + i];
#pragma unroll
            for (int j = 0; j < TN; j++) b[j] = Bs[k][tx * TN + j];
#pragma unroll
            for (int i = 0; i < TM; i++)
#pragma unroll
                for (int j = 0; j < TN; j++) acc[i][j] += a[i] * b[j];
        }
        __syncthreads();
    }
#pragma unroll
    for (int i = 0; i < TM; i++) {
        int gr = rowBase + ty * TM + i;
        if (gr >= M) continue;
#pragma unroll
        for (int j = 0; j < TN; j++) {
            int gc = colBase + tx * TN + j;
            if (gc >= N) continue;
            float v = acc[i][j];
            if (bias) v += bias[gc];
            if (relu) v = fmaxf(v, 0.f);
            C[(size_t)gr * N + gc] = v;
        }
    }
}

// ---------------- attention coefficients: a_s[n,h], a_d[n,h] ------------------
__global__ void attn_coef_k(const float* __restrict__ h,
                            const float* __restrict__ asw,
                            const float* __restrict__ adw,
                            float* __restrict__ as_o, float* __restrict__ ad_o,
                            int n, int H)
{
    int w = (blockIdx.x * blockDim.x + threadIdx.x) >> 5;
    int lane = threadIdx.x & 31;
    if (w >= n * H) return;
    int node = w / H, hd = w - node * H;
    const float* row = h + (size_t)node * H * CDIM + hd * CDIM;
    float s = 0.f, d = 0.f;
#pragma unroll
    for (int c = lane; c < CDIM; c += 32) {
        float v = row[c];
        s += v * asw[hd * CDIM + c];
        d += v * adw[hd * CDIM + c];
    }
#pragma unroll
    for (int o = 16; o; o >>= 1) {
        s += __shfl_down_sync(0xFFFFFFFFu, s, o);
        d += __shfl_down_sync(0xFFFFFFFFu, d, o);
    }
    if (!lane) { as_o[w] = s; ad_o[w] = d; }
}

// ---------------- fused softmax + CSR aggregation (H=4), single pass ----------
__global__ void agg4_k(const int* __restrict__ rowptr, const int* __restrict__ csrc,
                       const float* __restrict__ h,
                       const float* __restrict__ asb, const float* __restrict__ adb,
                       float* __restrict__ out, int n)
{
    int w = (blockIdx.x * blockDim.x + threadIdx.x) >> 5;
    int lane = threadIdx.x & 31;
    if (w >= n) return;
    int beg = rowptr[w], end = rowptr[w + 1];

    int eh = lane & 3;
    float ad_h = adb[(size_t)w * 4 + eh];
    int hA = lane >> 4;        // head supplying channels [0,128): 0 or 1
    int hB = 2 + hA;           // head supplying channels [128,256): 2 or 3

    float4 acc0 = make_float4(0.f, 0.f, 0.f, 0.f);
    float4 acc1 = make_float4(0.f, 0.f, 0.f, 0.f);
    float den = 0.f;
    for (int j = beg; j < end; j++) {
        int s = __ldg(&csrc[j]);
        float e = asb[(size_t)s * 4 + eh] + ad_h;
        e = e > 0.f ? e : 0.2f * e;
        float ww = __expf(e);
        den += ww;
        float aA = __shfl_sync(0xFFFFFFFFu, ww, hA);
        float aB = __shfl_sync(0xFFFFFFFFu, ww, hB);
        const float4* hr = (const float4*)(h + (size_t)s * 256);
        float4 v0 = hr[lane];
        float4 v1 = hr[32 + lane];
        acc0.x += v0.x * aA; acc0.y += v0.y * aA; acc0.z += v0.z * aA; acc0.w += v0.w * aA;
        acc1.x += v1.x * aB; acc1.y += v1.y * aB; acc1.z += v1.z * aB; acc1.w += v1.w * aB;
    }
    float iA = 1.f / __shfl_sync(0xFFFFFFFFu, den, hA);
    float iB = 1.f / __shfl_sync(0xFFFFFFFFu, den, hB);
    acc0.x *= iA; acc0.y *= iA; acc0.z *= iA; acc0.w *= iA;
    acc1.x *= iB; acc1.y *= iB; acc1.z *= iB; acc1.w *= iB;
    float4* o4 = (float4*)(out + (size_t)w * 256);
    o4[lane] = acc0;
    o4[32 + lane] = acc1;
}

// ---------------- fused softmax + CSR aggregation (H=1) + bias, single pass ---
__global__ void agg1_k(const int* __restrict__ rowptr, const int* __restrict__ csrc,
                       const float* __restrict__ h,
                       const float* __restrict__ asb, const float* __restrict__ adb,
                       const float* __restrict__ bias,
                       float* __restrict__ out, int n)
{
    int w = (blockIdx.x * blockDim.x + threadIdx.x) >> 5;
    int lane = threadIdx.x & 31;
    if (w >= n) return;
    int beg = rowptr[w], end = rowptr[w + 1];
    float ad = adb[w];

    float den = 0.f;
    float4 acc = make_float4(0.f, 0.f, 0.f, 0.f);
    for (int j = beg; j < end; j++) {
        int s = __ldg(&csrc[j]);
        float e = asb[s] + ad;
        e = e > 0.f ? e : 0.2f * e;
        float ww = __expf(e);
        den += ww;
        if (lane < 16) {
            float4 v = ((const float4*)(h + (size_t)s * 64))[lane];
            acc.x += v.x * ww; acc.y += v.y * ww; acc.z += v.z * ww; acc.w += v.w * ww;
        }
    }
    if (lane < 16) {
        float inv = 1.f / den;
        float4 b4 = ((const float4*)bias)[lane];
        acc.x = acc.x * inv + b4.x; acc.y = acc.y * inv + b4.y;
        acc.z = acc.z * inv + b4.z; acc.w = acc.w * inv + b4.w;
        ((float4*)(out + (size_t)w * 64))[lane] = acc;
    }
}

// ---------------- batch norm (C=256 channels) ---------------------------------
__global__ void bn_stats_k(const float* __restrict__ x, int n, float* sum, float* sq) {
    int ch = threadIdx.x;
    float s = 0.f, s2 = 0.f;
    for (int r = blockIdx.x; r < n; r += gridDim.x) {
        float v = x[(size_t)r * HWID + ch];
        s += v; s2 += v * v;
    }
    atomicAdd(&sum[ch], s);
    atomicAdd(&sq[ch], s2);
}

__global__ void bn_fin_k(const float* sum, const float* sq,
                         const float* __restrict__ g, const float* __restrict__ be,
                         int n, float* scl, float* sft) {
    int ch = threadIdx.x;
    float mu = sum[ch] / (float)n;
    float var = fmaxf(sq[ch] / (float)n - mu * mu, 0.f);
    float r = rsqrtf(var + 1e-5f);
    float s = g[ch] * r;
    scl[ch] = s;
    sft[ch] = be[ch] - mu * s;
}

// BN + ELU, output directly as bf16 hi/lo packed (feeds only the next GEMM)
__global__ void bn_apply_elu_split_k(const float4* __restrict__ in,
                                     unsigned int* __restrict__ hi2,
                                     unsigned int* __restrict__ lo2,
                                     const float* __restrict__ scl,
                                     const float* __restrict__ sft,
                                     int n4) {
    int i = blockIdx.x * blockDim.x + threadIdx.x;
    if (i >= n4) return;
    int c4 = (i & (HWID / 4 - 1)) * 4;
    float4 v = in[i];
    v.x = v.x * scl[c4 + 0] + sft[c4 + 0];
    v.y = v.y * scl[c4 + 1] + sft[c4 + 1];
    v.z = v.z * scl[c4 + 2] + sft[c4 + 2];
    v.w = v.w * scl[c4 + 3] + sft[c4 + 3];
    v.x = v.x > 0.f ? v.x : __expf(v.x) - 1.f;
    v.y = v.y > 0.f ? v.y : __expf(v.y) - 1.f;
    v.z = v.z > 0.f ? v.z : __expf(v.z) - 1.f;
    v.w = v.w > 0.f ? v.w : __expf(v.w) - 1.f;
    uint2 h, l;
    bf16split2(v.x, v.y, h.x, l.x);
    bf16split2(v.z, v.w, h.y, l.y);
    ((uint2*)hi2)[i] = h;
    ((uint2*)lo2)[i] = l;
}

// ---------------- host-side orchestration -------------------------------------
#define GEMM_SMEM 59392

static void run_bf16gemm(const unsigned int* Ah, const unsigned int* Al,
                         const unsigned int* Bh, const unsigned int* Bl,
                         float* C, int M, int N, int K) {
    dim3 grid(N / 64, (M + 127) / 128);
    bf16gemm2_k<<<grid, 256, GEMM_SMEM>>>(Ah, Al, Bh, Bl, C, M, N, K);
}

static void run_sgemm(const float* A, const float* B, float* C, int M, int N, int K,
                      const float* bias, int relu) {
    dim3 grid((N + BN - 1) / BN, (M + BM - 1) / BM);
    sgemm_k<<<grid, 256>>>(A, B, C, M, N, K, bias, relu);
}

static void bn_elu_split(const float* in, unsigned int* hi, unsigned int* lo,
                         const float* g, const float* be, int n,
                         float* sumb, float* sqb, float* sclb, float* sftb)
{
    fill_k<<<1, 256>>>(sumb, 0.f, HWID);
    fill_k<<<1, 256>>>(sqb, 0.f, HWID);
    bn_stats_k<<<512, 256>>>(in, n, sumb, sqb);
    bn_fin_k<<<1, 256>>>(sumb, sqb, g, be, n, sclb, sftb);
    bn_apply_elu_split_k<<<(n * HWID / 4 + 255) / 256, 256>>>(
        (const float4*)in, hi, lo, sclb, sftb, n * HWID / 4);
}

extern "C" void kernel_launch(void* const* d_in, const int* in_sizes, int n_in,
                              void* d_out, int out_size)
{
    const float* x   = (const float*)d_in[0];
    const int*   ei  = (const int*)  d_in[1];
    const float* W0  = (const float*)d_in[2];
    const float* as0 = (const float*)d_in[3];
    const float* ad0 = (const float*)d_in[4];
    // b0 (d_in[5]) cancels through BatchNorm — skipped
    const float* W1  = (const float*)d_in[6];
    const float* as1 = (const float*)d_in[7];
    const float* ad1 = (const float*)d_in[8];
    // b1 (d_in[9]) cancels through BatchNorm — skipped
    const float* W2  = (const float*)d_in[10];
    const float* as2 = (const float*)d_in[11];
    const float* ad2 = (const float*)d_in[12];
    const float* b2  = (const float*)d_in[13];
    const float* g0  = (const float*)d_in[14];
    const float* be0 = (const float*)d_in[15];
    const float* g1  = (const float*)d_in[16];
    const float* be1 = (const float*)d_in[17];
    const float* Wc1 = (const float*)d_in[18];
    const float* bc1 = (const float*)d_in[19];
    const float* Wc2 = (const float*)d_in[20];
    const float* bc2 = (const float*)d_in[21];
    float* out = (float*)d_out;

    const int n = N_NODES;
    const int* src = ei;
    const int* dst = ei + N_EDGES;

    static int smem_cfg_done = 0;
    if (!smem_cfg_done) {
        cudaFuncSetAttribute(bf16gemm2_k,
                             cudaFuncAttributeMaxDynamicSharedMemorySize, GEMM_SMEM);
        smem_cfg_done = 1;
    }

    float *hbuf, *aggbuf, *asb, *adb;
    float *sumb, *sqb, *sclb, *sftb, *clsb;
    unsigned int *ahi, *alo, *w0h, *w0l, *w1h, *w1l, *w2h, *w2l;
    int *degb, *curb, *rowb, *csrcb, *blkb;
    cudaGetSymbolAddress((void**)&hbuf,  g_h);
    cudaGetSymbolAddress((void**)&aggbuf, g_agg);
    cudaGetSymbolAddress((void**)&asb,   g_as);
    cudaGetSymbolAddress((void**)&adb,   g_ad);
    cudaGetSymbolAddress((void**)&sumb,  g_sum);
    cudaGetSymbolAddress((void**)&sqb,   g_sq);
    cudaGetSymbolAddress((void**)&sclb,  g_scl);
    cudaGetSymbolAddress((void**)&sftb,  g_sft);
    cudaGetSymbolAddress((void**)&clsb,  g_cls);
    cudaGetSymbolAddress((void**)&ahi,   g_ahi);
    cudaGetSymbolAddress((void**)&alo,   g_alo);
    cudaGetSymbolAddress((void**)&w0h,   g_w0h);
    cudaGetSymbolAddress((void**)&w0l,   g_w0l);
    cudaGetSymbolAddress((void**)&w1h,   g_w1h);
    cudaGetSymbolAddress((void**)&w1l,   g_w1l);
    cudaGetSymbolAddress((void**)&w2h,   g_w2h);
    cudaGetSymbolAddress((void**)&w2l,   g_w2l);
    cudaGetSymbolAddress((void**)&degb,  g_deg);
    cudaGetSymbolAddress((void**)&curb,  g_cursor);
    cudaGetSymbolAddress((void**)&rowb,  g_rowptr);
    cudaGetSymbolAddress((void**)&csrcb, g_csrc);
    cudaGetSymbolAddress((void**)&blkb,  g_blksum);

    // ---- operand splits + CSR zero; GEMM is our 4th launch (ncu window) ----
    split_x_k<<<(n * 64 + 255) / 256, 256>>>((const float2*)x, ahi, alo, n * 64);
    split_w_k<<<(64 * 256 + 255) / 256, 256>>>(W0, w0h, w0l, 128, 256);
    fill2i_k<<<(n + 255) / 256, 256>>>(degb, curb, n);

    // ---- GAT layer 0 GEMM: 128 -> 4x64 ----
    run_bf16gemm(ahi, alo, w0h, w0l, hbuf, n, 256, 128);
    attn_coef_k<<<(n * 4 * 32 + 255) / 256, 256>>>(hbuf, as0, ad0, asb, adb, n, 4);

    // ---- CSR build + remaining weight splits ----
    deg_k<<<(ET_EDGES + 255) / 256, 256>>>(dst, degb, N_EDGES, ET_EDGES);
    scan_part_k<<<NBLK_SCAN, 256>>>(degb, rowb, blkb, n);
    scan_tops_k<<<1, 256>>>(blkb, NBLK_SCAN);
    scan_write_k<<<NBLK_SCAN, 256>>>(rowb, blkb, n);
    fill_pos_k<<<(ET_EDGES + 255) / 256, 256>>>(src, dst, rowb, curb, csrcb,
                                                N_EDGES, ET_EDGES);
    split_w_k<<<(128 * 256 + 255) / 256, 256>>>(W1, w1h, w1l, 256, 256);
    split_w_k<<<(128 * 64 + 255) / 256, 256>>>(W2, w2h, w2l, 256, 64);

    int aggBlocks = (n * 32 + 255) / 256;

    // ---- GAT layer 0 aggregation + BN/ELU (-> split bufs) ----
    agg4_k<<<aggBlocks, 256>>>(rowb, csrcb, hbuf, asb, adb, aggbuf, n);
    bn_elu_split(aggbuf, ahi, alo, g0, be0, n, sumb, sqb, sclb, sftb);

    // ---- GAT layer 1: 256 -> 4x64 (concat) ----
    run_bf16gemm(ahi, alo, w1h, w1l, hbuf, n, 256, 256);
    attn_coef_k<<<(n * 4 * 32 + 255) / 256, 256>>>(hbuf, as1, ad1, asb, adb, n, 4);
    agg4_k<<<aggBlocks, 256>>>(rowb, csrcb, hbuf, asb, adb, aggbuf, n);
    bn_elu_split(aggbuf, ahi, alo, g1, be1, n, sumb, sqb, sclb, sftb);

    // ---- GAT layer 2: 256 -> 1x64 + bias ----
    run_bf16gemm(ahi, alo, w2h, w2l, hbuf, n, 64, 256);
    attn_coef_k<<<(n * 32 + 255) / 256, 256>>>(hbuf, as2, ad2, asb, adb, n, 1);
    agg1_k<<<aggBlocks, 256>>>(rowb, csrcb, hbuf, asb, adb, b2, aggbuf, n);

    // ---- classifier: 64 -> 32 (relu) -> 2 ----
    run_sgemm(aggbuf, Wc1, clsb, n, 32, 64, bc1, 1);
    run_sgemm(clsb, Wc2, out, n, 2, 32, bc2, 0);
}

// round 11
// speedup vs baseline: 1.3548x; 1.0806x over previous
#include <cuda_runtime.h>
#include <cuda_bf16.h>
#include <math.h>

// Problem constants (fixed by the dataset)
#define N_NODES 50000
#define N_EDGES 800000
#define ET_EDGES (N_NODES + N_EDGES)   // edges + self loops
#define HWID 256                        // heads*hid for layers 0/1
#define CDIM 64
#define NBLK_SCAN ((N_NODES + 255) / 256)   // 196

// ---------------- scratch (device globals; no allocation allowed) -------------
static __device__ float g_h   [(size_t)N_NODES * HWID];
static __device__ float g_agg [(size_t)N_NODES * HWID];
static __device__ float g_as  [N_NODES * 4];
static __device__ float g_ad  [N_NODES * 4];
static __device__ float g_sum [HWID];
static __device__ float g_sq  [HWID];
static __device__ float g_scl [HWID];
static __device__ float g_sft [HWID];
// bf16 hi/lo packed operands (A: [M][K/2] u32; W: [K/2][N] u32)
static __device__ unsigned int g_ahi[(size_t)N_NODES * 128];
static __device__ unsigned int g_alo[(size_t)N_NODES * 128];
static __device__ unsigned int g_w0h[64 * 256],  g_w0l[64 * 256];
static __device__ unsigned int g_w1h[128 * 256], g_w1l[128 * 256];
static __device__ unsigned int g_w2h[128 * 64],  g_w2l[128 * 64];
// CSR scratch
static __device__ int g_deg   [N_NODES];
static __device__ int g_cursor[N_NODES];
static __device__ int g_rowptr[N_NODES + 1];
static __device__ int g_csrc  [ET_EDGES];      // src node per CSR slot
static __device__ int g_blksum[256];

// ---------------- helpers -----------------------------------------------------
// split two fp32 into packed bf16x2 hi + bf16x2 lo (lower k in low 16 bits)
__device__ __forceinline__ void bf16split2(float v0, float v1,
                                           unsigned int& hi, unsigned int& lo) {
    __nv_bfloat16 h0 = __float2bfloat16(v0), h1 = __float2bfloat16(v1);
    float r0 = v0 - __bfloat162float(h0);
    float r1 = v1 - __bfloat162float(h1);
    __nv_bfloat16 l0 = __float2bfloat16(r0), l1 = __float2bfloat16(r1);
    hi = ((unsigned int)__bfloat16_as_ushort(h1) << 16) | __bfloat16_as_ushort(h0);
    lo = ((unsigned int)__bfloat16_as_ushort(l1) << 16) | __bfloat16_as_ushort(l0);
}

__device__ __forceinline__ void cpasync16(unsigned int dst, const void* src, bool pred) {
    int sz = pred ? 16 : 0;
    asm volatile("cp.async.cg.shared.global [%0], [%1], 16, %2;"
                 :: "r"(dst), "l"(src), "r"(sz) : "memory");
}
#define CP_COMMIT() asm volatile("cp.async.commit_group;" ::: "memory")
#define CP_WAIT(N)  asm volatile("cp.async.wait_group %0;" :: "n"(N) : "memory")

__global__ void fill_k(float* p, float v, int n) {
    int i = blockIdx.x * blockDim.x + threadIdx.x;
    if (i < n) p[i] = v;
}

__global__ void fill2f_k(float* p, float* q, int n) {
    int i = blockIdx.x * blockDim.x + threadIdx.x;
    if (i < n) { p[i] = 0.f; q[i] = 0.f; }
}

__global__ void fill2i_k(int* p, int* q, int n) {
    int i = blockIdx.x * blockDim.x + threadIdx.x;
    if (i < n) { p[i] = 0; q[i] = 0; }
}

// ---------------- operand pre-split kernels -----------------------------------
__global__ void split_x_k(const float2* __restrict__ x2,
                          unsigned int* __restrict__ hi, unsigned int* __restrict__ lo,
                          int n2) {
    int j = blockIdx.x * blockDim.x + threadIdx.x;
    if (j >= n2) return;
    float2 v = x2[j];
    bf16split2(v.x, v.y, hi[j], lo[j]);
}

__global__ void split_w_k(const float* __restrict__ W,
                          unsigned int* __restrict__ hi, unsigned int* __restrict__ lo,
                          int K, int N) {
    int j = blockIdx.x * blockDim.x + threadIdx.x;
    if (j >= (K / 2) * N) return;
    int k2 = j / N, nn = j - k2 * N;
    float v0 = W[(size_t)(2 * k2) * N + nn];
    float v1 = W[(size_t)(2 * k2 + 1) * N + nn];
    bf16split2(v0, v1, hi[j], lo[j]);
}

// ---------------- CSR construction --------------------------------------------
__global__ void deg_k(const int* __restrict__ dst, int* deg, int E, int et) {
    int e = blockIdx.x * blockDim.x + threadIdx.x;
    if (e >= et) return;
    int d = e < E ? dst[e] : e - E;
    atomicAdd(&deg[d], 1);
}

__global__ void scan_part_k(const int* __restrict__ deg, int* rowptr, int* blksum, int n) {
    __shared__ int sm[256];
    int i = blockIdx.x * 256 + threadIdx.x;
    int v = (i < n) ? deg[i] : 0;
    sm[threadIdx.x] = v;
    __syncthreads();
    for (int o = 1; o < 256; o <<= 1) {
        int t = (threadIdx.x >= o) ? sm[threadIdx.x - o] : 0;
        __syncthreads();
        sm[threadIdx.x] += t;
        __syncthreads();
    }
    if (i < n) rowptr[i] = sm[threadIdx.x] - v;      // exclusive
    if (threadIdx.x == 255) blksum[blockIdx.x] = sm[255];
}

__global__ void scan_tops_k(int* blksum, int nb) {
    __shared__ int sm[256];
    int v = (threadIdx.x < nb) ? blksum[threadIdx.x] : 0;
    sm[threadIdx.x] = v;
    __syncthreads();
    for (int o = 1; o < 256; o <<= 1) {
        int t = (threadIdx.x >= o) ? sm[threadIdx.x - o] : 0;
        __syncthreads();
        sm[threadIdx.x] += t;
        __syncthreads();
    }
    if (threadIdx.x < nb) blksum[threadIdx.x] = sm[threadIdx.x] - v;   // exclusive
}

__global__ void scan_write_k(int* rowptr, const int* __restrict__ blksum, int n) {
    int i = blockIdx.x * 256 + threadIdx.x;
    if (i < n) rowptr[i] += blksum[blockIdx.x];
    if (i == 0) rowptr[n] = ET_EDGES;
}

__global__ void fill_pos_k(const int* __restrict__ src, const int* __restrict__ dst,
                           const int* __restrict__ rowptr,
                           int* cursor, int* csrc, int E, int et) {
    int e = blockIdx.x * blockDim.x + threadIdx.x;
    if (e >= et) return;
    int s, d;
    if (e < E) { s = src[e]; d = dst[e]; } else { s = d = e - E; }
    int p = atomicAdd(&cursor[d], 1);
    csrc[rowptr[d] + p] = s;
}

// ---------------- bf16 hi/lo GEMM + fused attention coefficients --------------
// C = A @ B (pre-split bf16 hi/lo, packed bf16x2 along K).
// Epilogue also accumulates a_s[row][head] += C_row . attn_s[head],
// a_d likewise, via spread atomics (head = blockIdx.x since BN=64; H = gridDim.x).
// as_o/ad_o must be zeroed before launch.
__global__ __launch_bounds__(256, 3) void bf16gemm2_k(
    const unsigned int* __restrict__ Ah2, const unsigned int* __restrict__ Al2,
    const unsigned int* __restrict__ Bh2, const unsigned int* __restrict__ Bl2,
    float* __restrict__ C, int M, int N, int K,
    const float* __restrict__ attn_s, const float* __restrict__ attn_d,
    float* __restrict__ as_o, float* __restrict__ ad_o)
{
    extern __shared__ unsigned int smem[];
    unsigned int sbase = (unsigned int)__cvta_generic_to_shared(smem);

    int tid = threadIdx.x;
    int warp = tid >> 5, lane = tid & 31;
    int wm = (warp & 3) * 32;
    int wn = (warp >> 2) * 32;
    int rowBase = blockIdx.y * 128;
    int colBase = blockIdx.x * 64;
    int mrow = lane >> 2;           // 0..7
    int kc   = lane & 3;            // 0..3
    int K2 = K >> 1;

#define PREFETCH(IT, ST)                                                           \
    do {                                                                           \
        int k2b = (IT) * 16;                                                       \
        _Pragma("unroll")                                                          \
        for (int i = 0; i < 2; i++) {                                              \
            int c = tid + i * 256;                                                 \
            int r = c >> 2, c4 = (c & 3) * 4;                                      \
            int gr = rowBase + r;                                                  \
            bool ok = gr < M;                                                      \
            unsigned int off = ((ST) * 5120 + r * 20 + c4) * 4;                    \
            cpasync16(sbase + off, &Ah2[(size_t)gr * K2 + k2b + c4], ok);          \
            cpasync16(sbase + off + 2560 * 4, &Al2[(size_t)gr * K2 + k2b + c4], ok); \
        }                                                                          \
        {                                                                          \
            int r = tid >> 4, c4 = (tid & 15) * 4;                                 \
            unsigned int off = (10240 + (ST) * 2304 + r * 72 + c4) * 4;            \
            cpasync16(sbase + off, &Bh2[(size_t)(k2b + r) * N + colBase + c4], true); \
            cpasync16(sbase + off + 1152 * 4, &Bl2[(size_t)(k2b + r) * N + colBase + c4], true); \
        }                                                                          \
        CP_COMMIT();                                                               \
    } while (0)

    float acc[2][4][4];
#pragma unroll
    for (int mi = 0; mi < 2; mi++)
#pragma unroll
        for (int ni = 0; ni < 4; ni++)
#pragma unroll
            for (int r = 0; r < 4; r++) acc[mi][ni][r] = 0.f;

    int niter = K >> 5;
    PREFETCH(0, 0);

    for (int it = 0; it < niter; it++) {
        int st = it & 1;
        if (it + 1 < niter) {
            PREFETCH(it + 1, st ^ 1);
            CP_WAIT(1);
        } else {
            CP_WAIT(0);
        }
        __syncthreads();

        const unsigned int* AsH = smem + st * 5120;
        const unsigned int* AsL = AsH + 2560;
        const unsigned int* BsH = smem + 10240 + st * 2304;
        const unsigned int* BsL = BsH + 1152;

#pragma unroll
        for (int ks = 0; ks < 2; ks++) {
            unsigned int ah[2][4], al[2][4], bh[4][2], bl[4][2];
#pragma unroll
            for (int mi = 0; mi < 2; mi++) {
                int m = wm + mi * 16 + mrow;
                int i0 = m * 20 + ks * 8 + kc;
                ah[mi][0] = AsH[i0];            al[mi][0] = AsL[i0];
                ah[mi][1] = AsH[i0 + 160];      al[mi][1] = AsL[i0 + 160];   // row+8
                ah[mi][2] = AsH[i0 + 4];        al[mi][2] = AsL[i0 + 4];     // k+8
                ah[mi][3] = AsH[i0 + 164];      al[mi][3] = AsL[i0 + 164];
            }
#pragma unroll
            for (int ni = 0; ni < 4; ni++) {
                int ib = (ks * 8 + kc) * 72 + wn + ni * 8 + mrow;
                bh[ni][0] = BsH[ib];            bl[ni][0] = BsL[ib];
                bh[ni][1] = BsH[ib + 288];      bl[ni][1] = BsL[ib + 288];   // k+8
            }
#define MMA_B(ar, br, mi, ni)                                                     \
    asm volatile(                                                                 \
        "mma.sync.aligned.m16n8k16.row.col.f32.bf16.bf16.f32 "                    \
        "{%0,%1,%2,%3},{%4,%5,%6,%7},{%8,%9},{%0,%1,%2,%3};"                      \
        : "+f"(acc[mi][ni][0]), "+f"(acc[mi][ni][1]),                             \
          "+f"(acc[mi][ni][2]), "+f"(acc[mi][ni][3])                              \
        : "r"(ar[mi][0]), "r"(ar[mi][1]), "r"(ar[mi][2]), "r"(ar[mi][3]),         \
          "r"(br[ni][0]), "r"(br[ni][1]))
#pragma unroll
            for (int mi = 0; mi < 2; mi++)
#pragma unroll
                for (int ni = 0; ni < 4; ni++) {
                    MMA_B(ah, bl, mi, ni);
                    MMA_B(al, bh, mi, ni);
                    MMA_B(ah, bh, mi, ni);
                }
#undef MMA_B
        }
        __syncthreads();
    }
#undef PREFETCH

    // ---- epilogue: store C + fused attention coefficients ----
    int H = gridDim.x;
    int head = blockIdx.x;
    const float* av = attn_s + head * 64;
    const float* dv = attn_d + head * 64;
    float avv[8], dvv[8];
#pragma unroll
    for (int ni = 0; ni < 4; ni++)
#pragma unroll
        for (int j = 0; j < 2; j++) {
            int cc = wn + ni * 8 + kc * 2 + j;
            avv[ni * 2 + j] = __ldg(&av[cc]);
            dvv[ni * 2 + j] = __ldg(&dv[cc]);
        }

#pragma unroll
    for (int mi = 0; mi < 2; mi++) {
        int r0 = rowBase + wm + mi * 16 + mrow;
        float s0 = 0.f, d0 = 0.f, s1 = 0.f, d1 = 0.f;
#pragma unroll
        for (int ni = 0; ni < 4; ni++) {
            int c = colBase + wn + ni * 8 + kc * 2;
            if (r0 < M) {
                C[(size_t)r0 * N + c]     = acc[mi][ni][0];
                C[(size_t)r0 * N + c + 1] = acc[mi][ni][1];
            }
            if (r0 + 8 < M) {
                C[(size_t)(r0 + 8) * N + c]     = acc[mi][ni][2];
                C[(size_t)(r0 + 8) * N + c + 1] = acc[mi][ni][3];
            }
            s0 += acc[mi][ni][0] * avv[ni * 2] + acc[mi][ni][1] * avv[ni * 2 + 1];
            d0 += acc[mi][ni][0] * dvv[ni * 2] + acc[mi][ni][1] * dvv[ni * 2 + 1];
            s1 += acc[mi][ni][2] * avv[ni * 2] + acc[mi][ni][3] * avv[ni * 2 + 1];
            d1 += acc[mi][ni][2] * dvv[ni * 2] + acc[mi][ni][3] * dvv[ni * 2 + 1];
        }
        // reduce over kc (4-lane aligned groups)
#pragma unroll
        for (int o = 1; o < 4; o <<= 1) {
            s0 += __shfl_xor_sync(0xFFFFFFFFu, s0, o);
            d0 += __shfl_xor_sync(0xFFFFFFFFu, d0, o);
            s1 += __shfl_xor_sync(0xFFFFFFFFu, s1, o);
            d1 += __shfl_xor_sync(0xFFFFFFFFu, d1, o);
        }
        if (kc == 0) {
            if (r0 < M) {
                atomicAdd(&as_o[r0 * H + head], s0);
                atomicAdd(&ad_o[r0 * H + head], d0);
            }
            if (r0 + 8 < M) {
                atomicAdd(&as_o[(r0 + 8) * H + head], s1);
                atomicAdd(&ad_o[(r0 + 8) * H + head], d1);
            }
        }
    }
}

// ---------------- fused softmax + CSR aggregation (H=4), single pass ----------
__global__ void agg4_k(const int* __restrict__ rowptr, const int* __restrict__ csrc,
                       const float* __restrict__ h,
                       const float* __restrict__ asb, const float* __restrict__ adb,
                       float* __restrict__ out, int n)
{
    int w = (blockIdx.x * blockDim.x + threadIdx.x) >> 5;
    int lane = threadIdx.x & 31;
    if (w >= n) return;
    int beg = rowptr[w], end = rowptr[w + 1];

    int eh = lane & 3;
    float ad_h = adb[(size_t)w * 4 + eh];
    int hA = lane >> 4;        // head supplying channels [0,128): 0 or 1
    int hB = 2 + hA;           // head supplying channels [128,256): 2 or 3

    float4 acc0 = make_float4(0.f, 0.f, 0.f, 0.f);
    float4 acc1 = make_float4(0.f, 0.f, 0.f, 0.f);
    float den = 0.f;
    for (int j = beg; j < end; j++) {
        int s = __ldg(&csrc[j]);
        float e = asb[(size_t)s * 4 + eh] + ad_h;
        e = e > 0.f ? e : 0.2f * e;
        float ww = __expf(e);
        den += ww;
        float aA = __shfl_sync(0xFFFFFFFFu, ww, hA);
        float aB = __shfl_sync(0xFFFFFFFFu, ww, hB);
        const float4* hr = (const float4*)(h + (size_t)s * 256);
        float4 v0 = hr[lane];
        float4 v1 = hr[32 + lane];
        acc0.x += v0.x * aA; acc0.y += v0.y * aA; acc0.z += v0.z * aA; acc0.w += v0.w * aA;
        acc1.x += v1.x * aB; acc1.y += v1.y * aB; acc1.z += v1.z * aB; acc1.w += v1.w * aB;
    }
    float iA = 1.f / __shfl_sync(0xFFFFFFFFu, den, hA);
    float iB = 1.f / __shfl_sync(0xFFFFFFFFu, den, hB);
    acc0.x *= iA; acc0.y *= iA; acc0.z *= iA; acc0.w *= iA;
    acc1.x *= iB; acc1.y *= iB; acc1.z *= iB; acc1.w *= iB;
    float4* o4 = (float4*)(out + (size_t)w * 256);
    o4[lane] = acc0;
    o4[32 + lane] = acc1;
}

// ---------------- fused softmax + CSR aggregation (H=1) + bias, single pass ---
__global__ void agg1_k(const int* __restrict__ rowptr, const int* __restrict__ csrc,
                       const float* __restrict__ h,
                       const float* __restrict__ asb, const float* __restrict__ adb,
                       const float* __restrict__ bias,
                       float* __restrict__ out, int n)
{
    int w = (blockIdx.x * blockDim.x + threadIdx.x) >> 5;
    int lane = threadIdx.x & 31;
    if (w >= n) return;
    int beg = rowptr[w], end = rowptr[w + 1];
    float ad = adb[w];

    float den = 0.f;
    float4 acc = make_float4(0.f, 0.f, 0.f, 0.f);
    for (int j = beg; j < end; j++) {
        int s = __ldg(&csrc[j]);
        float e = asb[s] + ad;
        e = e > 0.f ? e : 0.2f * e;
        float ww = __expf(e);
        den += ww;
        if (lane < 16) {
            float4 v = ((const float4*)(h + (size_t)s * 64))[lane];
            acc.x += v.x * ww; acc.y += v.y * ww; acc.z += v.z * ww; acc.w += v.w * ww;
        }
    }
    if (lane < 16) {
        float inv = 1.f / den;
        float4 b4 = ((const float4*)bias)[lane];
        acc.x = acc.x * inv + b4.x; acc.y = acc.y * inv + b4.y;
        acc.z = acc.z * inv + b4.z; acc.w = acc.w * inv + b4.w;
        ((float4*)(out + (size_t)w * 64))[lane] = acc;
    }
}

// ---------------- batch norm (C=256 channels) ---------------------------------
__global__ void bn_stats_k(const float* __restrict__ x, int n, float* sum, float* sq) {
    int ch = threadIdx.x;
    float s = 0.f, s2 = 0.f;
    for (int r = blockIdx.x; r < n; r += gridDim.x) {
        float v = x[(size_t)r * HWID + ch];
        s += v; s2 += v * v;
    }
    atomicAdd(&sum[ch], s);
    atomicAdd(&sq[ch], s2);
}

__global__ void bn_fin_k(const float* sum, const float* sq,
                         const float* __restrict__ g, const float* __restrict__ be,
                         int n, float* scl, float* sft) {
    int ch = threadIdx.x;
    float mu = sum[ch] / (float)n;
    float var = fmaxf(sq[ch] / (float)n - mu * mu, 0.f);
    float r = rsqrtf(var + 1e-5f);
    float s = g[ch] * r;
    scl[ch] = s;
    sft[ch] = be[ch] - mu * s;
}

// BN + ELU, output directly as bf16 hi/lo packed (feeds only the next GEMM)
__global__ void bn_apply_elu_split_k(const float4* __restrict__ in,
                                     unsigned int* __restrict__ hi2,
                                     unsigned int* __restrict__ lo2,
                                     const float* __restrict__ scl,
                                     const float* __restrict__ sft,
                                     int n4) {
    int i = blockIdx.x * blockDim.x + threadIdx.x;
    if (i >= n4) return;
    int c4 = (i & (HWID / 4 - 1)) * 4;
    float4 v = in[i];
    v.x = v.x * scl[c4 + 0] + sft[c4 + 0];
    v.y = v.y * scl[c4 + 1] + sft[c4 + 1];
    v.z = v.z * scl[c4 + 2] + sft[c4 + 2];
    v.w = v.w * scl[c4 + 3] + sft[c4 + 3];
    v.x = v.x > 0.f ? v.x : __expf(v.x) - 1.f;
    v.y = v.y > 0.f ? v.y : __expf(v.y) - 1.f;
    v.z = v.z > 0.f ? v.z : __expf(v.z) - 1.f;
    v.w = v.w > 0.f ? v.w : __expf(v.w) - 1.f;
    uint2 h, l;
    bf16split2(v.x, v.y, h.x, l.x);
    bf16split2(v.z, v.w, h.y, l.y);
    ((uint2*)hi2)[i] = h;
    ((uint2*)lo2)[i] = l;
}

// ---------------- fused classifier: relu(X@Wc1+bc1)@Wc2+bc2 -------------------
// one warp per node; lane j owns hidden unit j (32 hidden units)
__global__ void classifier_k(const float* __restrict__ X,
                             const float* __restrict__ Wc1, const float* __restrict__ bc1,
                             const float* __restrict__ Wc2, const float* __restrict__ bc2,
                             float* __restrict__ out, int n)
{
    int w = (blockIdx.x * blockDim.x + threadIdx.x) >> 5;
    int lane = threadIdx.x & 31;
    if (w >= n) return;
    float2 xv = ((const float2*)(X + (size_t)w * 64))[lane];  // x[2*lane], x[2*lane+1]
    float h = bc1[lane];
#pragma unroll
    for (int c = 0; c < 64; c++) {
        float xc = __shfl_sync(0xFFFFFFFFu, (c & 1) ? xv.y : xv.x, c >> 1);
        h += xc * __ldg(&Wc1[c * 32 + lane]);
    }
    h = fmaxf(h, 0.f);
    float o0 = h * __ldg(&Wc2[lane * 2 + 0]);
    float o1 = h * __ldg(&Wc2[lane * 2 + 1]);
#pragma unroll
    for (int o = 16; o; o >>= 1) {
        o0 += __shfl_down_sync(0xFFFFFFFFu, o0, o);
        o1 += __shfl_down_sync(0xFFFFFFFFu, o1, o);
    }
    if (!lane) {
        out[(size_t)w * 2]     = o0 + bc2[0];
        out[(size_t)w * 2 + 1] = o1 + bc2[1];
    }
}

// ---------------- host-side orchestration -------------------------------------
#define GEMM_SMEM 59392

static void run_bf16gemm(const unsigned int* Ah, const unsigned int* Al,
                         const unsigned int* Bh, const unsigned int* Bl,
                         float* C, int M, int N, int K,
                         const float* atts, const float* attd,
                         float* aso, float* ado) {
    dim3 grid(N / 64, (M + 127) / 128);
    bf16gemm2_k<<<grid, 256, GEMM_SMEM>>>(Ah, Al, Bh, Bl, C, M, N, K,
                                          atts, attd, aso, ado);
}

static void bn_elu_split(const float* in, unsigned int* hi, unsigned int* lo,
                         const float* g, const float* be, int n,
                         float* sumb, float* sqb, float* sclb, float* sftb)
{
    fill2f_k<<<1, 256>>>(sumb, sqb, HWID);
    bn_stats_k<<<512, 256>>>(in, n, sumb, sqb);
    bn_fin_k<<<1, 256>>>(sumb, sqb, g, be, n, sclb, sftb);
    bn_apply_elu_split_k<<<(n * HWID / 4 + 255) / 256, 256>>>(
        (const float4*)in, hi, lo, sclb, sftb, n * HWID / 4);
}

extern "C" void kernel_launch(void* const* d_in, const int* in_sizes, int n_in,
                              void* d_out, int out_size)
{
    const float* x   = (const float*)d_in[0];
    const int*   ei  = (const int*)  d_in[1];
    const float* W0  = (const float*)d_in[2];
    const float* as0 = (const float*)d_in[3];
    const float* ad0 = (const float*)d_in[4];
    // b0 (d_in[5]) cancels through BatchNorm — skipped
    const float* W1  = (const float*)d_in[6];
    const float* as1 = (const float*)d_in[7];
    const float* ad1 = (const float*)d_in[8];
    // b1 (d_in[9]) cancels through BatchNorm — skipped
    const float* W2  = (const float*)d_in[10];
    const float* as2 = (const float*)d_in[11];
    const float* ad2 = (const float*)d_in[12];
    const float* b2  = (const float*)d_in[13];
    const float* g0  = (const float*)d_in[14];
    const float* be0 = (const float*)d_in[15];
    const float* g1  = (const float*)d_in[16];
    const float* be1 = (const float*)d_in[17];
    const float* Wc1 = (const float*)d_in[18];
    const float* bc1 = (const float*)d_in[19];
    const float* Wc2 = (const float*)d_in[20];
    const float* bc2 = (const float*)d_in[21];
    float* out = (float*)d_out;

    const int n = N_NODES;
    const int* src = ei;
    const int* dst = ei + N_EDGES;

    static int smem_cfg_done = 0;
    if (!smem_cfg_done) {
        cudaFuncSetAttribute(bf16gemm2_k,
                             cudaFuncAttributeMaxDynamicSharedMemorySize, GEMM_SMEM);
        smem_cfg_done = 1;
    }

    float *hbuf, *aggbuf, *asb, *adb;
    float *sumb, *sqb, *sclb, *sftb;
    unsigned int *ahi, *alo, *w0h, *w0l, *w1h, *w1l, *w2h, *w2l;
    int *degb, *curb, *rowb, *csrcb, *blkb;
    cudaGetSymbolAddress((void**)&hbuf,  g_h);
    cudaGetSymbolAddress((void**)&aggbuf, g_agg);
    cudaGetSymbolAddress((void**)&asb,   g_as);
    cudaGetSymbolAddress((void**)&adb,   g_ad);
    cudaGetSymbolAddress((void**)&sumb,  g_sum);
    cudaGetSymbolAddress((void**)&sqb,   g_sq);
    cudaGetSymbolAddress((void**)&sclb,  g_scl);
    cudaGetSymbolAddress((void**)&sftb,  g_sft);
    cudaGetSymbolAddress((void**)&ahi,   g_ahi);
    cudaGetSymbolAddress((void**)&alo,   g_alo);
    cudaGetSymbolAddress((void**)&w0h,   g_w0h);
    cudaGetSymbolAddress((void**)&w0l,   g_w0l);
    cudaGetSymbolAddress((void**)&w1h,   g_w1h);
    cudaGetSymbolAddress((void**)&w1l,   g_w1l);
    cudaGetSymbolAddress((void**)&w2h,   g_w2h);
    cudaGetSymbolAddress((void**)&w2l,   g_w2l);
    cudaGetSymbolAddress((void**)&degb,  g_deg);
    cudaGetSymbolAddress((void**)&curb,  g_cursor);
    cudaGetSymbolAddress((void**)&rowb,  g_rowptr);
    cudaGetSymbolAddress((void**)&csrcb, g_csrc);
    cudaGetSymbolAddress((void**)&blkb,  g_blksum);

    // ---- operand splits + zeroing; GEMM is our 4th launch (ncu window) ----
    split_x_k<<<(n * 64 + 255) / 256, 256>>>((const float2*)x, ahi, alo, n * 64);
    split_w_k<<<(64 * 256 + 255) / 256, 256>>>(W0, w0h, w0l, 128, 256);
    fill2f_k<<<(n * 4 + 255) / 256, 256>>>(asb, adb, n * 4);

    // ---- GAT layer 0 GEMM + attn: 128 -> 4x64 ----
    run_bf16gemm(ahi, alo, w0h, w0l, hbuf, n, 256, 128, as0, ad0, asb, adb);

    // ---- CSR build + remaining weight splits ----
    fill2i_k<<<(n + 255) / 256, 256>>>(degb, curb, n);
    deg_k<<<(ET_EDGES + 255) / 256, 256>>>(dst, degb, N_EDGES, ET_EDGES);
    scan_part_k<<<NBLK_SCAN, 256>>>(degb, rowb, blkb, n);
    scan_tops_k<<<1, 256>>>(blkb, NBLK_SCAN);
    scan_write_k<<<NBLK_SCAN, 256>>>(rowb, blkb, n);
    fill_pos_k<<<(ET_EDGES + 255) / 256, 256>>>(src, dst, rowb, curb, csrcb,
                                                N_EDGES, ET_EDGES);
    split_w_k<<<(128 * 256 + 255) / 256, 256>>>(W1, w1h, w1l, 256, 256);
    split_w_k<<<(128 * 64 + 255) / 256, 256>>>(W2, w2h, w2l, 256, 64);

    int aggBlocks = (n * 32 + 255) / 256;

    // ---- GAT layer 0 aggregation + BN/ELU (-> split bufs) ----
    agg4_k<<<aggBlocks, 256>>>(rowb, csrcb, hbuf, asb, adb, aggbuf, n);
    bn_elu_split(aggbuf, ahi, alo, g0, be0, n, sumb, sqb, sclb, sftb);

    // ---- GAT layer 1: 256 -> 4x64 (concat) ----
    fill2f_k<<<(n * 4 + 255) / 256, 256>>>(asb, adb, n * 4);
    run_bf16gemm(ahi, alo, w1h, w1l, hbuf, n, 256, 256, as1, ad1, asb, adb);
    agg4_k<<<aggBlocks, 256>>>(rowb, csrcb, hbuf, asb, adb, aggbuf, n);
    bn_elu_split(aggbuf, ahi, alo, g1, be1, n, sumb, sqb, sclb, sftb);

    // ---- GAT layer 2: 256 -> 1x64 + bias ----
    fill2f_k<<<(n + 255) / 256, 256>>>(asb, adb, n);
    run_bf16gemm(ahi, alo, w2h, w2l, hbuf, n, 64, 256, as2, ad2, asb, adb);
    agg1_k<<<aggBlocks, 256>>>(rowb, csrcb, hbuf, asb, adb, b2, aggbuf, n);

    // ---- classifier: 64 -> 32 (relu) -> 2, fused ----
    classifier_k<<<aggBlocks, 256>>>(aggbuf, Wc1, bc1, Wc2, bc2, out, n);
}

// round 12
// speedup vs baseline: 1.4074x; 1.0388x over previous
#include <cuda_runtime.h>
#include <cuda_bf16.h>
#include <math.h>

// Problem constants (fixed by the dataset)
#define N_NODES 50000
#define N_EDGES 800000
#define ET_EDGES (N_NODES + N_EDGES)   // edges + self loops
#define HWID 256                        // heads*hid for layers 0/1
#define CDIM 64
#define NBLK_SCAN ((N_NODES + 255) / 256)   // 196

// ---------------- scratch (device globals; no allocation allowed) -------------
static __device__ float g_h   [(size_t)N_NODES * HWID];
static __device__ float g_agg [(size_t)N_NODES * HWID];
static __device__ float g_as  [N_NODES * 4];
static __device__ float g_ad  [N_NODES * 4];
static __device__ float g_sum [HWID];
static __device__ float g_sq  [HWID];
static __device__ float g_scl [HWID];
static __device__ float g_sft [HWID];
// bf16 hi/lo packed weights ([K/2][N] u32)
static __device__ unsigned int g_w0h[64 * 256],  g_w0l[64 * 256];
static __device__ unsigned int g_w1h[128 * 256], g_w1l[128 * 256];
static __device__ unsigned int g_w2h[128 * 64],  g_w2l[128 * 64];
// CSR scratch
static __device__ int g_deg   [N_NODES];
static __device__ int g_cursor[N_NODES];
static __device__ int g_rowptr[N_NODES + 1];
static __device__ int g_csrc  [ET_EDGES];      // src node per CSR slot
static __device__ int g_blksum[256];

// ---------------- helpers -----------------------------------------------------
// split two fp32 into packed bf16x2 hi + bf16x2 lo (lower k in low 16 bits)
__device__ __forceinline__ void bf16split2(float v0, float v1,
                                           unsigned int& hi, unsigned int& lo) {
    __nv_bfloat16 h0 = __float2bfloat16(v0), h1 = __float2bfloat16(v1);
    float r0 = v0 - __bfloat162float(h0);
    float r1 = v1 - __bfloat162float(h1);
    __nv_bfloat16 l0 = __float2bfloat16(r0), l1 = __float2bfloat16(r1);
    hi = ((unsigned int)__bfloat16_as_ushort(h1) << 16) | __bfloat16_as_ushort(h0);
    lo = ((unsigned int)__bfloat16_as_ushort(l1) << 16) | __bfloat16_as_ushort(l0);
}

__device__ __forceinline__ void cpasync16(unsigned int dst, const void* src, bool pred) {
    int sz = pred ? 16 : 0;
    asm volatile("cp.async.cg.shared.global [%0], [%1], 16, %2;"
                 :: "r"(dst), "l"(src), "r"(sz) : "memory");
}
#define CP_COMMIT() asm volatile("cp.async.commit_group;" ::: "memory")
#define CP_WAIT(N)  asm volatile("cp.async.wait_group %0;" :: "n"(N) : "memory")

__global__ void fill_k(float* p, float v, int n) {
    int i = blockIdx.x * blockDim.x + threadIdx.x;
    if (i < n) p[i] = v;
}

__global__ void fill2f_k(float* p, float* q, int n) {
    int i = blockIdx.x * blockDim.x + threadIdx.x;
    if (i < n) { p[i] = 0.f; q[i] = 0.f; }
}

__global__ void fill2i_k(int* p, int* q, int n) {
    int i = blockIdx.x * blockDim.x + threadIdx.x;
    if (i < n) { p[i] = 0; q[i] = 0; }
}

// ---------------- weight pre-split: W [K][N] -> hi/lo [K/2][N] u32 ------------
__global__ void split_w_k(const float* __restrict__ W,
                          unsigned int* __restrict__ hi, unsigned int* __restrict__ lo,
                          int K, int N) {
    int j = blockIdx.x * blockDim.x + threadIdx.x;
    if (j >= (K / 2) * N) return;
    int k2 = j / N, nn = j - k2 * N;
    float v0 = W[(size_t)(2 * k2) * N + nn];
    float v1 = W[(size_t)(2 * k2 + 1) * N + nn];
    bf16split2(v0, v1, hi[j], lo[j]);
}

// ---------------- CSR construction --------------------------------------------
__global__ void deg_k(const int* __restrict__ dst, int* deg, int E, int et) {
    int e = blockIdx.x * blockDim.x + threadIdx.x;
    if (e >= et) return;
    int d = e < E ? dst[e] : e - E;
    atomicAdd(&deg[d], 1);
}

__global__ void scan_part_k(const int* __restrict__ deg, int* rowptr, int* blksum, int n) {
    __shared__ int sm[256];
    int i = blockIdx.x * 256 + threadIdx.x;
    int v = (i < n) ? deg[i] : 0;
    sm[threadIdx.x] = v;
    __syncthreads();
    for (int o = 1; o < 256; o <<= 1) {
        int t = (threadIdx.x >= o) ? sm[threadIdx.x - o] : 0;
        __syncthreads();
        sm[threadIdx.x] += t;
        __syncthreads();
    }
    if (i < n) rowptr[i] = sm[threadIdx.x] - v;      // exclusive
    if (threadIdx.x == 255) blksum[blockIdx.x] = sm[255];
}

__global__ void scan_tops_k(int* blksum, int nb) {
    __shared__ int sm[256];
    int v = (threadIdx.x < nb) ? blksum[threadIdx.x] : 0;
    sm[threadIdx.x] = v;
    __syncthreads();
    for (int o = 1; o < 256; o <<= 1) {
        int t = (threadIdx.x >= o) ? sm[threadIdx.x - o] : 0;
        __syncthreads();
        sm[threadIdx.x] += t;
        __syncthreads();
    }
    if (threadIdx.x < nb) blksum[threadIdx.x] = sm[threadIdx.x] - v;   // exclusive
}

__global__ void scan_write_k(int* rowptr, const int* __restrict__ blksum, int n) {
    int i = blockIdx.x * 256 + threadIdx.x;
    if (i < n) rowptr[i] += blksum[blockIdx.x];
    if (i == 0) rowptr[n] = ET_EDGES;
}

__global__ void fill_pos_k(const int* __restrict__ src, const int* __restrict__ dst,
                           const int* __restrict__ rowptr,
                           int* cursor, int* csrc, int E, int et) {
    int e = blockIdx.x * blockDim.x + threadIdx.x;
    if (e >= et) return;
    int s, d;
    if (e < E) { s = src[e]; d = dst[e]; } else { s = d = e - E; }
    int p = atomicAdd(&cursor[d], 1);
    csrc[rowptr[d] + p] = s;
}

// ---------------- fused GEMM: [BN+ELU] + bf16-split on A-fill + attn epilogue -
// C = f(A) @ B where f = identity (DOBN=0) or ELU(A*scl+sft) (DOBN=1).
// A is raw fp32 [M][K]; split to bf16 hi/lo during the smem fill.
// B pre-split ([K/2][N] u32 hi/lo). acc += ah*bl + al*bh + ah*bh.
// Epilogue: C store + a_s/a_d attention coefficients via spread atomics.
// Smem (u32): AH(st)=st*5952, AL=+2560 (128 x 20), BH=11904+st*2304, BL=+1152.
// Actually AH stage stride: (2560+2560) u32? laid out below. Dyn smem = 59392 B.
template <int DOBN>
__global__ __launch_bounds__(256, 3) void gemm_fused_k(
    const float* __restrict__ A,
    const unsigned int* __restrict__ Bh2, const unsigned int* __restrict__ Bl2,
    float* __restrict__ C, int M, int N, int K,
    const float* __restrict__ scl, const float* __restrict__ sft,
    const float* __restrict__ attn_s, const float* __restrict__ attn_d,
    float* __restrict__ as_o, float* __restrict__ ad_o)
{
    extern __shared__ unsigned int smem[];
    unsigned int sbase = (unsigned int)__cvta_generic_to_shared(smem);

    int tid = threadIdx.x;
    int warp = tid >> 5, lane = tid & 31;
    int wm = (warp & 3) * 32;
    int wn = (warp >> 2) * 32;
    int rowBase = blockIdx.y * 128;
    int colBase = blockIdx.x * 64;
    int mrow = lane >> 2;           // 0..7
    int kc   = lane & 3;            // 0..3
    int K4 = K >> 2;

    // B prefetch (cp.async, double-buffered)
#define PREFETCH_B(IT, ST)                                                         \
    do {                                                                           \
        int k2b = (IT) * 16;                                                       \
        int r = tid >> 4, c4 = (tid & 15) * 4;                                     \
        unsigned int off = (10240 + (ST) * 2304 + r * 72 + c4) * 4;                \
        cpasync16(sbase + off, &Bh2[(size_t)(k2b + r) * N + colBase + c4], true);  \
        cpasync16(sbase + off + 1152 * 4, &Bl2[(size_t)(k2b + r) * N + colBase + c4], true); \
        CP_COMMIT();                                                               \
    } while (0)

    float acc[2][4][4];
#pragma unroll
    for (int mi = 0; mi < 2; mi++)
#pragma unroll
        for (int ni = 0; ni < 4; ni++)
#pragma unroll
            for (int r = 0; r < 4; r++) acc[mi][ni][r] = 0.f;

    int niter = K >> 5;
    PREFETCH_B(0, 0);

    for (int it = 0; it < niter; it++) {
        int st = it & 1;
        // ---- A fill: load fp32, [BN+ELU], bf16-split, STS (stage st) ----
        {
            unsigned int* AsH = smem + st * 5120;     // [128][20]
            unsigned int* AsL = AsH + 2560;
#pragma unroll
            for (int i = 0; i < 4; i++) {
                int f4 = tid + i * 256;
                int r = f4 >> 3, cf = (f4 & 7) * 4;   // fp32 col within BK=32
                int gr = rowBase + r;
                float4 v = make_float4(0.f, 0.f, 0.f, 0.f);
                if (gr < M) v = ((const float4*)A)[(size_t)gr * K4 + it * 8 + (f4 & 7)];
                if (DOBN) {
                    int ch = it * 32 + cf;
                    float4 s4 = *(const float4*)&scl[ch];
                    float4 t4 = *(const float4*)&sft[ch];
                    v.x = v.x * s4.x + t4.x;
                    v.y = v.y * s4.y + t4.y;
                    v.z = v.z * s4.z + t4.z;
                    v.w = v.w * s4.w + t4.w;
                    v.x = v.x > 0.f ? v.x : __expf(v.x) - 1.f;
                    v.y = v.y > 0.f ? v.y : __expf(v.y) - 1.f;
                    v.z = v.z > 0.f ? v.z : __expf(v.z) - 1.f;
                    v.w = v.w > 0.f ? v.w : __expf(v.w) - 1.f;
                }
                uint2 hi, lo;
                bf16split2(v.x, v.y, hi.x, lo.x);
                bf16split2(v.z, v.w, hi.y, lo.y);
                *(uint2*)&AsH[r * 20 + (cf >> 1)] = hi;
                *(uint2*)&AsL[r * 20 + (cf >> 1)] = lo;
            }
        }
        if (it + 1 < niter) {
            PREFETCH_B(it + 1, st ^ 1);
            CP_WAIT(1);
        } else {
            CP_WAIT(0);
        }
        __syncthreads();

        const unsigned int* AsH = smem + st * 5120;
        const unsigned int* AsL = AsH + 2560;
        const unsigned int* BsH = smem + 10240 + st * 2304;
        const unsigned int* BsL = BsH + 1152;

#pragma unroll
        for (int ks = 0; ks < 2; ks++) {
            unsigned int ah[2][4], al[2][4], bh[4][2], bl[4][2];
#pragma unroll
            for (int mi = 0; mi < 2; mi++) {
                int m = wm + mi * 16 + mrow;
                int i0 = m * 20 + ks * 8 + kc;
                ah[mi][0] = AsH[i0];            al[mi][0] = AsL[i0];
                ah[mi][1] = AsH[i0 + 160];      al[mi][1] = AsL[i0 + 160];   // row+8
                ah[mi][2] = AsH[i0 + 4];        al[mi][2] = AsL[i0 + 4];     // k+8
                ah[mi][3] = AsH[i0 + 164];      al[mi][3] = AsL[i0 + 164];
            }
#pragma unroll
            for (int ni = 0; ni < 4; ni++) {
                int ib = (ks * 8 + kc) * 72 + wn + ni * 8 + mrow;
                bh[ni][0] = BsH[ib];            bl[ni][0] = BsL[ib];
                bh[ni][1] = BsH[ib + 288];      bl[ni][1] = BsL[ib + 288];   // k+8
            }
#define MMA_B(ar, br, mi, ni)                                                     \
    asm volatile(                                                                 \
        "mma.sync.aligned.m16n8k16.row.col.f32.bf16.bf16.f32 "                    \
        "{%0,%1,%2,%3},{%4,%5,%6,%7},{%8,%9},{%0,%1,%2,%3};"                      \
        : "+f"(acc[mi][ni][0]), "+f"(acc[mi][ni][1]),                             \
          "+f"(acc[mi][ni][2]), "+f"(acc[mi][ni][3])                              \
        : "r"(ar[mi][0]), "r"(ar[mi][1]), "r"(ar[mi][2]), "r"(ar[mi][3]),         \
          "r"(br[ni][0]), "r"(br[ni][1]))
#pragma unroll
            for (int mi = 0; mi < 2; mi++)
#pragma unroll
                for (int ni = 0; ni < 4; ni++) {
                    MMA_B(ah, bl, mi, ni);
                    MMA_B(al, bh, mi, ni);
                    MMA_B(ah, bh, mi, ni);
                }
#undef MMA_B
        }
        __syncthreads();
    }
#undef PREFETCH_B

    // ---- epilogue: store C + fused attention coefficients ----
    int H = gridDim.x;
    int head = blockIdx.x;
    const float* av = attn_s + head * 64;
    const float* dv = attn_d + head * 64;
    float avv[8], dvv[8];
#pragma unroll
    for (int ni = 0; ni < 4; ni++)
#pragma unroll
        for (int j = 0; j < 2; j++) {
            int cc = wn + ni * 8 + kc * 2 + j;
            avv[ni * 2 + j] = __ldg(&av[cc]);
            dvv[ni * 2 + j] = __ldg(&dv[cc]);
        }

#pragma unroll
    for (int mi = 0; mi < 2; mi++) {
        int r0 = rowBase + wm + mi * 16 + mrow;
        float s0 = 0.f, d0 = 0.f, s1 = 0.f, d1 = 0.f;
#pragma unroll
        for (int ni = 0; ni < 4; ni++) {
            int c = colBase + wn + ni * 8 + kc * 2;
            if (r0 < M) {
                C[(size_t)r0 * N + c]     = acc[mi][ni][0];
                C[(size_t)r0 * N + c + 1] = acc[mi][ni][1];
            }
            if (r0 + 8 < M) {
                C[(size_t)(r0 + 8) * N + c]     = acc[mi][ni][2];
                C[(size_t)(r0 + 8) * N + c + 1] = acc[mi][ni][3];
            }
            s0 += acc[mi][ni][0] * avv[ni * 2] + acc[mi][ni][1] * avv[ni * 2 + 1];
            d0 += acc[mi][ni][0] * dvv[ni * 2] + acc[mi][ni][1] * dvv[ni * 2 + 1];
            s1 += acc[mi][ni][2] * avv[ni * 2] + acc[mi][ni][3] * avv[ni * 2 + 1];
            d1 += acc[mi][ni][2] * dvv[ni * 2] + acc[mi][ni][3] * dvv[ni * 2 + 1];
        }
#pragma unroll
        for (int o = 1; o < 4; o <<= 1) {
            s0 += __shfl_xor_sync(0xFFFFFFFFu, s0, o);
            d0 += __shfl_xor_sync(0xFFFFFFFFu, d0, o);
            s1 += __shfl_xor_sync(0xFFFFFFFFu, s1, o);
            d1 += __shfl_xor_sync(0xFFFFFFFFu, d1, o);
        }
        if (kc == 0) {
            if (r0 < M) {
                atomicAdd(&as_o[r0 * H + head], s0);
                atomicAdd(&ad_o[r0 * H + head], d0);
            }
            if (r0 + 8 < M) {
                atomicAdd(&as_o[(r0 + 8) * H + head], s1);
                atomicAdd(&ad_o[(r0 + 8) * H + head], d1);
            }
        }
    }
}

// ---------------- fused softmax + CSR aggregation (H=4), single pass ----------
__global__ void agg4_k(const int* __restrict__ rowptr, const int* __restrict__ csrc,
                       const float* __restrict__ h,
                       const float* __restrict__ asb, const float* __restrict__ adb,
                       float* __restrict__ out, int n)
{
    int w = (blockIdx.x * blockDim.x + threadIdx.x) >> 5;
    int lane = threadIdx.x & 31;
    if (w >= n) return;
    int beg = rowptr[w], end = rowptr[w + 1];

    int eh = lane & 3;
    float ad_h = adb[(size_t)w * 4 + eh];
    int hA = lane >> 4;        // head supplying channels [0,128): 0 or 1
    int hB = 2 + hA;           // head supplying channels [128,256): 2 or 3

    float4 acc0 = make_float4(0.f, 0.f, 0.f, 0.f);
    float4 acc1 = make_float4(0.f, 0.f, 0.f, 0.f);
    float den = 0.f;
    for (int j = beg; j < end; j++) {
        int s = __ldg(&csrc[j]);
        float e = asb[(size_t)s * 4 + eh] + ad_h;
        e = e > 0.f ? e : 0.2f * e;
        float ww = __expf(e);
        den += ww;
        float aA = __shfl_sync(0xFFFFFFFFu, ww, hA);
        float aB = __shfl_sync(0xFFFFFFFFu, ww, hB);
        const float4* hr = (const float4*)(h + (size_t)s * 256);
        float4 v0 = hr[lane];
        float4 v1 = hr[32 + lane];
        acc0.x += v0.x * aA; acc0.y += v0.y * aA; acc0.z += v0.z * aA; acc0.w += v0.w * aA;
        acc1.x += v1.x * aB; acc1.y += v1.y * aB; acc1.z += v1.z * aB; acc1.w += v1.w * aB;
    }
    float iA = 1.f / __shfl_sync(0xFFFFFFFFu, den, hA);
    float iB = 1.f / __shfl_sync(0xFFFFFFFFu, den, hB);
    acc0.x *= iA; acc0.y *= iA; acc0.z *= iA; acc0.w *= iA;
    acc1.x *= iB; acc1.y *= iB; acc1.z *= iB; acc1.w *= iB;
    float4* o4 = (float4*)(out + (size_t)w * 256);
    o4[lane] = acc0;
    o4[32 + lane] = acc1;
}

// ---- fused agg (H=1) + bias + classifier: out[n,2], no intermediate traffic --
__global__ void agg1_cls_k(const int* __restrict__ rowptr, const int* __restrict__ csrc,
                           const float* __restrict__ h,
                           const float* __restrict__ asb, const float* __restrict__ adb,
                           const float* __restrict__ bias,
                           const float* __restrict__ Wc1, const float* __restrict__ bc1,
                           const float* __restrict__ Wc2, const float* __restrict__ bc2,
                           float* __restrict__ out, int n)
{
    int w = (blockIdx.x * blockDim.x + threadIdx.x) >> 5;
    int lane = threadIdx.x & 31;
    if (w >= n) return;
    int beg = rowptr[w], end = rowptr[w + 1];
    float ad = adb[w];

    float den = 0.f;
    float4 acc = make_float4(0.f, 0.f, 0.f, 0.f);
    for (int j = beg; j < end; j++) {
        int s = __ldg(&csrc[j]);
        float e = asb[s] + ad;
        e = e > 0.f ? e : 0.2f * e;
        float ww = __expf(e);
        den += ww;
        if (lane < 16) {
            float4 v = ((const float4*)(h + (size_t)s * 64))[lane];
            acc.x += v.x * ww; acc.y += v.y * ww; acc.z += v.z * ww; acc.w += v.w * ww;
        }
    }
    if (lane < 16) {
        float inv = 1.f / den;
        float4 b4 = ((const float4*)bias)[lane];
        acc.x = acc.x * inv + b4.x; acc.y = acc.y * inv + b4.y;
        acc.z = acc.z * inv + b4.z; acc.w = acc.w * inv + b4.w;
    }
    // classifier: lane j owns hidden unit j; x channels broadcast from lanes 0-15
    float hj = __ldg(&bc1[lane]);
#pragma unroll
    for (int c = 0; c < 64; c++) {
        int q = c >> 2, t = c & 3;
        float src = t == 0 ? acc.x : (t == 1 ? acc.y : (t == 2 ? acc.z : acc.w));
        float xc = __shfl_sync(0xFFFFFFFFu, src, q);
        hj += xc * __ldg(&Wc1[c * 32 + lane]);
    }
    hj = fmaxf(hj, 0.f);
    float o0 = hj * __ldg(&Wc2[lane * 2 + 0]);
    float o1 = hj * __ldg(&Wc2[lane * 2 + 1]);
#pragma unroll
    for (int o = 16; o; o >>= 1) {
        o0 += __shfl_down_sync(0xFFFFFFFFu, o0, o);
        o1 += __shfl_down_sync(0xFFFFFFFFu, o1, o);
    }
    if (!lane) {
        out[(size_t)w * 2]     = o0 + __ldg(&bc2[0]);
        out[(size_t)w * 2 + 1] = o1 + __ldg(&bc2[1]);
    }
}

// ---------------- batch norm stats (C=256 channels) ---------------------------
__global__ void bn_stats_k(const float* __restrict__ x, int n, float* sum, float* sq) {
    int ch = threadIdx.x;
    float s = 0.f, s2 = 0.f;
    for (int r = blockIdx.x; r < n; r += gridDim.x) {
        float v = x[(size_t)r * HWID + ch];
        s += v; s2 += v * v;
    }
    atomicAdd(&sum[ch], s);
    atomicAdd(&sq[ch], s2);
}

__global__ void bn_fin_k(const float* sum, const float* sq,
                         const float* __restrict__ g, const float* __restrict__ be,
                         int n, float* scl, float* sft) {
    int ch = threadIdx.x;
    float mu = sum[ch] / (float)n;
    float var = fmaxf(sq[ch] / (float)n - mu * mu, 0.f);
    float r = rsqrtf(var + 1e-5f);
    float s = g[ch] * r;
    scl[ch] = s;
    sft[ch] = be[ch] - mu * s;
}

// ---------------- host-side orchestration -------------------------------------
#define GEMM_SMEM 59392

static void run_gemm(int dobn, const float* A,
                     const unsigned int* Bh, const unsigned int* Bl,
                     float* C, int M, int N, int K,
                     const float* scl, const float* sft,
                     const float* atts, const float* attd,
                     float* aso, float* ado) {
    dim3 grid(N / 64, (M + 127) / 128);
    if (dobn)
        gemm_fused_k<1><<<grid, 256, GEMM_SMEM>>>(A, Bh, Bl, C, M, N, K,
                                                  scl, sft, atts, attd, aso, ado);
    else
        gemm_fused_k<0><<<grid, 256, GEMM_SMEM>>>(A, Bh, Bl, C, M, N, K,
                                                  scl, sft, atts, attd, aso, ado);
}

extern "C" void kernel_launch(void* const* d_in, const int* in_sizes, int n_in,
                              void* d_out, int out_size)
{
    const float* x   = (const float*)d_in[0];
    const int*   ei  = (const int*)  d_in[1];
    const float* W0  = (const float*)d_in[2];
    const float* as0 = (const float*)d_in[3];
    const float* ad0 = (const float*)d_in[4];
    // b0 (d_in[5]) cancels through BatchNorm — skipped
    const float* W1  = (const float*)d_in[6];
    const float* as1 = (const float*)d_in[7];
    const float* ad1 = (const float*)d_in[8];
    // b1 (d_in[9]) cancels through BatchNorm — skipped
    const float* W2  = (const float*)d_in[10];
    const float* as2 = (const float*)d_in[11];
    const float* ad2 = (const float*)d_in[12];
    const float* b2  = (const float*)d_in[13];
    const float* g0  = (const float*)d_in[14];
    const float* be0 = (const float*)d_in[15];
    const float* g1  = (const float*)d_in[16];
    const float* be1 = (const float*)d_in[17];
    const float* Wc1 = (const float*)d_in[18];
    const float* bc1 = (const float*)d_in[19];
    const float* Wc2 = (const float*)d_in[20];
    const float* bc2 = (const float*)d_in[21];
    float* out = (float*)d_out;

    const int n = N_NODES;
    const int* src = ei;
    const int* dst = ei + N_EDGES;

    static int smem_cfg_done = 0;
    if (!smem_cfg_done) {
        cudaFuncSetAttribute(gemm_fused_k<0>,
                             cudaFuncAttributeMaxDynamicSharedMemorySize, GEMM_SMEM);
        cudaFuncSetAttribute(gemm_fused_k<1>,
                             cudaFuncAttributeMaxDynamicSharedMemorySize, GEMM_SMEM);
        smem_cfg_done = 1;
    }

    float *hbuf, *aggbuf, *asb, *adb;
    float *sumb, *sqb, *sclb, *sftb;
    unsigned int *w0h, *w0l, *w1h, *w1l, *w2h, *w2l;
    int *degb, *curb, *rowb, *csrcb, *blkb;
    cudaGetSymbolAddress((void**)&hbuf,  g_h);
    cudaGetSymbolAddress((void**)&aggbuf, g_agg);
    cudaGetSymbolAddress((void**)&asb,   g_as);
    cudaGetSymbolAddress((void**)&adb,   g_ad);
    cudaGetSymbolAddress((void**)&sumb,  g_sum);
    cudaGetSymbolAddress((void**)&sqb,   g_sq);
    cudaGetSymbolAddress((void**)&sclb,  g_scl);
    cudaGetSymbolAddress((void**)&sftb,  g_sft);
    cudaGetSymbolAddress((void**)&w0h,   g_w0h);
    cudaGetSymbolAddress((void**)&w0l,   g_w0l);
    cudaGetSymbolAddress((void**)&w1h,   g_w1h);
    cudaGetSymbolAddress((void**)&w1l,   g_w1l);
    cudaGetSymbolAddress((void**)&w2h,   g_w2h);
    cudaGetSymbolAddress((void**)&w2l,   g_w2l);
    cudaGetSymbolAddress((void**)&degb,  g_deg);
    cudaGetSymbolAddress((void**)&curb,  g_cursor);
    cudaGetSymbolAddress((void**)&rowb,  g_rowptr);
    cudaGetSymbolAddress((void**)&csrcb, g_csrc);
    cudaGetSymbolAddress((void**)&blkb,  g_blksum);

    // ---- prologue; GEMM is our 4th launch (ncu window) ----
    split_w_k<<<(64 * 256 + 255) / 256, 256>>>(W0, w0h, w0l, 128, 256);
    fill2f_k<<<(n * 4 + 255) / 256, 256>>>(asb, adb, n * 4);
    fill2i_k<<<(n + 255) / 256, 256>>>(degb, curb, n);

    // ---- GAT layer 0 GEMM + attn: 128 -> 4x64 (A = x, no BN) ----
    run_gemm(0, x, w0h, w0l, hbuf, n, 256, 128, nullptr, nullptr,
             as0, ad0, asb, adb);

    // ---- CSR build + remaining weight splits ----
    deg_k<<<(ET_EDGES + 255) / 256, 256>>>(dst, degb, N_EDGES, ET_EDGES);
    scan_part_k<<<NBLK_SCAN, 256>>>(degb, rowb, blkb, n);
    scan_tops_k<<<1, 256>>>(blkb, NBLK_SCAN);
    scan_write_k<<<NBLK_SCAN, 256>>>(rowb, blkb, n);
    fill_pos_k<<<(ET_EDGES + 255) / 256, 256>>>(src, dst, rowb, curb, csrcb,
                                                N_EDGES, ET_EDGES);
    split_w_k<<<(128 * 256 + 255) / 256, 256>>>(W1, w1h, w1l, 256, 256);
    split_w_k<<<(128 * 64 + 255) / 256, 256>>>(W2, w2h, w2l, 256, 64);

    int aggBlocks = (n * 32 + 255) / 256;

    // ---- GAT layer 0 aggregation + BN stats ----
    agg4_k<<<aggBlocks, 256>>>(rowb, csrcb, hbuf, asb, adb, aggbuf, n);
    fill2f_k<<<1, 256>>>(sumb, sqb, HWID);
    bn_stats_k<<<512, 256>>>(aggbuf, n, sumb, sqb);
    bn_fin_k<<<1, 256>>>(sumb, sqb, g0, be0, n, sclb, sftb);

    // ---- GAT layer 1: BN+ELU fused into GEMM A-path ----
    fill2f_k<<<(n * 4 + 255) / 256, 256>>>(asb, adb, n * 4);
    run_gemm(1, aggbuf, w1h, w1l, hbuf, n, 256, 256, sclb, sftb,
             as1, ad1, asb, adb);
    agg4_k<<<aggBlocks, 256>>>(rowb, csrcb, hbuf, asb, adb, aggbuf, n);
    fill2f_k<<<1, 256>>>(sumb, sqb, HWID);
    bn_stats_k<<<512, 256>>>(aggbuf, n, sumb, sqb);
    bn_fin_k<<<1, 256>>>(sumb, sqb, g1, be1, n, sclb, sftb);

    // ---- GAT layer 2: BN+ELU fused into GEMM A-path; 256 -> 1x64 ----
    fill2f_k<<<(n + 255) / 256, 256>>>(asb, adb, n);
    run_gemm(1, aggbuf, w2h, w2l, hbuf, n, 64, 256, sclb, sftb,
             as2, ad2, asb, adb);

    // ---- agg1 + bias + classifier fused ----
    agg1_cls_k<<<aggBlocks, 256>>>(rowb, csrcb, hbuf, asb, adb, b2,
                                   Wc1, bc1, Wc2, bc2, out, n);
}

// round 14
// speedup vs baseline: 1.4335x; 1.0185x over previous
#include <cuda_runtime.h>
#include <cuda_bf16.h>
#include <math.h>

// Problem constants (fixed by the dataset)
#define N_NODES 50000
#define N_EDGES 800000
#define ET_EDGES (N_NODES + N_EDGES)   // edges + self loops
#define HWID 256                        // heads*hid for layers 0/1
#define CDIM 64
#define NBLK_SCAN ((N_NODES + 255) / 256)   // 196

// ---------------- scratch (device globals; no allocation allowed) -------------
static __device__ float g_h   [(size_t)N_NODES * HWID];
static __device__ float g_agg [(size_t)N_NODES * HWID];
static __device__ float g_as  [N_NODES * 4];
static __device__ float g_ad  [N_NODES * 4];
static __device__ float g_sum [HWID];
static __device__ float g_sq  [HWID];
static __device__ float g_scl [HWID];
static __device__ float g_sft [HWID];
// bf16 hi/lo packed weights ([K/2][N] u32)
static __device__ unsigned int g_w0h[64 * 256],  g_w0l[64 * 256];
static __device__ unsigned int g_w1h[128 * 256], g_w1l[128 * 256];
static __device__ unsigned int g_w2h[128 * 64],  g_w2l[128 * 64];
// CSR scratch
static __device__ int g_deg   [N_NODES];
static __device__ int g_cursor[N_NODES];
static __device__ int g_rowptr[N_NODES + 1];
static __device__ int g_csrc  [ET_EDGES];      // src node per CSR slot
static __device__ int g_blksum[256];

// ---------------- helpers -----------------------------------------------------
// split two fp32 into packed bf16x2 hi + bf16x2 lo (lower k in low 16 bits)
__device__ __forceinline__ void bf16split2(float v0, float v1,
                                           unsigned int& hi, unsigned int& lo) {
    __nv_bfloat16 h0 = __float2bfloat16(v0), h1 = __float2bfloat16(v1);
    float r0 = v0 - __bfloat162float(h0);
    float r1 = v1 - __bfloat162float(h1);
    __nv_bfloat16 l0 = __float2bfloat16(r0), l1 = __float2bfloat16(r1);
    hi = ((unsigned int)__bfloat16_as_ushort(h1) << 16) | __bfloat16_as_ushort(h0);
    lo = ((unsigned int)__bfloat16_as_ushort(l1) << 16) | __bfloat16_as_ushort(l0);
}

__device__ __forceinline__ void cpasync16(unsigned int dst, const void* src, bool pred) {
    int sz = pred ? 16 : 0;
    asm volatile("cp.async.cg.shared.global [%0], [%1], 16, %2;"
                 :: "r"(dst), "l"(src), "r"(sz) : "memory");
}
#define CP_COMMIT() asm volatile("cp.async.commit_group;" ::: "memory")
#define CP_WAIT(N)  asm volatile("cp.async.wait_group %0;" :: "n"(N) : "memory")

__global__ void fill2f_k(float* p, float* q, int n) {
    int i = blockIdx.x * blockDim.x + threadIdx.x;
    if (i < n) { p[i] = 0.f; q[i] = 0.f; }
}

__global__ void fill2i_k(int* p, int* q, int n) {
    int i = blockIdx.x * blockDim.x + threadIdx.x;
    if (i < n) { p[i] = 0; q[i] = 0; }
}

// ---------------- weight pre-split: W [K][N] -> hi/lo [K/2][N] u32 ------------
__global__ void split_w_k(const float* __restrict__ W,
                          unsigned int* __restrict__ hi, unsigned int* __restrict__ lo,
                          int K, int N) {
    int j = blockIdx.x * blockDim.x + threadIdx.x;
    if (j >= (K / 2) * N) return;
    int k2 = j / N, nn = j - k2 * N;
    float v0 = W[(size_t)(2 * k2) * N + nn];
    float v1 = W[(size_t)(2 * k2 + 1) * N + nn];
    bf16split2(v0, v1, hi[j], lo[j]);
}

// ---------------- CSR construction --------------------------------------------
__global__ void deg_k(const int* __restrict__ dst, int* deg, int E, int et) {
    int e = blockIdx.x * blockDim.x + threadIdx.x;
    if (e >= et) return;
    int d = e < E ? dst[e] : e - E;
    atomicAdd(&deg[d], 1);
}

__global__ void scan_part_k(const int* __restrict__ deg, int* rowptr, int* blksum, int n) {
    __shared__ int sm[256];
    int i = blockIdx.x * 256 + threadIdx.x;
    int v = (i < n) ? deg[i] : 0;
    sm[threadIdx.x] = v;
    __syncthreads();
    for (int o = 1; o < 256; o <<= 1) {
        int t = (threadIdx.x >= o) ? sm[threadIdx.x - o] : 0;
        __syncthreads();
        sm[threadIdx.x] += t;
        __syncthreads();
    }
    if (i < n) rowptr[i] = sm[threadIdx.x] - v;      // exclusive
    if (threadIdx.x == 255) blksum[blockIdx.x] = sm[255];
}

__global__ void scan_tops_k(int* blksum, int nb) {
    __shared__ int sm[256];
    int v = (threadIdx.x < nb) ? blksum[threadIdx.x] : 0;
    sm[threadIdx.x] = v;
    __syncthreads();
    for (int o = 1; o < 256; o <<= 1) {
        int t = (threadIdx.x >= o) ? sm[threadIdx.x - o] : 0;
        __syncthreads();
        sm[threadIdx.x] += t;
        __syncthreads();
    }
    if (threadIdx.x < nb) blksum[threadIdx.x] = sm[threadIdx.x] - v;   // exclusive
}

__global__ void scan_write_k(int* rowptr, const int* __restrict__ blksum, int n) {
    int i = blockIdx.x * 256 + threadIdx.x;
    if (i < n) rowptr[i] += blksum[blockIdx.x];
    if (i == 0) rowptr[n] = ET_EDGES;
}

__global__ void fill_pos_k(const int* __restrict__ src, const int* __restrict__ dst,
                           const int* __restrict__ rowptr,
                           int* cursor, int* csrc, int E, int et) {
    int e = blockIdx.x * blockDim.x + threadIdx.x;
    if (e >= et) return;
    int s, d;
    if (e < E) { s = src[e]; d = dst[e]; } else { s = d = e - E; }
    int p = atomicAdd(&cursor[d], 1);
    csrc[rowptr[d] + p] = s;
}

// ---------------- fused GEMM: [BN+ELU] + bf16-split on A-fill + attn epilogue -
// C = f(A) @ B where f = identity (DOBN=0) or ELU(A*scl+sft) (DOBN=1).
// A: raw fp32 [M][K], split to bf16 hi/lo during the smem fill (single stage —
// the loop's two syncthreads make double-buffering A useless; smaller smem
// grows the L1D carveout for the A LDG path).
// B: pre-split [K/2][N] u32 hi/lo, double-buffered cp.async, issued BEFORE the
// A fill so its latency hides behind A's synchronous LDG+split.
// acc += ah*bl + al*bh + ah*bh. Epilogue: C store + a_s/a_d via spread atomics.
// Smem (u32): AH=0 (128x20), AL=+2560; BH=5120+st*2304, BL=+1152.
// Dyn smem = 38912 B. Requires K%32==0, N%64==0.
template <int DOBN>
__global__ __launch_bounds__(256, 3) void gemm_fused_k(
    const float* __restrict__ A,
    const unsigned int* __restrict__ Bh2, const unsigned int* __restrict__ Bl2,
    float* __restrict__ C, int M, int N, int K,
    const float* __restrict__ scl, const float* __restrict__ sft,
    const float* __restrict__ attn_s, const float* __restrict__ attn_d,
    float* __restrict__ as_o, float* __restrict__ ad_o)
{
    extern __shared__ unsigned int smem[];
    unsigned int sbase = (unsigned int)__cvta_generic_to_shared(smem);

    int tid = threadIdx.x;
    int warp = tid >> 5, lane = tid & 31;
    int wm = (warp & 3) * 32;
    int wn = (warp >> 2) * 32;
    int rowBase = blockIdx.y * 128;
    int colBase = blockIdx.x * 64;
    int mrow = lane >> 2;           // 0..7
    int kc   = lane & 3;            // 0..3
    int K4 = K >> 2;

#define PREFETCH_B(IT, ST)                                                         \
    do {                                                                           \
        int k2b = (IT) * 16;                                                       \
        int r = tid >> 4, c4 = (tid & 15) * 4;                                     \
        unsigned int off = (5120 + (ST) * 2304 + r * 72 + c4) * 4;                 \
        cpasync16(sbase + off, &Bh2[(size_t)(k2b + r) * N + colBase + c4], true);  \
        cpasync16(sbase + off + 1152 * 4, &Bl2[(size_t)(k2b + r) * N + colBase + c4], true); \
        CP_COMMIT();                                                               \
    } while (0)

    float acc[2][4][4];
#pragma unroll
    for (int mi = 0; mi < 2; mi++)
#pragma unroll
        for (int ni = 0; ni < 4; ni++)
#pragma unroll
            for (int r = 0; r < 4; r++) acc[mi][ni][r] = 0.f;

    int niter = K >> 5;
    PREFETCH_B(0, 0);

    for (int it = 0; it < niter; it++) {
        int st = it & 1;
        // B prefetch for next iter first: overlaps the synchronous A fill below
        if (it + 1 < niter) PREFETCH_B(it + 1, st ^ 1);

        // ---- A fill (single stage): load fp32, [BN+ELU], bf16-split, STS ----
        {
            unsigned int* AsH = smem;               // [128][20]
            unsigned int* AsL = smem + 2560;
#pragma unroll
            for (int i = 0; i < 4; i++) {
                int f4 = tid + i * 256;
                int r = f4 >> 3, cf = (f4 & 7) * 4;   // fp32 col within BK=32
                int gr = rowBase + r;
                float4 v = make_float4(0.f, 0.f, 0.f, 0.f);
                if (gr < M) v = ((const float4*)A)[(size_t)gr * K4 + it * 8 + (f4 & 7)];
                if (DOBN) {
                    int ch = it * 32 + cf;
                    float4 s4 = *(const float4*)&scl[ch];
                    float4 t4 = *(const float4*)&sft[ch];
                    v.x = v.x * s4.x + t4.x;
                    v.y = v.y * s4.y + t4.y;
                    v.z = v.z * s4.z + t4.z;
                    v.w = v.w * s4.w + t4.w;
                    v.x = v.x > 0.f ? v.x : __expf(v.x) - 1.f;
                    v.y = v.y > 0.f ? v.y : __expf(v.y) - 1.f;
                    v.z = v.z > 0.f ? v.z : __expf(v.z) - 1.f;
                    v.w = v.w > 0.f ? v.w : __expf(v.w) - 1.f;
                }
                uint2 hi, lo;
                bf16split2(v.x, v.y, hi.x, lo.x);
                bf16split2(v.z, v.w, hi.y, lo.y);
                *(uint2*)&AsH[r * 20 + (cf >> 1)] = hi;
                *(uint2*)&AsL[r * 20 + (cf >> 1)] = lo;
            }
        }
        if (it + 1 < niter) CP_WAIT(1); else CP_WAIT(0);
        __syncthreads();

        const unsigned int* AsH = smem;
        const unsigned int* AsL = smem + 2560;
        const unsigned int* BsH = smem + 5120 + st * 2304;
        const unsigned int* BsL = BsH + 1152;

#pragma unroll
        for (int ks = 0; ks < 2; ks++) {
            unsigned int ah[2][4], al[2][4], bh[4][2], bl[4][2];
#pragma unroll
            for (int mi = 0; mi < 2; mi++) {
                int m = wm + mi * 16 + mrow;
                int i0 = m * 20 + ks * 8 + kc;
                ah[mi][0] = AsH[i0];            al[mi][0] = AsL[i0];
                ah[mi][1] = AsH[i0 + 160];      al[mi][1] = AsL[i0 + 160];   // row+8
                ah[mi][2] = AsH[i0 + 4];        al[mi][2] = AsL[i0 + 4];     // k+8
                ah[mi][3] = AsH[i0 + 164];      al[mi][3] = AsL[i0 + 164];
            }
#pragma unroll
            for (int ni = 0; ni < 4; ni++) {
                int ib = (ks * 8 + kc) * 72 + wn + ni * 8 + mrow;
                bh[ni][0] = BsH[ib];            bl[ni][0] = BsL[ib];
                bh[ni][1] = BsH[ib + 288];      bl[ni][1] = BsL[ib + 288];   // k+8
            }
#define MMA_B(ar, br, mi, ni)                                                     \
    asm volatile(                                                                 \
        "mma.sync.aligned.m16n8k16.row.col.f32.bf16.bf16.f32 "                    \
        "{%0,%1,%2,%3},{%4,%5,%6,%7},{%8,%9},{%0,%1,%2,%3};"                      \
        : "+f"(acc[mi][ni][0]), "+f"(acc[mi][ni][1]),                             \
          "+f"(acc[mi][ni][2]), "+f"(acc[mi][ni][3])                              \
        : "r"(ar[mi][0]), "r"(ar[mi][1]), "r"(ar[mi][2]), "r"(ar[mi][3]),         \
          "r"(br[ni][0]), "r"(br[ni][1]))
#pragma unroll
            for (int mi = 0; mi < 2; mi++)
#pragma unroll
                for (int ni = 0; ni < 4; ni++) {
                    MMA_B(ah, bl, mi, ni);
                    MMA_B(al, bh, mi, ni);
                    MMA_B(ah, bh, mi, ni);
                }
#undef MMA_B
        }
        __syncthreads();
    }
#undef PREFETCH_B

    // ---- epilogue: store C + fused attention coefficients ----
    int H = gridDim.x;
    int head = blockIdx.x;
    const float* av = attn_s + head * 64;
    const float* dv = attn_d + head * 64;
    float avv[8], dvv[8];
#pragma unroll
    for (int ni = 0; ni < 4; ni++)
#pragma unroll
        for (int j = 0; j < 2; j++) {
            int cc = wn + ni * 8 + kc * 2 + j;
            avv[ni * 2 + j] = __ldg(&av[cc]);
            dvv[ni * 2 + j] = __ldg(&dv[cc]);
        }

#pragma unroll
    for (int mi = 0; mi < 2; mi++) {
        int r0 = rowBase + wm + mi * 16 + mrow;
        float s0 = 0.f, d0 = 0.f, s1 = 0.f, d1 = 0.f;
#pragma unroll
        for (int ni = 0; ni < 4; ni++) {
            int c = colBase + wn + ni * 8 + kc * 2;
            if (r0 < M) {
                C[(size_t)r0 * N + c]     = acc[mi][ni][0];
                C[(size_t)r0 * N + c + 1] = acc[mi][ni][1];
            }
            if (r0 + 8 < M) {
                C[(size_t)(r0 + 8) * N + c]     = acc[mi][ni][2];
                C[(size_t)(r0 + 8) * N + c + 1] = acc[mi][ni][3];
            }
            s0 += acc[mi][ni][0] * avv[ni * 2] + acc[mi][ni][1] * avv[ni * 2 + 1];
            d0 += acc[mi][ni][0] * dvv[ni * 2] + acc[mi][ni][1] * dvv[ni * 2 + 1];
            s1 += acc[mi][ni][2] * avv[ni * 2] + acc[mi][ni][3] * avv[ni * 2 + 1];
            d1 += acc[mi][ni][2] * dvv[ni * 2] + acc[mi][ni][3] * dvv[ni * 2 + 1];
        }
#pragma unroll
        for (int o = 1; o < 4; o <<= 1) {
            s0 += __shfl_xor_sync(0xFFFFFFFFu, s0, o);
            d0 += __shfl_xor_sync(0xFFFFFFFFu, d0, o);
            s1 += __shfl_xor_sync(0xFFFFFFFFu, s1, o);
            d1 += __shfl_xor_sync(0xFFFFFFFFu, d1, o);
        }
        if (kc == 0) {
            if (r0 < M) {
                atomicAdd(&as_o[r0 * H + head], s0);
                atomicAdd(&ad_o[r0 * H + head], d0);
            }
            if (r0 + 8 < M) {
                atomicAdd(&as_o[(r0 + 8) * H + head], s1);
                atomicAdd(&ad_o[(r0 + 8) * H + head], d1);
            }
        }
    }
}

// ---------------- fused softmax + CSR aggregation (H=4), single pass ----------
__global__ void agg4_k(const int* __restrict__ rowptr, const int* __restrict__ csrc,
                       const float* __restrict__ h,
                       const float* __restrict__ asb, const float* __restrict__ adb,
                       float* __restrict__ out, int n)
{
    int w = (blockIdx.x * blockDim.x + threadIdx.x) >> 5;
    int lane = threadIdx.x & 31;
    if (w >= n) return;
    int beg = rowptr[w], end = rowptr[w + 1];

    int eh = lane & 3;
    float ad_h = adb[(size_t)w * 4 + eh];
    int hA = lane >> 4;        // head supplying channels [0,128): 0 or 1
    int hB = 2 + hA;           // head supplying channels [128,256): 2 or 3

    float4 acc0 = make_float4(0.f, 0.f, 0.f, 0.f);
    float4 acc1 = make_float4(0.f, 0.f, 0.f, 0.f);
    float den = 0.f;
    for (int j = beg; j < end; j++) {
        int s = __ldg(&csrc[j]);
        float e = asb[(size_t)s * 4 + eh] + ad_h;
        e = e > 0.f ? e : 0.2f * e;
        float ww = __expf(e);
        den += ww;
        float aA = __shfl_sync(0xFFFFFFFFu, ww, hA);
        float aB = __shfl_sync(0xFFFFFFFFu, ww, hB);
        const float4* hr = (const float4*)(h + (size_t)s * 256);
        float4 v0 = hr[lane];
        float4 v1 = hr[32 + lane];
        acc0.x += v0.x * aA; acc0.y += v0.y * aA; acc0.z += v0.z * aA; acc0.w += v0.w * aA;
        acc1.x += v1.x * aB; acc1.y += v1.y * aB; acc1.z += v1.z * aB; acc1.w += v1.w * aB;
    }
    float iA = 1.f / __shfl_sync(0xFFFFFFFFu, den, hA);
    float iB = 1.f / __shfl_sync(0xFFFFFFFFu, den, hB);
    acc0.x *= iA; acc0.y *= iA; acc0.z *= iA; acc0.w *= iA;
    acc1.x *= iB; acc1.y *= iB; acc1.z *= iB; acc1.w *= iB;
    float4* o4 = (float4*)(out + (size_t)w * 256);
    o4[lane] = acc0;
    o4[32 + lane] = acc1;
}

// ---- fused agg (H=1) + bias + classifier: out[n,2], no intermediate traffic --
__global__ void agg1_cls_k(const int* __restrict__ rowptr, const int* __restrict__ csrc,
                           const float* __restrict__ h,
                           const float* __restrict__ asb, const float* __restrict__ adb,
                           const float* __restrict__ bias,
                           const float* __restrict__ Wc1, const float* __restrict__ bc1,
                           const float* __restrict__ Wc2, const float* __restrict__ bc2,
                           float* __restrict__ out, int n)
{
    int w = (blockIdx.x * blockDim.x + threadIdx.x) >> 5;
    int lane = threadIdx.x & 31;
    if (w >= n) return;
    int beg = rowptr[w], end = rowptr[w + 1];
    float ad = adb[w];

    float den = 0.f;
    float4 acc = make_float4(0.f, 0.f, 0.f, 0.f);
    for (int j = beg; j < end; j++) {
        int s = __ldg(&csrc[j]);
        float e = asb[s] + ad;
        e = e > 0.f ? e : 0.2f * e;
        float ww = __expf(e);
        den += ww;
        if (lane < 16) {
            float4 v = ((const float4*)(h + (size_t)s * 64))[lane];
            acc.x += v.x * ww; acc.y += v.y * ww; acc.z += v.z * ww; acc.w += v.w * ww;
        }
    }
    if (lane < 16) {
        float inv = 1.f / den;
        float4 b4 = ((const float4*)bias)[lane];
        acc.x = acc.x * inv + b4.x; acc.y = acc.y * inv + b4.y;
        acc.z = acc.z * inv + b4.z; acc.w = acc.w * inv + b4.w;
    }
    // classifier: lane j owns hidden unit j; x channels broadcast from lanes 0-15
    float hj = __ldg(&bc1[lane]);
#pragma unroll
    for (int c = 0; c < 64; c++) {
        int q = c >> 2, t = c & 3;
        float src = t == 0 ? acc.x : (t == 1 ? acc.y : (t == 2 ? acc.z : acc.w));
        float xc = __shfl_sync(0xFFFFFFFFu, src, q);
        hj += xc * __ldg(&Wc1[c * 32 + lane]);
    }
    hj = fmaxf(hj, 0.f);
    float o0 = hj * __ldg(&Wc2[lane * 2 + 0]);
    float o1 = hj * __ldg(&Wc2[lane * 2 + 1]);
#pragma unroll
    for (int o = 16; o; o >>= 1) {
        o0 += __shfl_down_sync(0xFFFFFFFFu, o0, o);
        o1 += __shfl_down_sync(0xFFFFFFFFu, o1, o);
    }
    if (!lane) {
        out[(size_t)w * 2]     = o0 + __ldg(&bc2[0]);
        out[(size_t)w * 2 + 1] = o1 + __ldg(&bc2[1]);
    }
}

// ---------------- batch norm stats (C=256 channels) ---------------------------
__global__ void bn_stats_k(const float* __restrict__ x, int n, float* sum, float* sq) {
    int ch = threadIdx.x;
    float s = 0.f, s2 = 0.f;
    for (int r = blockIdx.x; r < n; r += gridDim.x) {
        float v = x[(size_t)r * HWID + ch];
        s += v; s2 += v * v;
    }
    atomicAdd(&sum[ch], s);
    atomicAdd(&sq[ch], s2);
}

__global__ void bn_fin_k(const float* sum, const float* sq,
                         const float* __restrict__ g, const float* __restrict__ be,
                         int n, float* scl, float* sft) {
    int ch = threadIdx.x;
    float mu = sum[ch] / (float)n;
    float var = fmaxf(sq[ch] / (float)n - mu * mu, 0.f);
    float r = rsqrtf(var + 1e-5f);
    float s = g[ch] * r;
    scl[ch] = s;
    sft[ch] = be[ch] - mu * s;
}

// ---------------- host-side orchestration -------------------------------------
#define GEMM_SMEM 38912

static void run_gemm(int dobn, const float* A,
                     const unsigned int* Bh, const unsigned int* Bl,
                     float* C, int M, int N, int K,
                     const float* scl, const float* sft,
                     const float* atts, const float* attd,
                     float* aso, float* ado) {
    dim3 grid(N / 64, (M + 127) / 128);
    if (dobn)
        gemm_fused_k<1><<<grid, 256, GEMM_SMEM>>>(A, Bh, Bl, C, M, N, K,
                                                  scl, sft, atts, attd, aso, ado);
    else
        gemm_fused_k<0><<<grid, 256, GEMM_SMEM>>>(A, Bh, Bl, C, M, N, K,
                                                  scl, sft, atts, attd, aso, ado);
}

extern "C" void kernel_launch(void* const* d_in, const int* in_sizes, int n_in,
                              void* d_out, int out_size)
{
    const float* x   = (const float*)d_in[0];
    const int*   ei  = (const int*)  d_in[1];
    const float* W0  = (const float*)d_in[2];
    const float* as0 = (const float*)d_in[3];
    const float* ad0 = (const float*)d_in[4];
    // b0 (d_in[5]) cancels through BatchNorm — skipped
    const float* W1  = (const float*)d_in[6];
    const float* as1 = (const float*)d_in[7];
    const float* ad1 = (const float*)d_in[8];
    // b1 (d_in[9]) cancels through BatchNorm — skipped
    const float* W2  = (const float*)d_in[10];
    const float* as2 = (const float*)d_in[11];
    const float* ad2 = (const float*)d_in[12];
    const float* b2  = (const float*)d_in[13];
    const float* g0  = (const float*)d_in[14];
    const float* be0 = (const float*)d_in[15];
    const float* g1  = (const float*)d_in[16];
    const float* be1 = (const float*)d_in[17];
    const float* Wc1 = (const float*)d_in[18];
    const float* bc1 = (const float*)d_in[19];
    const float* Wc2 = (const float*)d_in[20];
    const float* bc2 = (const float*)d_in[21];
    float* out = (float*)d_out;

    const int n = N_NODES;
    const int* src = ei;
    const int* dst = ei + N_EDGES;

    static int smem_cfg_done = 0;
    if (!smem_cfg_done) {
        cudaFuncSetAttribute(gemm_fused_k<0>,
                             cudaFuncAttributeMaxDynamicSharedMemorySize, GEMM_SMEM);
        cudaFuncSetAttribute(gemm_fused_k<1>,
                             cudaFuncAttributeMaxDynamicSharedMemorySize, GEMM_SMEM);
        smem_cfg_done = 1;
    }

    float *hbuf, *aggbuf, *asb, *adb;
    float *sumb, *sqb, *sclb, *sftb;
    unsigned int *w0h, *w0l, *w1h, *w1l, *w2h, *w2l;
    int *degb, *curb, *rowb, *csrcb, *blkb;
    cudaGetSymbolAddress((void**)&hbuf,  g_h);
    cudaGetSymbolAddress((void**)&aggbuf, g_agg);
    cudaGetSymbolAddress((void**)&asb,   g_as);
    cudaGetSymbolAddress((void**)&adb,   g_ad);
    cudaGetSymbolAddress((void**)&sumb,  g_sum);
    cudaGetSymbolAddress((void**)&sqb,   g_sq);
    cudaGetSymbolAddress((void**)&sclb,  g_scl);
    cudaGetSymbolAddress((void**)&sftb,  g_sft);
    cudaGetSymbolAddress((void**)&w0h,   g_w0h);
    cudaGetSymbolAddress((void**)&w0l,   g_w0l);
    cudaGetSymbolAddress((void**)&w1h,   g_w1h);
    cudaGetSymbolAddress((void**)&w1l,   g_w1l);
    cudaGetSymbolAddress((void**)&w2h,   g_w2h);
    cudaGetSymbolAddress((void**)&w2l,   g_w2l);
    cudaGetSymbolAddress((void**)&degb,  g_deg);
    cudaGetSymbolAddress((void**)&curb,  g_cursor);
    cudaGetSymbolAddress((void**)&rowb,  g_rowptr);
    cudaGetSymbolAddress((void**)&csrcb, g_csrc);
    cudaGetSymbolAddress((void**)&blkb,  g_blksum);

    // ---- prologue; GEMM is our 4th launch (ncu window) ----
    split_w_k<<<(64 * 256 + 255) / 256, 256>>>(W0, w0h, w0l, 128, 256);
    fill2f_k<<<(n * 4 + 255) / 256, 256>>>(asb, adb, n * 4);
    fill2i_k<<<(n + 255) / 256, 256>>>(degb, curb, n);

    // ---- GAT layer 0 GEMM + attn: 128 -> 4x64 (A = x, no BN) ----
    run_gemm(0, x, w0h, w0l, hbuf, n, 256, 128, nullptr, nullptr,
             as0, ad0, asb, adb);

    // ---- CSR build + remaining weight splits ----
    deg_k<<<(ET_EDGES + 255) / 256, 256>>>(dst, degb, N_EDGES, ET_EDGES);
    scan_part_k<<<NBLK_SCAN, 256>>>(degb, rowb, blkb, n);
    scan_tops_k<<<1, 256>>>(blkb, NBLK_SCAN);
    scan_write_k<<<NBLK_SCAN, 256>>>(rowb, blkb, n);
    fill_pos_k<<<(ET_EDGES + 255) / 256, 256>>>(src, dst, rowb, curb, csrcb,
                                                N_EDGES, ET_EDGES);
    split_w_k<<<(128 * 256 + 255) / 256, 256>>>(W1, w1h, w1l, 256, 256);
    split_w_k<<<(128 * 64 + 255) / 256, 256>>>(W2, w2h, w2l, 256, 64);

    int aggBlocks = (n * 32 + 255) / 256;

    // ---- GAT layer 0 aggregation + BN stats ----
    agg4_k<<<aggBlocks, 256>>>(rowb, csrcb, hbuf, asb, adb, aggbuf, n);
    fill2f_k<<<1, 256>>>(sumb, sqb, HWID);
    bn_stats_k<<<512, 256>>>(aggbuf, n, sumb, sqb);
    bn_fin_k<<<1, 256>>>(sumb, sqb, g0, be0, n, sclb, sftb);

    // ---- GAT layer 1: BN+ELU fused into GEMM A-path ----
    fill2f_k<<<(n * 4 + 255) / 256, 256>>>(asb, adb, n * 4);
    run_gemm(1, aggbuf, w1h, w1l, hbuf, n, 256, 256, sclb, sftb,
             as1, ad1, asb, adb);
    agg4_k<<<aggBlocks, 256>>>(rowb, csrcb, hbuf, asb, adb, aggbuf, n);
    fill2f_k<<<1, 256>>>(sumb, sqb, HWID);
    bn_stats_k<<<512, 256>>>(aggbuf, n, sumb, sqb);
    bn_fin_k<<<1, 256>>>(sumb, sqb, g1, be1, n, sclb, sftb);

    // ---- GAT layer 2: BN+ELU fused into GEMM A-path; 256 -> 1x64 ----
    fill2f_k<<<(n + 255) / 256, 256>>>(asb, adb, n);
    run_gemm(1, aggbuf, w2h, w2l, hbuf, n, 64, 256, sclb, sftb,
             as2, ad2, asb, adb);

    // ---- agg1 + bias + classifier fused ----
    agg1_cls_k<<<aggBlocks, 256>>>(rowb, csrcb, hbuf, asb, adb, b2,
                                   Wc1, bc1, Wc2, bc2, out, n);
}

// round 15
// speedup vs baseline: 1.6740x; 1.1678x over previous
#include <cuda_runtime.h>
#include <cuda_bf16.h>
#include <math.h>

// Problem constants (fixed by the dataset)
#define N_NODES 50000
#define N_EDGES 800000
#define ET_EDGES (N_NODES + N_EDGES)   // edges + self loops
#define HWID 256                        // heads*hid for layers 0/1
#define CDIM 64
#define NBLK_SCAN ((N_NODES + 255) / 256)   // 196

// ---------------- scratch (device globals; no allocation allowed) -------------
static __device__ float g_h   [(size_t)N_NODES * HWID];
static __device__ float g_agg [(size_t)N_NODES * HWID];
static __device__ float g_as  [N_NODES * 4];
static __device__ float g_ad  [N_NODES * 4];
static __device__ float g_sum [HWID];
static __device__ float g_sq  [HWID];
static __device__ float g_scl [HWID];
static __device__ float g_sft [HWID];
// bf16 hi/lo packed weights ([K/2][N] u32)
static __device__ unsigned int g_w0h[64 * 256],  g_w0l[64 * 256];
static __device__ unsigned int g_w1h[128 * 256], g_w1l[128 * 256];
static __device__ unsigned int g_w2h[128 * 64],  g_w2l[128 * 64];
// CSR scratch
static __device__ int g_deg   [N_NODES];
static __device__ int g_cursor[N_NODES];
static __device__ int g_rowptr[N_NODES + 1];
static __device__ int g_csrc  [ET_EDGES];      // src node per CSR slot
static __device__ int g_blksum[256];

// ---------------- helpers -----------------------------------------------------
// split two fp32 into packed bf16x2 hi + bf16x2 lo (lower k in low 16 bits)
__device__ __forceinline__ void bf16split2(float v0, float v1,
                                           unsigned int& hi, unsigned int& lo) {
    __nv_bfloat16 h0 = __float2bfloat16(v0), h1 = __float2bfloat16(v1);
    float r0 = v0 - __bfloat162float(h0);
    float r1 = v1 - __bfloat162float(h1);
    __nv_bfloat16 l0 = __float2bfloat16(r0), l1 = __float2bfloat16(r1);
    hi = ((unsigned int)__bfloat16_as_ushort(h1) << 16) | __bfloat16_as_ushort(h0);
    lo = ((unsigned int)__bfloat16_as_ushort(l1) << 16) | __bfloat16_as_ushort(l0);
}

__device__ __forceinline__ void cpasync16(unsigned int dst, const void* src, bool pred) {
    int sz = pred ? 16 : 0;
    asm volatile("cp.async.cg.shared.global [%0], [%1], 16, %2;"
                 :: "r"(dst), "l"(src), "r"(sz) : "memory");
}
#define CP_COMMIT() asm volatile("cp.async.commit_group;" ::: "memory")
#define CP_WAIT(N)  asm volatile("cp.async.wait_group %0;" :: "n"(N) : "memory")

__global__ void fill2f_k(float* p, float* q, int n) {
    int i = blockIdx.x * blockDim.x + threadIdx.x;
    if (i < n) { p[i] = 0.f; q[i] = 0.f; }
}

__global__ void fill2i_k(int* p, int* q, int n) {
    int i = blockIdx.x * blockDim.x + threadIdx.x;
    if (i < n) { p[i] = 0; q[i] = 0; }
}

// ---------------- weight pre-split: W [K][N] -> hi/lo [K/2][N] u32 ------------
__global__ void split_w_k(const float* __restrict__ W,
                          unsigned int* __restrict__ hi, unsigned int* __restrict__ lo,
                          int K, int N) {
    int j = blockIdx.x * blockDim.x + threadIdx.x;
    if (j >= (K / 2) * N) return;
    int k2 = j / N, nn = j - k2 * N;
    float v0 = W[(size_t)(2 * k2) * N + nn];
    float v1 = W[(size_t)(2 * k2 + 1) * N + nn];
    bf16split2(v0, v1, hi[j], lo[j]);
}

// ---------------- CSR construction --------------------------------------------
__global__ void deg_k(const int* __restrict__ dst, int* deg, int E, int et) {
    int e = blockIdx.x * blockDim.x + threadIdx.x;
    if (e >= et) return;
    int d = e < E ? dst[e] : e - E;
    atomicAdd(&deg[d], 1);
}

__global__ void scan_part_k(const int* __restrict__ deg, int* rowptr, int* blksum, int n) {
    __shared__ int sm[256];
    int i = blockIdx.x * 256 + threadIdx.x;
    int v = (i < n) ? deg[i] : 0;
    sm[threadIdx.x] = v;
    __syncthreads();
    for (int o = 1; o < 256; o <<= 1) {
        int t = (threadIdx.x >= o) ? sm[threadIdx.x - o] : 0;
        __syncthreads();
        sm[threadIdx.x] += t;
        __syncthreads();
    }
    if (i < n) rowptr[i] = sm[threadIdx.x] - v;      // exclusive
    if (threadIdx.x == 255) blksum[blockIdx.x] = sm[255];
}

__global__ void scan_tops_k(int* blksum, int nb) {
    __shared__ int sm[256];
    int v = (threadIdx.x < nb) ? blksum[threadIdx.x] : 0;
    sm[threadIdx.x] = v;
    __syncthreads();
    for (int o = 1; o < 256; o <<= 1) {
        int t = (threadIdx.x >= o) ? sm[threadIdx.x - o] : 0;
        __syncthreads();
        sm[threadIdx.x] += t;
        __syncthreads();
    }
    if (threadIdx.x < nb) blksum[threadIdx.x] = sm[threadIdx.x] - v;   // exclusive
}

__global__ void scan_write_k(int* rowptr, const int* __restrict__ blksum, int n) {
    int i = blockIdx.x * 256 + threadIdx.x;
    if (i < n) rowptr[i] += blksum[blockIdx.x];
    if (i == 0) rowptr[n] = ET_EDGES;
}

__global__ void fill_pos_k(const int* __restrict__ src, const int* __restrict__ dst,
                           const int* __restrict__ rowptr,
                           int* cursor, int* csrc, int E, int et) {
    int e = blockIdx.x * blockDim.x + threadIdx.x;
    if (e >= et) return;
    int s, d;
    if (e < E) { s = src[e]; d = dst[e]; } else { s = d = e - E; }
    int p = atomicAdd(&cursor[d], 1);
    csrc[rowptr[d] + p] = s;
}

// ---------------- fused GEMM: [BN+ELU] + bf16-split on A-fill + attn epilogue -
// C = f(A) @ B where f = identity (DOBN=0) or ELU(A*scl+sft) (DOBN=1).
// A: raw fp32 [M][K], split to bf16 hi/lo during the smem fill (single stage).
// B: pre-split [K/2][N] u32 hi/lo, double-buffered cp.async, issued BEFORE the
// A fill so its latency hides behind A's synchronous LDG+split.
// acc += ah*bl + al*bh + ah*bh. Epilogue: C store + a_s/a_d via spread atomics.
// Smem (u32): AH=0 (128x20), AL=+2560; BH=5120+st*2304, BL=+1152.
// Dyn smem = 38912 B. Requires K%32==0, N%64==0.
template <int DOBN>
__global__ __launch_bounds__(256, 3) void gemm_fused_k(
    const float* __restrict__ A,
    const unsigned int* __restrict__ Bh2, const unsigned int* __restrict__ Bl2,
    float* __restrict__ C, int M, int N, int K,
    const float* __restrict__ scl, const float* __restrict__ sft,
    const float* __restrict__ attn_s, const float* __restrict__ attn_d,
    float* __restrict__ as_o, float* __restrict__ ad_o)
{
    extern __shared__ unsigned int smem[];
    unsigned int sbase = (unsigned int)__cvta_generic_to_shared(smem);

    int tid = threadIdx.x;
    int warp = tid >> 5, lane = tid & 31;
    int wm = (warp & 3) * 32;
    int wn = (warp >> 2) * 32;
    int rowBase = blockIdx.y * 128;
    int colBase = blockIdx.x * 64;
    int mrow = lane >> 2;           // 0..7
    int kc   = lane & 3;            // 0..3
    int K4 = K >> 2;

#define PREFETCH_B(IT, ST)                                                         \
    do {                                                                           \
        int k2b = (IT) * 16;                                                       \
        int r = tid >> 4, c4 = (tid & 15) * 4;                                     \
        unsigned int off = (5120 + (ST) * 2304 + r * 72 + c4) * 4;                 \
        cpasync16(sbase + off, &Bh2[(size_t)(k2b + r) * N + colBase + c4], true);  \
        cpasync16(sbase + off + 1152 * 4, &Bl2[(size_t)(k2b + r) * N + colBase + c4], true); \
        CP_COMMIT();                                                               \
    } while (0)

    float acc[2][4][4];
#pragma unroll
    for (int mi = 0; mi < 2; mi++)
#pragma unroll
        for (int ni = 0; ni < 4; ni++)
#pragma unroll
            for (int r = 0; r < 4; r++) acc[mi][ni][r] = 0.f;

    int niter = K >> 5;
    PREFETCH_B(0, 0);

    for (int it = 0; it < niter; it++) {
        int st = it & 1;
        if (it + 1 < niter) PREFETCH_B(it + 1, st ^ 1);

        // ---- A fill (single stage): load fp32, [BN+ELU], bf16-split, STS ----
        {
            unsigned int* AsH = smem;               // [128][20]
            unsigned int* AsL = smem + 2560;
#pragma unroll
            for (int i = 0; i < 4; i++) {
                int f4 = tid + i * 256;
                int r = f4 >> 3, cf = (f4 & 7) * 4;   // fp32 col within BK=32
                int gr = rowBase + r;
                float4 v = make_float4(0.f, 0.f, 0.f, 0.f);
                if (gr < M) v = ((const float4*)A)[(size_t)gr * K4 + it * 8 + (f4 & 7)];
                if (DOBN) {
                    int ch = it * 32 + cf;
                    float4 s4 = *(const float4*)&scl[ch];
                    float4 t4 = *(const float4*)&sft[ch];
                    v.x = v.x * s4.x + t4.x;
                    v.y = v.y * s4.y + t4.y;
                    v.z = v.z * s4.z + t4.z;
                    v.w = v.w * s4.w + t4.w;
                    v.x = v.x > 0.f ? v.x : __expf(v.x) - 1.f;
                    v.y = v.y > 0.f ? v.y : __expf(v.y) - 1.f;
                    v.z = v.z > 0.f ? v.z : __expf(v.z) - 1.f;
                    v.w = v.w > 0.f ? v.w : __expf(v.w) - 1.f;
                }
                uint2 hi, lo;
                bf16split2(v.x, v.y, hi.x, lo.x);
                bf16split2(v.z, v.w, hi.y, lo.y);
                *(uint2*)&AsH[r * 20 + (cf >> 1)] = hi;
                *(uint2*)&AsL[r * 20 + (cf >> 1)] = lo;
            }
        }
        if (it + 1 < niter) CP_WAIT(1); else CP_WAIT(0);
        __syncthreads();

        const unsigned int* AsH = smem;
        const unsigned int* AsL = smem + 2560;
        const unsigned int* BsH = smem + 5120 + st * 2304;
        const unsigned int* BsL = BsH + 1152;

#pragma unroll
        for (int ks = 0; ks < 2; ks++) {
            unsigned int ah[2][4], al[2][4], bh[4][2], bl[4][2];
#pragma unroll
            for (int mi = 0; mi < 2; mi++) {
                int m = wm + mi * 16 + mrow;
                int i0 = m * 20 + ks * 8 + kc;
                ah[mi][0] = AsH[i0];            al[mi][0] = AsL[i0];
                ah[mi][1] = AsH[i0 + 160];      al[mi][1] = AsL[i0 + 160];   // row+8
                ah[mi][2] = AsH[i0 + 4];        al[mi][2] = AsL[i0 + 4];     // k+8
                ah[mi][3] = AsH[i0 + 164];      al[mi][3] = AsL[i0 + 164];
            }
#pragma unroll
            for (int ni = 0; ni < 4; ni++) {
                int ib = (ks * 8 + kc) * 72 + wn + ni * 8 + mrow;
                bh[ni][0] = BsH[ib];            bl[ni][0] = BsL[ib];
                bh[ni][1] = BsH[ib + 288];      bl[ni][1] = BsL[ib + 288];   // k+8
            }
#define MMA_B(ar, br, mi, ni)                                                     \
    asm volatile(                                                                 \
        "mma.sync.aligned.m16n8k16.row.col.f32.bf16.bf16.f32 "                    \
        "{%0,%1,%2,%3},{%4,%5,%6,%7},{%8,%9},{%0,%1,%2,%3};"                      \
        : "+f"(acc[mi][ni][0]), "+f"(acc[mi][ni][1]),                             \
          "+f"(acc[mi][ni][2]), "+f"(acc[mi][ni][3])                              \
        : "r"(ar[mi][0]), "r"(ar[mi][1]), "r"(ar[mi][2]), "r"(ar[mi][3]),         \
          "r"(br[ni][0]), "r"(br[ni][1]))
#pragma unroll
            for (int mi = 0; mi < 2; mi++)
#pragma unroll
                for (int ni = 0; ni < 4; ni++) {
                    MMA_B(ah, bl, mi, ni);
                    MMA_B(al, bh, mi, ni);
                    MMA_B(ah, bh, mi, ni);
                }
#undef MMA_B
        }
        __syncthreads();
    }
#undef PREFETCH_B

    // ---- epilogue: store C + fused attention coefficients ----
    int H = gridDim.x;
    int head = blockIdx.x;
    const float* av = attn_s + head * 64;
    const float* dv = attn_d + head * 64;
    float avv[8], dvv[8];
#pragma unroll
    for (int ni = 0; ni < 4; ni++)
#pragma unroll
        for (int j = 0; j < 2; j++) {
            int cc = wn + ni * 8 + kc * 2 + j;
            avv[ni * 2 + j] = __ldg(&av[cc]);
            dvv[ni * 2 + j] = __ldg(&dv[cc]);
        }

#pragma unroll
    for (int mi = 0; mi < 2; mi++) {
        int r0 = rowBase + wm + mi * 16 + mrow;
        float s0 = 0.f, d0 = 0.f, s1 = 0.f, d1 = 0.f;
#pragma unroll
        for (int ni = 0; ni < 4; ni++) {
            int c = colBase + wn + ni * 8 + kc * 2;
            if (r0 < M) {
                C[(size_t)r0 * N + c]     = acc[mi][ni][0];
                C[(size_t)r0 * N + c + 1] = acc[mi][ni][1];
            }
            if (r0 + 8 < M) {
                C[(size_t)(r0 + 8) * N + c]     = acc[mi][ni][2];
                C[(size_t)(r0 + 8) * N + c + 1] = acc[mi][ni][3];
            }
            s0 += acc[mi][ni][0] * avv[ni * 2] + acc[mi][ni][1] * avv[ni * 2 + 1];
            d0 += acc[mi][ni][0] * dvv[ni * 2] + acc[mi][ni][1] * dvv[ni * 2 + 1];
            s1 += acc[mi][ni][2] * avv[ni * 2] + acc[mi][ni][3] * avv[ni * 2 + 1];
            d1 += acc[mi][ni][2] * dvv[ni * 2] + acc[mi][ni][3] * dvv[ni * 2 + 1];
        }
#pragma unroll
        for (int o = 1; o < 4; o <<= 1) {
            s0 += __shfl_xor_sync(0xFFFFFFFFu, s0, o);
            d0 += __shfl_xor_sync(0xFFFFFFFFu, d0, o);
            s1 += __shfl_xor_sync(0xFFFFFFFFu, s1, o);
            d1 += __shfl_xor_sync(0xFFFFFFFFu, d1, o);
        }
        if (kc == 0) {
            if (r0 < M) {
                atomicAdd(&as_o[r0 * H + head], s0);
                atomicAdd(&ad_o[r0 * H + head], d0);
            }
            if (r0 + 8 < M) {
                atomicAdd(&as_o[(r0 + 8) * H + head], s1);
                atomicAdd(&ad_o[(r0 + 8) * H + head], d1);
            }
        }
    }
}

// ------ fused softmax + CSR aggregation (H=4) + BN statistics, single pass ----
// One warp per dst node. Lane l owns channels [4l,4l+4) and [128+4l,128+4l+4).
// Block-level BN partials in smem (8 warps x 256 ch), cross-warp tree at block
// end, then 512 global atomics per block into sum/sq (pre-zeroed).
__global__ void agg4_k(const int* __restrict__ rowptr, const int* __restrict__ csrc,
                       const float* __restrict__ h,
                       const float* __restrict__ asb, const float* __restrict__ adb,
                       float* __restrict__ out,
                       float* __restrict__ sum, float* __restrict__ sq, int n)
{
    __shared__ float ps[8 * 256];    // [warp][channel]

    int tid = threadIdx.x;
    int w = (blockIdx.x * blockDim.x + tid) >> 5;
    int warp = tid >> 5;
    int lane = tid & 31;
    bool active = w < n;

    float4 acc0 = make_float4(0.f, 0.f, 0.f, 0.f);
    float4 acc1 = make_float4(0.f, 0.f, 0.f, 0.f);

    if (active) {
        int beg = rowptr[w], end = rowptr[w + 1];
        int eh = lane & 3;
        float ad_h = adb[(size_t)w * 4 + eh];
        int hA = lane >> 4;        // head supplying channels [0,128): 0 or 1
        int hB = 2 + hA;           // head supplying channels [128,256): 2 or 3

        float den = 0.f;
        for (int j = beg; j < end; j++) {
            int s = __ldg(&csrc[j]);
            float e = asb[(size_t)s * 4 + eh] + ad_h;
            e = e > 0.f ? e : 0.2f * e;
            float ww = __expf(e);
            den += ww;
            float aA = __shfl_sync(0xFFFFFFFFu, ww, hA);
            float aB = __shfl_sync(0xFFFFFFFFu, ww, hB);
            const float4* hr = (const float4*)(h + (size_t)s * 256);
            float4 v0 = hr[lane];
            float4 v1 = hr[32 + lane];
            acc0.x += v0.x * aA; acc0.y += v0.y * aA; acc0.z += v0.z * aA; acc0.w += v0.w * aA;
            acc1.x += v1.x * aB; acc1.y += v1.y * aB; acc1.z += v1.z * aB; acc1.w += v1.w * aB;
        }
        float iA = 1.f / __shfl_sync(0xFFFFFFFFu, den, hA);
        float iB = 1.f / __shfl_sync(0xFFFFFFFFu, den, hB);
        acc0.x *= iA; acc0.y *= iA; acc0.z *= iA; acc0.w *= iA;
        acc1.x *= iB; acc1.y *= iB; acc1.z *= iB; acc1.w *= iB;
        float4* o4 = (float4*)(out + (size_t)w * 256);
        o4[lane] = acc0;
        o4[32 + lane] = acc1;
    }

    // BN partials: channel c = 4*lane + j (acc0), 128 + 4*lane + j (acc1)
    *(float4*)&ps[warp * 256 + lane * 4]       = acc0;
    *(float4*)&ps[warp * 256 + 128 + lane * 4] = acc1;
    __syncthreads();

    // cross-warp reduce: thread t handles channel t (bank-conflict-free)
    float s = 0.f, s2 = 0.f;
#pragma unroll
    for (int ww = 0; ww < 8; ww++) {
        float v = ps[ww * 256 + tid];
        s += v; s2 += v * v;
    }
    atomicAdd(&sum[tid], s);
    atomicAdd(&sq[tid], s2);
}

// ---- fused agg (H=1) + bias + classifier: out[n,2], no intermediate traffic --
__global__ void agg1_cls_k(const int* __restrict__ rowptr, const int* __restrict__ csrc,
                           const float* __restrict__ h,
                           const float* __restrict__ asb, const float* __restrict__ adb,
                           const float* __restrict__ bias,
                           const float* __restrict__ Wc1, const float* __restrict__ bc1,
                           const float* __restrict__ Wc2, const float* __restrict__ bc2,
                           float* __restrict__ out, int n)
{
    int w = (blockIdx.x * blockDim.x + threadIdx.x) >> 5;
    int lane = threadIdx.x & 31;
    if (w >= n) return;
    int beg = rowptr[w], end = rowptr[w + 1];
    float ad = adb[w];

    float den = 0.f;
    float4 acc = make_float4(0.f, 0.f, 0.f, 0.f);
    for (int j = beg; j < end; j++) {
        int s = __ldg(&csrc[j]);
        float e = asb[s] + ad;
        e = e > 0.f ? e : 0.2f * e;
        float ww = __expf(e);
        den += ww;
        if (lane < 16) {
            float4 v = ((const float4*)(h + (size_t)s * 64))[lane];
            acc.x += v.x * ww; acc.y += v.y * ww; acc.z += v.z * ww; acc.w += v.w * ww;
        }
    }
    if (lane < 16) {
        float inv = 1.f / den;
        float4 b4 = ((const float4*)bias)[lane];
        acc.x = acc.x * inv + b4.x; acc.y = acc.y * inv + b4.y;
        acc.z = acc.z * inv + b4.z; acc.w = acc.w * inv + b4.w;
    }
    // classifier: lane j owns hidden unit j; x channels broadcast from lanes 0-15
    float hj = __ldg(&bc1[lane]);
#pragma unroll
    for (int c = 0; c < 64; c++) {
        int q = c >> 2, t = c & 3;
        float src = t == 0 ? acc.x : (t == 1 ? acc.y : (t == 2 ? acc.z : acc.w));
        float xc = __shfl_sync(0xFFFFFFFFu, src, q);
        hj += xc * __ldg(&Wc1[c * 32 + lane]);
    }
    hj = fmaxf(hj, 0.f);
    float o0 = hj * __ldg(&Wc2[lane * 2 + 0]);
    float o1 = hj * __ldg(&Wc2[lane * 2 + 1]);
#pragma unroll
    for (int o = 16; o; o >>= 1) {
        o0 += __shfl_down_sync(0xFFFFFFFFu, o0, o);
        o1 += __shfl_down_sync(0xFFFFFFFFu, o1, o);
    }
    if (!lane) {
        out[(size_t)w * 2]     = o0 + __ldg(&bc2[0]);
        out[(size_t)w * 2 + 1] = o1 + __ldg(&bc2[1]);
    }
}

__global__ void bn_fin_k(const float* sum, const float* sq,
                         const float* __restrict__ g, const float* __restrict__ be,
                         int n, float* scl, float* sft) {
    int ch = threadIdx.x;
    float mu = sum[ch] / (float)n;
    float var = fmaxf(sq[ch] / (float)n - mu * mu, 0.f);
    float r = rsqrtf(var + 1e-5f);
    float s = g[ch] * r;
    scl[ch] = s;
    sft[ch] = be[ch] - mu * s;
}

// ---------------- host-side orchestration -------------------------------------
#define GEMM_SMEM 38912

static void run_gemm(int dobn, const float* A,
                     const unsigned int* Bh, const unsigned int* Bl,
                     float* C, int M, int N, int K,
                     const float* scl, const float* sft,
                     const float* atts, const float* attd,
                     float* aso, float* ado) {
    dim3 grid(N / 64, (M + 127) / 128);
    if (dobn)
        gemm_fused_k<1><<<grid, 256, GEMM_SMEM>>>(A, Bh, Bl, C, M, N, K,
                                                  scl, sft, atts, attd, aso, ado);
    else
        gemm_fused_k<0><<<grid, 256, GEMM_SMEM>>>(A, Bh, Bl, C, M, N, K,
                                                  scl, sft, atts, attd, aso, ado);
}

extern "C" void kernel_launch(void* const* d_in, const int* in_sizes, int n_in,
                              void* d_out, int out_size)
{
    const float* x   = (const float*)d_in[0];
    const int*   ei  = (const int*)  d_in[1];
    const float* W0  = (const float*)d_in[2];
    const float* as0 = (const float*)d_in[3];
    const float* ad0 = (const float*)d_in[4];
    // b0 (d_in[5]) cancels through BatchNorm — skipped
    const float* W1  = (const float*)d_in[6];
    const float* as1 = (const float*)d_in[7];
    const float* ad1 = (const float*)d_in[8];
    // b1 (d_in[9]) cancels through BatchNorm — skipped
    const float* W2  = (const float*)d_in[10];
    const float* as2 = (const float*)d_in[11];
    const float* ad2 = (const float*)d_in[12];
    const float* b2  = (const float*)d_in[13];
    const float* g0  = (const float*)d_in[14];
    const float* be0 = (const float*)d_in[15];
    const float* g1  = (const float*)d_in[16];
    const float* be1 = (const float*)d_in[17];
    const float* Wc1 = (const float*)d_in[18];
    const float* bc1 = (const float*)d_in[19];
    const float* Wc2 = (const float*)d_in[20];
    const float* bc2 = (const float*)d_in[21];
    float* out = (float*)d_out;

    const int n = N_NODES;
    const int* src = ei;
    const int* dst = ei + N_EDGES;

    static int smem_cfg_done = 0;
    if (!smem_cfg_done) {
        cudaFuncSetAttribute(gemm_fused_k<0>,
                             cudaFuncAttributeMaxDynamicSharedMemorySize, GEMM_SMEM);
        cudaFuncSetAttribute(gemm_fused_k<1>,
                             cudaFuncAttributeMaxDynamicSharedMemorySize, GEMM_SMEM);
        smem_cfg_done = 1;
    }

    float *hbuf, *aggbuf, *asb, *adb;
    float *sumb, *sqb, *sclb, *sftb;
    unsigned int *w0h, *w0l, *w1h, *w1l, *w2h, *w2l;
    int *degb, *curb, *rowb, *csrcb, *blkb;
    cudaGetSymbolAddress((void**)&hbuf,  g_h);
    cudaGetSymbolAddress((void**)&aggbuf, g_agg);
    cudaGetSymbolAddress((void**)&asb,   g_as);
    cudaGetSymbolAddress((void**)&adb,   g_ad);
    cudaGetSymbolAddress((void**)&sumb,  g_sum);
    cudaGetSymbolAddress((void**)&sqb,   g_sq);
    cudaGetSymbolAddress((void**)&sclb,  g_scl);
    cudaGetSymbolAddress((void**)&sftb,  g_sft);
    cudaGetSymbolAddress((void**)&w0h,   g_w0h);
    cudaGetSymbolAddress((void**)&w0l,   g_w0l);
    cudaGetSymbolAddress((void**)&w1h,   g_w1h);
    cudaGetSymbolAddress((void**)&w1l,   g_w1l);
    cudaGetSymbolAddress((void**)&w2h,   g_w2h);
    cudaGetSymbolAddress((void**)&w2l,   g_w2l);
    cudaGetSymbolAddress((void**)&degb,  g_deg);
    cudaGetSymbolAddress((void**)&curb,  g_cursor);
    cudaGetSymbolAddress((void**)&rowb,  g_rowptr);
    cudaGetSymbolAddress((void**)&csrcb, g_csrc);
    cudaGetSymbolAddress((void**)&blkb,  g_blksum);

    // ---- prologue; GEMM is our 4th launch (ncu window) ----
    split_w_k<<<(64 * 256 + 255) / 256, 256>>>(W0, w0h, w0l, 128, 256);
    fill2f_k<<<(n * 4 + 255) / 256, 256>>>(asb, adb, n * 4);
    fill2i_k<<<(n + 255) / 256, 256>>>(degb, curb, n);

    // ---- GAT layer 0 GEMM + attn: 128 -> 4x64 (A = x, no BN) ----
    run_gemm(0, x, w0h, w0l, hbuf, n, 256, 128, nullptr, nullptr,
             as0, ad0, asb, adb);

    // ---- CSR build + remaining weight splits ----
    deg_k<<<(ET_EDGES + 255) / 256, 256>>>(dst, degb, N_EDGES, ET_EDGES);
    scan_part_k<<<NBLK_SCAN, 256>>>(degb, rowb, blkb, n);
    scan_tops_k<<<1, 256>>>(blkb, NBLK_SCAN);
    scan_write_k<<<NBLK_SCAN, 256>>>(rowb, blkb, n);
    fill_pos_k<<<(ET_EDGES + 255) / 256, 256>>>(src, dst, rowb, curb, csrcb,
                                                N_EDGES, ET_EDGES);
    split_w_k<<<(128 * 256 + 255) / 256, 256>>>(W1, w1h, w1l, 256, 256);
    split_w_k<<<(128 * 64 + 255) / 256, 256>>>(W2, w2h, w2l, 256, 64);

    int aggBlocks = (n * 32 + 255) / 256;

    // ---- GAT layer 0 aggregation + fused BN stats ----
    fill2f_k<<<1, 256>>>(sumb, sqb, HWID);
    agg4_k<<<aggBlocks, 256>>>(rowb, csrcb, hbuf, asb, adb, aggbuf,
                               sumb, sqb, n);
    bn_fin_k<<<1, 256>>>(sumb, sqb, g0, be0, n, sclb, sftb);

    // ---- GAT layer 1: BN+ELU fused into GEMM A-path ----
    fill2f_k<<<(n * 4 + 255) / 256, 256>>>(asb, adb, n * 4);
    run_gemm(1, aggbuf, w1h, w1l, hbuf, n, 256, 256, sclb, sftb,
             as1, ad1, asb, adb);
    fill2f_k<<<1, 256>>>(sumb, sqb, HWID);
    agg4_k<<<aggBlocks, 256>>>(rowb, csrcb, hbuf, asb, adb, aggbuf,
                               sumb, sqb, n);
    bn_fin_k<<<1, 256>>>(sumb, sqb, g1, be1, n, sclb, sftb);

    // ---- GAT layer 2: BN+ELU fused into GEMM A-path; 256 -> 1x64 ----
    fill2f_k<<<(n + 255) / 256, 256>>>(asb, adb, n);
    run_gemm(1, aggbuf, w2h, w2l, hbuf, n, 64, 256, sclb, sftb,
             as2, ad2, asb, adb);

    // ---- agg1 + bias + classifier fused ----
    agg1_cls_k<<<aggBlocks, 256>>>(rowb, csrcb, hbuf, asb, adb, b2,
                                   Wc1, bc1, Wc2, bc2, out, n);
}

// round 17
// speedup vs baseline: 1.6963x; 1.0133x over previous
#include <cuda_runtime.h>
#include <cuda_bf16.h>
#include <math.h>

// Problem constants (fixed by the dataset)
#define N_NODES 50000
#define N_EDGES 800000
#define ET_EDGES (N_NODES + N_EDGES)   // edges + self loops
#define HWID 256
#define NBLK_SCAN ((N_NODES + 255) / 256)   // 196

// ---------------- scratch (device globals; no allocation allowed) -------------
static __device__ float g_h   [(size_t)N_NODES * HWID];
static __device__ float g_agg [(size_t)N_NODES * HWID];
static __device__ float g_as  [N_NODES * 4];
static __device__ float g_ad  [N_NODES * 4];
static __device__ float g_sum [HWID];
static __device__ float g_sq  [HWID];
static __device__ float g_scl [HWID];
static __device__ float g_sft [HWID];
// bf16 hi/lo packed weights ([K/2][N] u32)
static __device__ unsigned int g_w0h[64 * 256],  g_w0l[64 * 256];
static __device__ unsigned int g_w1h[128 * 256], g_w1l[128 * 256];
static __device__ unsigned int g_w2h[128 * 64],  g_w2l[128 * 64];
// CSR scratch
static __device__ int g_deg   [N_NODES];
static __device__ int g_cursor[N_NODES];
static __device__ int g_rowptr[N_NODES + 1];
static __device__ int g_csrc  [ET_EDGES];      // src node per CSR slot
static __device__ int g_blksum[256];

// ---------------- helpers -----------------------------------------------------
// split two fp32 into packed bf16x2 hi + bf16x2 lo (lower k in low 16 bits)
__device__ __forceinline__ void bf16split2(float v0, float v1,
                                           unsigned int& hi, unsigned int& lo) {
    __nv_bfloat16 h0 = __float2bfloat16(v0), h1 = __float2bfloat16(v1);
    float r0 = v0 - __bfloat162float(h0);
    float r1 = v1 - __bfloat162float(h1);
    __nv_bfloat16 l0 = __float2bfloat16(r0), l1 = __float2bfloat16(r1);
    hi = ((unsigned int)__bfloat16_as_ushort(h1) << 16) | __bfloat16_as_ushort(h0);
    lo = ((unsigned int)__bfloat16_as_ushort(l1) << 16) | __bfloat16_as_ushort(l0);
}

__device__ __forceinline__ void cpasync16(unsigned int dst, const void* src, bool pred) {
    int sz = pred ? 16 : 0;
    asm volatile("cp.async.cg.shared.global [%0], [%1], 16, %2;"
                 :: "r"(dst), "l"(src), "r"(sz) : "memory");
}
#define CP_COMMIT() asm volatile("cp.async.commit_group;" ::: "memory")
#define CP_WAIT(N)  asm volatile("cp.async.wait_group %0;" :: "n"(N) : "memory")

__global__ void fill2f_k(float* p, float* q, int n) {
    int i = blockIdx.x * blockDim.x + threadIdx.x;
    if (i < n) { p[i] = 0.f; q[i] = 0.f; }
}

__global__ void fill2i_k(int* p, int* q, int n) {
    int i = blockIdx.x * blockDim.x + threadIdx.x;
    if (i < n) { p[i] = 0; q[i] = 0; }
}

// ---------------- weight pre-split: W [K][N] -> hi/lo [K/2][N] u32 ------------
__global__ void split_w_k(const float* __restrict__ W,
                          unsigned int* __restrict__ hi, unsigned int* __restrict__ lo,
                          int K, int N) {
    int j = blockIdx.x * blockDim.x + threadIdx.x;
    if (j >= (K / 2) * N) return;
    int k2 = j / N, nn = j - k2 * N;
    float v0 = W[(size_t)(2 * k2) * N + nn];
    float v1 = W[(size_t)(2 * k2 + 1) * N + nn];
    bf16split2(v0, v1, hi[j], lo[j]);
}

// ---------------- CSR construction --------------------------------------------
__global__ void deg_k(const int* __restrict__ dst, int* deg, int E, int et) {
    int e = blockIdx.x * blockDim.x + threadIdx.x;
    if (e >= et) return;
    int d = e < E ? dst[e] : e - E;
    atomicAdd(&deg[d], 1);
}

__global__ void scan_part_k(const int* __restrict__ deg, int* rowptr, int* blksum, int n) {
    __shared__ int sm[256];
    int i = blockIdx.x * 256 + threadIdx.x;
    int v = (i < n) ? deg[i] : 0;
    sm[threadIdx.x] = v;
    __syncthreads();
    for (int o = 1; o < 256; o <<= 1) {
        int t = (threadIdx.x >= o) ? sm[threadIdx.x - o] : 0;
        __syncthreads();
        sm[threadIdx.x] += t;
        __syncthreads();
    }
    if (i < n) rowptr[i] = sm[threadIdx.x] - v;      // exclusive
    if (threadIdx.x == 255) blksum[blockIdx.x] = sm[255];
}

__global__ void scan_tops_k(int* blksum, int nb) {
    __shared__ int sm[256];
    int v = (threadIdx.x < nb) ? blksum[threadIdx.x] : 0;
    sm[threadIdx.x] = v;
    __syncthreads();
    for (int o = 1; o < 256; o <<= 1) {
        int t = (threadIdx.x >= o) ? sm[threadIdx.x - o] : 0;
        __syncthreads();
        sm[threadIdx.x] += t;
        __syncthreads();
    }
    if (threadIdx.x < nb) blksum[threadIdx.x] = sm[threadIdx.x] - v;   // exclusive
}

__global__ void scan_write_k(int* rowptr, const int* __restrict__ blksum, int n) {
    int i = blockIdx.x * 256 + threadIdx.x;
    if (i < n) rowptr[i] += blksum[blockIdx.x];
    if (i == 0) rowptr[n] = ET_EDGES;
}

__global__ void fill_pos_k(const int* __restrict__ src, const int* __restrict__ dst,
                           const int* __restrict__ rowptr,
                           int* cursor, int* csrc, int E, int et) {
    int e = blockIdx.x * blockDim.x + threadIdx.x;
    if (e >= et) return;
    int s, d;
    if (e < E) { s = src[e]; d = dst[e]; } else { s = d = e - E; }
    int p = atomicAdd(&cursor[d], 1);
    csrc[rowptr[d] + p] = s;
}

// ---------------- fused GEMM: [BN+ELU] + bf16-split on A-fill + attn epilogue -
// C = f(A) @ B where f = identity (DOBN=0) or ELU(A*scl+sft) (DOBN=1).
// A: raw fp32 [M][K], split to bf16 hi/lo during the smem fill (single stage).
// B: pre-split [K/2][N] u32 hi/lo, double-buffered cp.async, issued BEFORE the
// A fill so its latency hides behind A's synchronous LDG+split.
// acc += ah*bl + al*bh + ah*bh.
// Epilogue: C store + a_s/a_d attention coefficients. Block (head=bx, rows by)
// fully owns each (row, head) output -> smem-staged partials + DIRECT stores
// (no global atomics, no zero-fill of as_o/ad_o needed).
// Smem (u32): AH=0 (128x20), AL=+2560; BH=5120+st*2304, BL=+1152.
// Dyn smem = 38912 B. Requires K%32==0, N%64==0.
template <int DOBN>
__global__ __launch_bounds__(256, 3) void gemm_fused_k(
    const float* __restrict__ A,
    const unsigned int* __restrict__ Bh2, const unsigned int* __restrict__ Bl2,
    float* __restrict__ C, int M, int N, int K,
    const float* __restrict__ scl, const float* __restrict__ sft,
    const float* __restrict__ attn_s, const float* __restrict__ attn_d,
    float* __restrict__ as_o, float* __restrict__ ad_o)
{
    extern __shared__ unsigned int smem[];
    unsigned int sbase = (unsigned int)__cvta_generic_to_shared(smem);

    int tid = threadIdx.x;
    int warp = tid >> 5, lane = tid & 31;
    int wm = (warp & 3) * 32;
    int wn = (warp >> 2) * 32;
    int rowBase = blockIdx.y * 128;
    int colBase = blockIdx.x * 64;
    int mrow = lane >> 2;           // 0..7
    int kc   = lane & 3;            // 0..3
    int K4 = K >> 2;

#define PREFETCH_B(IT, ST)                                                         \
    do {                                                                           \
        int k2b = (IT) * 16;                                                       \
        int r = tid >> 4, c4 = (tid & 15) * 4;                                     \
        unsigned int off = (5120 + (ST) * 2304 + r * 72 + c4) * 4;                 \
        cpasync16(sbase + off, &Bh2[(size_t)(k2b + r) * N + colBase + c4], true);  \
        cpasync16(sbase + off + 1152 * 4, &Bl2[(size_t)(k2b + r) * N + colBase + c4], true); \
        CP_COMMIT();                                                               \
    } while (0)

    float acc[2][4][4];
#pragma unroll
    for (int mi = 0; mi < 2; mi++)
#pragma unroll
        for (int ni = 0; ni < 4; ni++)
#pragma unroll
            for (int r = 0; r < 4; r++) acc[mi][ni][r] = 0.f;

    int niter = K >> 5;
    PREFETCH_B(0, 0);

    for (int it = 0; it < niter; it++) {
        int st = it & 1;
        if (it + 1 < niter) PREFETCH_B(it + 1, st ^ 1);

        // ---- A fill (single stage): load fp32, [BN+ELU], bf16-split, STS ----
        {
            unsigned int* AsH = smem;               // [128][20]
            unsigned int* AsL = smem + 2560;
#pragma unroll
            for (int i = 0; i < 4; i++) {
                int f4 = tid + i * 256;
                int r = f4 >> 3, cf = (f4 & 7) * 4;   // fp32 col within BK=32
                int gr = rowBase + r;
                float4 v = make_float4(0.f, 0.f, 0.f, 0.f);
                if (gr < M) v = ((const float4*)A)[(size_t)gr * K4 + it * 8 + (f4 & 7)];
                if (DOBN) {
                    int ch = it * 32 + cf;
                    float4 s4 = *(const float4*)&scl[ch];
                    float4 t4 = *(const float4*)&sft[ch];
                    v.x = v.x * s4.x + t4.x;
                    v.y = v.y * s4.y + t4.y;
                    v.z = v.z * s4.z + t4.z;
                    v.w = v.w * s4.w + t4.w;
                    v.x = v.x > 0.f ? v.x : __expf(v.x) - 1.f;
                    v.y = v.y > 0.f ? v.y : __expf(v.y) - 1.f;
                    v.z = v.z > 0.f ? v.z : __expf(v.z) - 1.f;
                    v.w = v.w > 0.f ? v.w : __expf(v.w) - 1.f;
                }
                uint2 hi, lo;
                bf16split2(v.x, v.y, hi.x, lo.x);
                bf16split2(v.z, v.w, hi.y, lo.y);
                *(uint2*)&AsH[r * 20 + (cf >> 1)] = hi;
                *(uint2*)&AsL[r * 20 + (cf >> 1)] = lo;
            }
        }
        if (it + 1 < niter) CP_WAIT(1); else CP_WAIT(0);
        __syncthreads();

        const unsigned int* AsH = smem;
        const unsigned int* AsL = smem + 2560;
        const unsigned int* BsH = smem + 5120 + st * 2304;
        const unsigned int* BsL = BsH + 1152;

#pragma unroll
        for (int ks = 0; ks < 2; ks++) {
            unsigned int ah[2][4], al[2][4], bh[4][2], bl[4][2];
#pragma unroll
            for (int mi = 0; mi < 2; mi++) {
                int m = wm + mi * 16 + mrow;
                int i0 = m * 20 + ks * 8 + kc;
                ah[mi][0] = AsH[i0];            al[mi][0] = AsL[i0];
                ah[mi][1] = AsH[i0 + 160];      al[mi][1] = AsL[i0 + 160];   // row+8
                ah[mi][2] = AsH[i0 + 4];        al[mi][2] = AsL[i0 + 4];     // k+8
                ah[mi][3] = AsH[i0 + 164];      al[mi][3] = AsL[i0 + 164];
            }
#pragma unroll
            for (int ni = 0; ni < 4; ni++) {
                int ib = (ks * 8 + kc) * 72 + wn + ni * 8 + mrow;
                bh[ni][0] = BsH[ib];            bl[ni][0] = BsL[ib];
                bh[ni][1] = BsH[ib + 288];      bl[ni][1] = BsL[ib + 288];   // k+8
            }
#define MMA_B(ar, br, mi, ni)                                                     \
    asm volatile(                                                                 \
        "mma.sync.aligned.m16n8k16.row.col.f32.bf16.bf16.f32 "                    \
        "{%0,%1,%2,%3},{%4,%5,%6,%7},{%8,%9},{%0,%1,%2,%3};"                      \
        : "+f"(acc[mi][ni][0]), "+f"(acc[mi][ni][1]),                             \
          "+f"(acc[mi][ni][2]), "+f"(acc[mi][ni][3])                              \
        : "r"(ar[mi][0]), "r"(ar[mi][1]), "r"(ar[mi][2]), "r"(ar[mi][3]),         \
          "r"(br[ni][0]), "r"(br[ni][1]))
#pragma unroll
            for (int mi = 0; mi < 2; mi++)
#pragma unroll
                for (int ni = 0; ni < 4; ni++) {
                    MMA_B(ah, bl, mi, ni);
                    MMA_B(al, bh, mi, ni);
                    MMA_B(ah, bh, mi, ni);
                }
#undef MMA_B
        }
        __syncthreads();
    }
#undef PREFETCH_B

    // ---- epilogue: store C + attention coefficients (smem-staged) ----
    int H = gridDim.x;
    int head = blockIdx.x;
    const float* av = attn_s + head * 64;
    const float* dv = attn_d + head * 64;
    float avv[8], dvv[8];
#pragma unroll
    for (int ni = 0; ni < 4; ni++)
#pragma unroll
        for (int j = 0; j < 2; j++) {
            int cc = wn + ni * 8 + kc * 2 + j;
            avv[ni * 2 + j] = __ldg(&av[cc]);
            dvv[ni * 2 + j] = __ldg(&dv[cc]);
        }

    // A smem region is dead after the final loop sync; stage partials there.
    float* asP = (float*)smem;          // [128][2]
    float* adP = (float*)smem + 256;    // [128][2]
    int wc = wn >> 5;                   // 0 or 1: which column half

#pragma unroll
    for (int mi = 0; mi < 2; mi++) {
        int rloc = wm + mi * 16 + mrow;
        int r0 = rowBase + rloc;
        float s0 = 0.f, d0 = 0.f, s1 = 0.f, d1 = 0.f;
#pragma unroll
        for (int ni = 0; ni < 4; ni++) {
            int c = colBase + wn + ni * 8 + kc * 2;
            if (r0 < M) {
                C[(size_t)r0 * N + c]     = acc[mi][ni][0];
                C[(size_t)r0 * N + c + 1] = acc[mi][ni][1];
            }
            if (r0 + 8 < M) {
                C[(size_t)(r0 + 8) * N + c]     = acc[mi][ni][2];
                C[(size_t)(r0 + 8) * N + c + 1] = acc[mi][ni][3];
            }
            s0 += acc[mi][ni][0] * avv[ni * 2] + acc[mi][ni][1] * avv[ni * 2 + 1];
            d0 += acc[mi][ni][0] * dvv[ni * 2] + acc[mi][ni][1] * dvv[ni * 2 + 1];
            s1 += acc[mi][ni][2] * avv[ni * 2] + acc[mi][ni][3] * avv[ni * 2 + 1];
            d1 += acc[mi][ni][2] * dvv[ni * 2] + acc[mi][ni][3] * dvv[ni * 2 + 1];
        }
#pragma unroll
        for (int o = 1; o < 4; o <<= 1) {
            s0 += __shfl_xor_sync(0xFFFFFFFFu, s0, o);
            d0 += __shfl_xor_sync(0xFFFFFFFFu, d0, o);
            s1 += __shfl_xor_sync(0xFFFFFFFFu, s1, o);
            d1 += __shfl_xor_sync(0xFFFFFFFFu, d1, o);
        }
        if (kc == 0) {
            asP[rloc * 2 + wc] = s0;       adP[rloc * 2 + wc] = d0;
            asP[(rloc + 8) * 2 + wc] = s1; adP[(rloc + 8) * 2 + wc] = d1;
        }
    }
    __syncthreads();
    if (tid < 128) {
        int gr = rowBase + tid;
        if (gr < M) {
            as_o[gr * H + head] = asP[tid * 2] + asP[tid * 2 + 1];
            ad_o[gr * H + head] = adP[tid * 2] + adP[tid * 2 + 1];
        }
    }
}

// ------ fused softmax + CSR aggregation (H=4) + BN statistics, single pass ----
__global__ void agg4_k(const int* __restrict__ rowptr, const int* __restrict__ csrc,
                       const float* __restrict__ h,
                       const float* __restrict__ asb, const float* __restrict__ adb,
                       float* __restrict__ out,
                       float* __restrict__ sum, float* __restrict__ sq, int n)
{
    __shared__ float ps[8 * 256];

    int tid = threadIdx.x;
    int w = (blockIdx.x * blockDim.x + tid) >> 5;
    int warp = tid >> 5;
    int lane = tid & 31;
    bool active = w < n;

    float4 acc0 = make_float4(0.f, 0.f, 0.f, 0.f);
    float4 acc1 = make_float4(0.f, 0.f, 0.f, 0.f);

    if (active) {
        int beg = rowptr[w], end = rowptr[w + 1];
        int eh = lane & 3;
        float ad_h = adb[(size_t)w * 4 + eh];
        int hA = lane >> 4;
        int hB = 2 + hA;

        float den = 0.f;
        for (int j = beg; j < end; j++) {
            int s = __ldg(&csrc[j]);
            float e = asb[(size_t)s * 4 + eh] + ad_h;
            e = e > 0.f ? e : 0.2f * e;
            float ww = __expf(e);
            den += ww;
            float aA = __shfl_sync(0xFFFFFFFFu, ww, hA);
            float aB = __shfl_sync(0xFFFFFFFFu, ww, hB);
            const float4* hr = (const float4*)(h + (size_t)s * 256);
            float4 v0 = hr[lane];
            float4 v1 = hr[32 + lane];
            acc0.x += v0.x * aA; acc0.y += v0.y * aA; acc0.z += v0.z * aA; acc0.w += v0.w * aA;
            acc1.x += v1.x * aB; acc1.y += v1.y * aB; acc1.z += v1.z * aB; acc1.w += v1.w * aB;
        }
        float iA = 1.f / __shfl_sync(0xFFFFFFFFu, den, hA);
        float iB = 1.f / __shfl_sync(0xFFFFFFFFu, den, hB);
        acc0.x *= iA; acc0.y *= iA; acc0.z *= iA; acc0.w *= iA;
        acc1.x *= iB; acc1.y *= iB; acc1.z *= iB; acc1.w *= iB;
        float4* o4 = (float4*)(out + (size_t)w * 256);
        o4[lane] = acc0;
        o4[32 + lane] = acc1;
    }

    *(float4*)&ps[warp * 256 + lane * 4]       = acc0;
    *(float4*)&ps[warp * 256 + 128 + lane * 4] = acc1;
    __syncthreads();

    float s = 0.f, s2 = 0.f;
#pragma unroll
    for (int ww = 0; ww < 8; ww++) {
        float v = ps[ww * 256 + tid];
        s += v; s2 += v * v;
    }
    atomicAdd(&sum[tid], s);
    atomicAdd(&sq[tid], s2);
}

// ---- fused agg (H=1) + bias + classifier ------------------------------------
__global__ void agg1_cls_k(const int* __restrict__ rowptr, const int* __restrict__ csrc,
                           const float* __restrict__ h,
                           const float* __restrict__ asb, const float* __restrict__ adb,
                           const float* __restrict__ bias,
                           const float* __restrict__ Wc1, const float* __restrict__ bc1,
                           const float* __restrict__ Wc2, const float* __restrict__ bc2,
                           float* __restrict__ out, int n)
{
    int w = (blockIdx.x * blockDim.x + threadIdx.x) >> 5;
    int lane = threadIdx.x & 31;
    if (w >= n) return;
    int beg = rowptr[w], end = rowptr[w + 1];
    float ad = adb[w];

    float den = 0.f;
    float4 acc = make_float4(0.f, 0.f, 0.f, 0.f);
    for (int j = beg; j < end; j++) {
        int s = __ldg(&csrc[j]);
        float e = asb[s] + ad;
        e = e > 0.f ? e : 0.2f * e;
        float ww = __expf(e);
        den += ww;
        if (lane < 16) {
            float4 v = ((const float4*)(h + (size_t)s * 64))[lane];
            acc.x += v.x * ww; acc.y += v.y * ww; acc.z += v.z * ww; acc.w += v.w * ww;
        }
    }
    if (lane < 16) {
        float inv = 1.f / den;
        float4 b4 = ((const float4*)bias)[lane];
        acc.x = acc.x * inv + b4.x; acc.y = acc.y * inv + b4.y;
        acc.z = acc.z * inv + b4.z; acc.w = acc.w * inv + b4.w;
    }
    float hj = __ldg(&bc1[lane]);
#pragma unroll
    for (int c = 0; c < 64; c++) {
        int q = c >> 2, t = c & 3;
        float src = t == 0 ? acc.x : (t == 1 ? acc.y : (t == 2 ? acc.z : acc.w));
        float xc = __shfl_sync(0xFFFFFFFFu, src, q);
        hj += xc * __ldg(&Wc1[c * 32 + lane]);
    }
    hj = fmaxf(hj, 0.f);
    float o0 = hj * __ldg(&Wc2[lane * 2 + 0]);
    float o1 = hj * __ldg(&Wc2[lane * 2 + 1]);
#pragma unroll
    for (int o = 16; o; o >>= 1) {
        o0 += __shfl_down_sync(0xFFFFFFFFu, o0, o);
        o1 += __shfl_down_sync(0xFFFFFFFFu, o1, o);
    }
    if (!lane) {
        out[(size_t)w * 2]     = o0 + __ldg(&bc2[0]);
        out[(size_t)w * 2 + 1] = o1 + __ldg(&bc2[1]);
    }
}

__global__ void bn_fin_k(const float* sum, const float* sq,
                         const float* __restrict__ g, const float* __restrict__ be,
                         int n, float* scl, float* sft) {
    int ch = threadIdx.x;
    float mu = sum[ch] / (float)n;
    float var = fmaxf(sq[ch] / (float)n - mu * mu, 0.f);
    float r = rsqrtf(var + 1e-5f);
    float s = g[ch] * r;
    scl[ch] = s;
    sft[ch] = be[ch] - mu * s;
}

// ---------------- host-side orchestration -------------------------------------
#define GEMM_SMEM 38912

static void run_gemm(int dobn, const float* A,
                     const unsigned int* Bh, const unsigned int* Bl,
                     float* C, int M, int N, int K,
                     const float* scl, const float* sft,
                     const float* atts, const float* attd,
                     float* aso, float* ado) {
    dim3 grid(N / 64, (M + 127) / 128);
    if (dobn)
        gemm_fused_k<1><<<grid, 256, GEMM_SMEM>>>(A, Bh, Bl, C, M, N, K,
                                                  scl, sft, atts, attd, aso, ado);
    else
        gemm_fused_k<0><<<grid, 256, GEMM_SMEM>>>(A, Bh, Bl, C, M, N, K,
                                                  scl, sft, atts, attd, aso, ado);
}

extern "C" void kernel_launch(void* const* d_in, const int* in_sizes, int n_in,
                              void* d_out, int out_size)
{
    const float* x   = (const float*)d_in[0];
    const int*   ei  = (const int*)  d_in[1];
    const float* W0  = (const float*)d_in[2];
    const float* as0 = (const float*)d_in[3];
    const float* ad0 = (const float*)d_in[4];
    // b0 (d_in[5]) cancels through BatchNorm — skipped
    const float* W1  = (const float*)d_in[6];
    const float* as1 = (const float*)d_in[7];
    const float* ad1 = (const float*)d_in[8];
    // b1 (d_in[9]) cancels through BatchNorm — skipped
    const float* W2  = (const float*)d_in[10];
    const float* as2 = (const float*)d_in[11];
    const float* ad2 = (const float*)d_in[12];
    const float* b2  = (const float*)d_in[13];
    const float* g0  = (const float*)d_in[14];
    const float* be0 = (const float*)d_in[15];
    const float* g1  = (const float*)d_in[16];
    const float* be1 = (const float*)d_in[17];
    const float* Wc1 = (const float*)d_in[18];
    const float* bc1 = (const float*)d_in[19];
    const float* Wc2 = (const float*)d_in[20];
    const float* bc2 = (const float*)d_in[21];
    float* out = (float*)d_out;

    const int n = N_NODES;
    const int* src = ei;
    const int* dst = ei + N_EDGES;

    static int smem_cfg_done = 0;
    if (!smem_cfg_done) {
        cudaFuncSetAttribute(gemm_fused_k<0>,
                             cudaFuncAttributeMaxDynamicSharedMemorySize, GEMM_SMEM);
        cudaFuncSetAttribute(gemm_fused_k<1>,
                             cudaFuncAttributeMaxDynamicSharedMemorySize, GEMM_SMEM);
        smem_cfg_done = 1;
    }

    float *hbuf, *aggbuf, *asb, *adb;
    float *sumb, *sqb, *sclb, *sftb;
    unsigned int *w0h, *w0l, *w1h, *w1l, *w2h, *w2l;
    int *degb, *curb, *rowb, *csrcb, *blkb;
    cudaGetSymbolAddress((void**)&hbuf,  g_h);
    cudaGetSymbolAddress((void**)&aggbuf, g_agg);
    cudaGetSymbolAddress((void**)&asb,   g_as);
    cudaGetSymbolAddress((void**)&adb,   g_ad);
    cudaGetSymbolAddress((void**)&sumb,  g_sum);
    cudaGetSymbolAddress((void**)&sqb,   g_sq);
    cudaGetSymbolAddress((void**)&sclb,  g_scl);
    cudaGetSymbolAddress((void**)&sftb,  g_sft);
    cudaGetSymbolAddress((void**)&w0h,   g_w0h);
    cudaGetSymbolAddress((void**)&w0l,   g_w0l);
    cudaGetSymbolAddress((void**)&w1h,   g_w1h);
    cudaGetSymbolAddress((void**)&w1l,   g_w1l);
    cudaGetSymbolAddress((void**)&w2h,   g_w2h);
    cudaGetSymbolAddress((void**)&w2l,   g_w2l);
    cudaGetSymbolAddress((void**)&degb,  g_deg);
    cudaGetSymbolAddress((void**)&curb,  g_cursor);
    cudaGetSymbolAddress((void**)&rowb,  g_rowptr);
    cudaGetSymbolAddress((void**)&csrcb, g_csrc);
    cudaGetSymbolAddress((void**)&blkb,  g_blksum);

    // ---- prologue; GEMM is our 4th launch (ncu window) ----
    split_w_k<<<(64 * 256 + 255) / 256, 256>>>(W0, w0h, w0l, 128, 256);
    split_w_k<<<(128 * 256 + 255) / 256, 256>>>(W1, w1h, w1l, 256, 256);
    fill2i_k<<<(n + 255) / 256, 256>>>(degb, curb, n);

    // ---- GAT layer 0 GEMM + attn: 128 -> 4x64 (A = x, no BN) ----
    run_gemm(0, x, w0h, w0l, hbuf, n, 256, 128, nullptr, nullptr,
             as0, ad0, asb, adb);

    // ---- CSR build + W2 split ----
    deg_k<<<(ET_EDGES + 255) / 256, 256>>>(dst, degb, N_EDGES, ET_EDGES);
    scan_part_k<<<NBLK_SCAN, 256>>>(degb, rowb, blkb, n);
    scan_tops_k<<<1, 256>>>(blkb, NBLK_SCAN);
    scan_write_k<<<NBLK_SCAN, 256>>>(rowb, blkb, n);
    fill_pos_k<<<(ET_EDGES + 255) / 256, 256>>>(src, dst, rowb, curb, csrcb,
                                                N_EDGES, ET_EDGES);
    split_w_k<<<(128 * 64 + 255) / 256, 256>>>(W2, w2h, w2l, 256, 64);

    int aggBlocks = (n * 32 + 255) / 256;

    // ---- layer 0 aggregation + fused BN stats ----
    fill2f_k<<<1, 256>>>(sumb, sqb, HWID);
    agg4_k<<<aggBlocks, 256>>>(rowb, csrcb, hbuf, asb, adb, aggbuf, sumb, sqb, n);
    bn_fin_k<<<1, 256>>>(sumb, sqb, g0, be0, n, sclb, sftb);

    // ---- layer 1: BN+ELU fused into GEMM A-path ----
    run_gemm(1, aggbuf, w1h, w1l, hbuf, n, 256, 256, sclb, sftb,
             as1, ad1, asb, adb);
    fill2f_k<<<1, 256>>>(sumb, sqb, HWID);
    agg4_k<<<aggBlocks, 256>>>(rowb, csrcb, hbuf, asb, adb, aggbuf, sumb, sqb, n);
    bn_fin_k<<<1, 256>>>(sumb, sqb, g1, be1, n, sclb, sftb);

    // ---- layer 2: BN+ELU fused into GEMM A-path; 256 -> 1x64 ----
    run_gemm(1, aggbuf, w2h, w2l, hbuf, n, 64, 256, sclb, sftb,
             as2, ad2, asb, adb);

    // ---- agg1 + bias + classifier fused ----
    agg1_cls_k<<<aggBlocks, 256>>>(rowb, csrcb, hbuf, asb, adb, b2,
                                   Wc1, bc1, Wc2, bc2, out, n);
}